// round 1
// baseline (speedup 1.0000x reference)
#include <cuda_runtime.h>
#include <cuda_bf16.h>
#include <math.h>

// Problem constants
#define BB 8
#define NN 2048
#define CC 32
#define DD 64
#define QQ 256
#define KK 205
#define KPAD 208
#define TWO_PI 6.28318530717958647692f

// ---------------- scratch (device globals; no allocations) ----------------
__device__ float g_xl[BB * NN * CC];          // 2 MB   xl[b][n][c]
__device__ float g_M[QQ * BB * CC * CC];      // 8 MB   M[(q*8+b)][j][c]  (row stride 1024)
__device__ float g_zc[QQ * BB * CC];          // 256 KB zc[(q*8+b)][c]
__device__ float g_y[BB * QQ * DD];           // 512 KB y[(b*256+q)][d]

__device__ __forceinline__ float gelu_exact(float v) {
    return 0.5f * v * (1.0f + erff(v * 0.70710678118654752440f));
}
__device__ __forceinline__ float wrapd(float d) {
    float t = d + 0.5f;
    t -= floorf(t);
    return t - 0.5f;
}

// ---------------- Kernel A: xl = x @ W_lin + b_lin ; copy query_pos tail ----
__global__ __launch_bounds__(256) void kernA(const float* __restrict__ x,
                                             const float* __restrict__ W_lin,
                                             const float* __restrict__ b_lin,
                                             const float* __restrict__ qp,
                                             float* __restrict__ out, int out_size) {
    __shared__ float Ws[CC * CC];
    __shared__ float xr[256];
    __shared__ float bs[CC];
    int tid = threadIdx.x;
    int rowbase = blockIdx.x * 8;   // 8 rows of (b*N+n) per block, grid=2048
    for (int l = tid; l < CC * CC; l += 256) Ws[l] = W_lin[l];
    if (tid < CC) bs[tid] = b_lin[tid];
    xr[tid] = x[rowbase * CC + tid];
    __syncthreads();
    int r = tid >> 5, c = tid & 31;
    float acc = bs[c];
#pragma unroll
    for (int i = 0; i < CC; i++) acc = fmaf(xr[r * CC + i], Ws[i * CC + c], acc);
    g_xl[rowbase * CC + tid] = acc;
    if (blockIdx.x == 0) {
        for (int l = tid; l < QQ * 2; l += 256) out[out_size - QQ * 2 + l] = qp[l];
    }
}

// ---------------- Kernel B: per-query topK + features + M/zc accumulation ---
// shared layout (floats):
//  [0 .. 6655]     gs[KPAD*32]          (aliases u64 keys[2048] = first 4096 floats)
//  [6656 .. 8703]  zs[8][8][32]
//  [8704 .. 8911]  s_sh[KPAD]
//  [8912 .. 9119]  ind_sh[KPAD] (int)
//  [9120 ..10143]  W1s[1024]
//  [10144..10175]  b1s[32]
//  [10176..10207]  qmws[32]
//  [10208..10239]  qmos[32]
//  [10240..10271]  rffs[32]
//  [10272..10335]  red[64]
#define SMB_FLOATS 10336
__global__ __launch_bounds__(256, 2) void kernB(const float* __restrict__ pos,
                                                const float* __restrict__ qp,
                                                const float* __restrict__ qmw,
                                                const float* __restrict__ qmo,
                                                const float* __restrict__ rff,
                                                const float* __restrict__ W1,
                                                const float* __restrict__ b1) {
    __shared__ __align__(16) float sm[SMB_FLOATS];
    unsigned long long* keys = (unsigned long long*)sm;
    float* gs   = sm;
    float* zs   = sm + 6656;
    float* s_sh = sm + 8704;
    int*   ind_sh = (int*)(sm + 8912);
    float* W1s  = sm + 9120;
    float* b1s  = sm + 10144;
    float* qmws = sm + 10176;
    float* qmos = sm + 10208;
    float* rffs = sm + 10240;
    float* red  = sm + 10272;

    int q = blockIdx.x, tid = threadIdx.x;
    float qp0 = qp[2 * q], qp1 = qp[2 * q + 1];

    // stage constants (regions disjoint from keys)
    for (int l = tid; l < 1024; l += 256) W1s[l] = W1[l];
    if (tid < 32) {
        b1s[tid] = b1[tid];
        qmws[tid] = qmw[q * 32 + tid];
        qmos[tid] = qmo[q * 32 + tid];
        rffs[tid] = rff[tid];
    }

    // ---- phase 1: edist keys ----
    for (int n = tid; n < NN; n += 256) {
        float d0 = wrapd(qp0 - pos[2 * n]);
        float d1 = wrapd(qp1 - pos[2 * n + 1]);
        float e = d0 * d0 + d1 * d1;
        keys[n] = ((unsigned long long)__float_as_uint(e) << 32) | (unsigned)n;
    }
    __syncthreads();

    // ---- phase 2: bitonic sort 2048 keys ascending ----
    for (int size = 2; size <= NN; size <<= 1) {
        for (int stride = size >> 1; stride; stride >>= 1) {
            for (int t = tid; t < NN / 2; t += 256) {
                int i = 2 * t - (t & (stride - 1));
                unsigned long long a = keys[i], c = keys[i + stride];
                if ((a > c) == ((i & size) == 0)) { keys[i] = c; keys[i + stride] = a; }
            }
            __syncthreads();
        }
    }

    // ---- phase 3: ed normalization + softmax weights ----
    float ed0 = __uint_as_float((unsigned)(keys[0] >> 32));
    float edK = __uint_as_float((unsigned)(keys[KK - 1] >> 32));
    float w = 0.0f; int indv = 0;
    if (tid < KK) {
        unsigned long long kk = keys[tid];
        float edv = __uint_as_float((unsigned)(kk >> 32));
        indv = (int)(unsigned)(kk & 0xFFFFFFFFull);
        float e = (edv - ed0) / ((edK - ed0) + 1e-8f);
        w = expf(-e);
    }
    if (tid < KPAD) ind_sh[tid] = indv;  // pads -> 0 (safe row, weight 0)
    // block reduce sum of w
    float ws = w;
#pragma unroll
    for (int o = 16; o; o >>= 1) ws += __shfl_xor_sync(0xffffffffu, ws, o);
    if ((tid & 31) == 0) red[tid >> 5] = ws;
    __syncthreads();
    if (tid < 8) {
        float v = red[tid];
        v += __shfl_xor_sync(0x000000ffu, v, 4);
        v += __shfl_xor_sync(0x000000ffu, v, 2);
        v += __shfl_xor_sync(0x000000ffu, v, 1);
        if (tid == 0) red[0] = v;
    }
    __syncthreads();
    float ssum = red[0];
    float sk = (tid < KK) ? (w / ssum) : 0.0f;
    if (tid < KPAD) s_sh[tid] = sk;
    __syncthreads();   // keys fully consumed; gs region may now be overwritten

    // ---- phase 4: per-k RFF features -> h -> gelu -> gs = g * s ----
    if (tid < KK) {
        float d0 = wrapd(qp0 - pos[2 * indv]);
        float d1 = wrapd(qp1 - pos[2 * indv + 1]);
        float ft[32];
#pragma unroll
        for (int f = 0; f < 16; f++) {
            float p = TWO_PI * (d0 * rffs[f] + d1 * rffs[16 + f]);
            float sv, cv;
            sincosf(p, &sv, &cv);
            ft[f] = sv; ft[f + 16] = cv;
        }
#pragma unroll 4
        for (int j = 0; j < 32; j++) {
            float h = b1s[j];
#pragma unroll
            for (int i = 0; i < 32; i++) h = fmaf(ft[i], W1s[i * 32 + j], h);
            h = h * qmws[j] + qmos[j];
            gs[tid * 32 + j] = gelu_exact(h) * sk;
        }
    } else if (tid < KPAD) {
#pragma unroll
        for (int j = 0; j < 32; j++) gs[tid * 32 + j] = 0.0f;
    }
    __syncthreads();

    // ---- phase 5: M[b,j,c] = sum_k gs[k,j]*xl[b,ind[k],c]; zc[b,c]=sum_k s*xl ----
    float acc[32];
#pragma unroll
    for (int i = 0; i < 32; i++) acc[i] = 0.0f;
    float zca = 0.0f;
    int b = tid >> 5, j = tid & 31;

    for (int k0 = 0; k0 < KPAD; k0 += 8) {
        __syncthreads();   // protect zs from previous iteration's readers
        for (int l = tid; l < 512; l += 256) {
            int kk = l >> 6, bb = (l >> 3) & 7, c4 = l & 7;
            int n = ind_sh[k0 + kk];
            const float4* src = (const float4*)(g_xl + ((bb * NN + n) << 5));
            ((float4*)(zs + ((kk * 8 + bb) << 5)))[c4] = src[c4];
        }
        __syncthreads();
#pragma unroll
        for (int kk = 0; kk < 8; kk++) {
            float gv = gs[(k0 + kk) * 32 + j];
            const float* zr = zs + ((kk * 8 + b) << 5);
            zca = fmaf(s_sh[k0 + kk], zr[j], zca);
#pragma unroll
            for (int c4 = 0; c4 < 8; c4++) {
                float4 zz = ((const float4*)zr)[c4];
                acc[4 * c4 + 0] = fmaf(gv, zz.x, acc[4 * c4 + 0]);
                acc[4 * c4 + 1] = fmaf(gv, zz.y, acc[4 * c4 + 1]);
                acc[4 * c4 + 2] = fmaf(gv, zz.z, acc[4 * c4 + 2]);
                acc[4 * c4 + 3] = fmaf(gv, zz.w, acc[4 * c4 + 3]);
            }
        }
    }
    float4* Mout = (float4*)(g_M + ((q * 8 + b) * 32 + j) * 32);
#pragma unroll
    for (int c4 = 0; c4 < 8; c4++)
        Mout[c4] = make_float4(acc[4 * c4], acc[4 * c4 + 1], acc[4 * c4 + 2], acc[4 * c4 + 3]);
    g_zc[(q * 8 + b) * 32 + j] = zca;
}

// ---------------- Kernel C: Y1 = M@W2r + zc@filt ; y = gelu(Y1 + bias) ------
__global__ __launch_bounds__(256) void kernC(const float* __restrict__ W2,
                                             const float* __restrict__ filt,
                                             const float* __restrict__ bias) {
    __shared__ float W2t[32 * 64];
    __shared__ float Mt[16 * 32];
    __shared__ float filts[2048];
    __shared__ float zct[16 * 32];
    __shared__ float biass[64];
    int tid = threadIdx.x;
    int rowbase = blockIdx.x * 16;   // rows r = q*8+b ; grid = 128

    for (int l = tid; l < 2048; l += 256) filts[l] = filt[l];
    for (int l = tid; l < 512; l += 256) zct[l] = g_zc[rowbase * 32 + l];
    if (tid < 64) biass[tid] = bias[tid];

    int rg = tid >> 5, d0 = tid & 31;
    float a00 = 0.f, a01 = 0.f, a10 = 0.f, a11 = 0.f;   // rows {rg, rg+8} x cols {d0, d0+32}

    for (int jc0 = 0; jc0 < 1024; jc0 += 32) {
        __syncthreads();
        for (int l = tid; l < 2048; l += 256) {
            int jcl = l >> 6, dd = l & 63;
            int jcg = jc0 + jcl;
            W2t[l] = W2[(jcg >> 5) * 2048 + (jcg & 31) * 64 + dd];
        }
        for (int l = tid; l < 512; l += 256) {
            int rl = l >> 5, jcl = l & 31;
            Mt[l] = g_M[(rowbase + rl) * 1024 + jc0 + jcl];
        }
        __syncthreads();
#pragma unroll 8
        for (int jcl = 0; jcl < 32; jcl++) {
            float w0 = W2t[jcl * 64 + d0], w1 = W2t[jcl * 64 + d0 + 32];
            float m0 = Mt[rg * 32 + jcl],  m1 = Mt[(rg + 8) * 32 + jcl];
            a00 = fmaf(m0, w0, a00); a01 = fmaf(m0, w1, a01);
            a10 = fmaf(m1, w0, a10); a11 = fmaf(m1, w1, a11);
        }
    }
#pragma unroll 8
    for (int c = 0; c < 32; c++) {
        float w0 = filts[c * 64 + d0], w1 = filts[c * 64 + d0 + 32];
        float m0 = zct[rg * 32 + c],   m1 = zct[(rg + 8) * 32 + c];
        a00 = fmaf(m0, w0, a00); a01 = fmaf(m0, w1, a01);
        a10 = fmaf(m1, w0, a10); a11 = fmaf(m1, w1, a11);
    }
    int r0 = rowbase + rg, r1 = rowbase + rg + 8;
    int q0 = r0 >> 3, b0 = r0 & 7, q1 = r1 >> 3, b1v = r1 & 7;
    g_y[(b0 * QQ + q0) * 64 + d0]      = gelu_exact(a00 + biass[d0]);
    g_y[(b0 * QQ + q0) * 64 + d0 + 32] = gelu_exact(a01 + biass[d0 + 32]);
    g_y[(b1v * QQ + q1) * 64 + d0]      = gelu_exact(a10 + biass[d0]);
    g_y[(b1v * QQ + q1) * 64 + d0 + 32] = gelu_exact(a11 + biass[d0 + 32]);
}

// ---------------- Kernel D: out = gelu(y@Wm1+bm1)@Wm2 + bm2 + y -------------
__global__ __launch_bounds__(256) void kernD(const float* __restrict__ Wm1,
                                             const float* __restrict__ bm1,
                                             const float* __restrict__ Wm2,
                                             const float* __restrict__ bm2,
                                             float* __restrict__ out) {
    __shared__ float yr[8 * 64];
    __shared__ float ts[8 * 256];
    int tid = threadIdx.x;
    int rb = blockIdx.x * 8;   // rows rbq = b*256+q ; grid = 256
    for (int l = tid; l < 512; l += 256) yr[l] = g_y[rb * 64 + l];
    __syncthreads();
    {
        int i = tid;
        float acc[8];
        float bb = bm1[i];
#pragma unroll
        for (int l = 0; l < 8; l++) acc[l] = bb;
        for (int d = 0; d < 64; d++) {
            float wv = Wm1[d * 256 + i];
#pragma unroll
            for (int l = 0; l < 8; l++) acc[l] = fmaf(yr[l * 64 + d], wv, acc[l]);
        }
#pragma unroll
        for (int l = 0; l < 8; l++) ts[l * 256 + i] = gelu_exact(acc[l]);
    }
    __syncthreads();
    {
        int d = tid & 63, lg = tid >> 6;
        int l0 = lg, l1 = lg + 4;
        float a0 = bm2[d] + yr[l0 * 64 + d];
        float a1 = bm2[d] + yr[l1 * 64 + d];
        for (int i = 0; i < 256; i++) {
            float wv = Wm2[i * 64 + d];
            a0 = fmaf(ts[l0 * 256 + i], wv, a0);
            a1 = fmaf(ts[l1 * 256 + i], wv, a1);
        }
        out[(rb + l0) * 64 + d] = a0;
        out[(rb + l1) * 64 + d] = a1;
    }
}

// ---------------- launch ----------------------------------------------------
extern "C" void kernel_launch(void* const* d_in, const int* in_sizes, int n_in,
                              void* d_out, int out_size) {
    const float* x    = (const float*)d_in[0];
    const float* pos  = (const float*)d_in[1];
    const float* qp   = (const float*)d_in[2];
    const float* qmw  = (const float*)d_in[3];
    const float* qmo  = (const float*)d_in[4];
    const float* W_lin = (const float*)d_in[5];
    const float* b_lin = (const float*)d_in[6];
    const float* rff  = (const float*)d_in[7];
    const float* W1   = (const float*)d_in[8];
    const float* b1   = (const float*)d_in[9];
    const float* W2   = (const float*)d_in[10];
    const float* filt = (const float*)d_in[11];
    const float* bias = (const float*)d_in[12];
    const float* Wm1  = (const float*)d_in[13];
    const float* bm1  = (const float*)d_in[14];
    const float* Wm2  = (const float*)d_in[15];
    const float* bm2  = (const float*)d_in[16];
    float* out = (float*)d_out;

    kernA<<<2048, 256>>>(x, W_lin, b_lin, qp, out, out_size);
    kernB<<<QQ, 256>>>(pos, qp, qmw, qmo, rff, W1, b1);
    kernC<<<128, 256>>>(W2, filt, bias);
    kernD<<<256, 256>>>(Wm1, bm1, Wm2, bm2, out);
}

// round 2
// speedup vs baseline: 1.1869x; 1.1869x over previous
#include <cuda_runtime.h>
#include <cuda_bf16.h>
#include <math.h>

// Problem constants
#define BB 8
#define NN 2048
#define CC 32
#define DD 64
#define QQ 256
#define KK 205
#define KPAD 208
#define TWO_PI 6.28318530717958647692f

// ---------------- scratch (device globals; no allocations) ----------------
__device__ float g_xl[BB * NN * CC];          // 2 MB   xl[b][n][c]
__device__ float g_M[QQ * BB * CC * CC];      // 8 MB   M[(q*8+b)][j][c]  (row stride 1024)
__device__ float g_zc[QQ * BB * CC];          // 256 KB zc[(q*8+b)][c]
__device__ float g_y[BB * QQ * DD];           // 512 KB y[(b*256+q)][d]

__device__ __forceinline__ float gelu_exact(float v) {
    return 0.5f * v * (1.0f + erff(v * 0.70710678118654752440f));
}
__device__ __forceinline__ float wrapd(float d) {
    float t = d + 0.5f;
    t -= floorf(t);
    return t - 0.5f;
}

// ---- packed f32x2 helpers (sm_100+) ----
__device__ __forceinline__ unsigned long long pk2(float lo, float hi) {
    unsigned long long r;
    asm("mov.b64 %0, {%1,%2};" : "=l"(r) : "f"(lo), "f"(hi));
    return r;
}
__device__ __forceinline__ void fma2(unsigned long long& d, unsigned long long a, unsigned long long b) {
    asm("fma.rn.f32x2 %0, %1, %2, %0;" : "+l"(d) : "l"(a), "l"(b));
}
__device__ __forceinline__ float2 up2(unsigned long long v) {
    float lo, hi;
    asm("mov.b64 {%0,%1}, %2;" : "=f"(lo), "=f"(hi) : "l"(v));
    return make_float2(lo, hi);
}

// ---------------- Kernel A: xl = x @ W_lin + b_lin ; copy query_pos tail ----
__global__ __launch_bounds__(256) void kernA(const float* __restrict__ x,
                                             const float* __restrict__ W_lin,
                                             const float* __restrict__ b_lin,
                                             const float* __restrict__ qp,
                                             float* __restrict__ out, int out_size) {
    __shared__ float Ws[CC * CC];
    __shared__ float xr[256];
    __shared__ float bs[CC];
    int tid = threadIdx.x;
    int rowbase = blockIdx.x * 8;   // 8 rows of (b*N+n) per block, grid=2048
    for (int l = tid; l < CC * CC; l += 256) Ws[l] = W_lin[l];
    if (tid < CC) bs[tid] = b_lin[tid];
    xr[tid] = x[rowbase * CC + tid];
    __syncthreads();
    int r = tid >> 5, c = tid & 31;
    float acc = bs[c];
#pragma unroll
    for (int i = 0; i < CC; i++) acc = fmaf(xr[r * CC + i], Ws[i * CC + c], acc);
    g_xl[rowbase * CC + tid] = acc;
    if (blockIdx.x == 0) {
        for (int l = tid; l < QQ * 2; l += 256) out[out_size - QQ * 2 + l] = qp[l];
    }
}

// ---------------- Kernel B: per-query topK (radix select) + features + M/zc --
#define GSTR 34
#define ZSTR 36
// shared layout (floats):
//  [0 .. 7071]      gs[KPAD*GSTR]   (aliases: ebits[2048] at 0, eq[2048] at 2048)
//  [7072 .. 9375]   zs[64*ZSTR]
//  [9376 .. 9583]   s_sh[KPAD]
//  [9584 .. 9791]   ind_sh[KPAD] (int)
//  [9792 ..10815]   W1s[1024]
//  [10816..10847]   b1s
//  [10848..10879]   qmws
//  [10880..10911]   qmos
//  [10912..10943]   rffs
//  [10944..11199]   hist[256] (int)
//  [11200..11215]   misc: [0]=cnt [1]=cnteq [2]=minbits [3]=prefix [4]=rank ; red at [8..15]
#define SMB_FLOATS 11216
__global__ __launch_bounds__(256, 2) void kernB(const float* __restrict__ pos,
                                                const float* __restrict__ qp,
                                                const float* __restrict__ qmw,
                                                const float* __restrict__ qmo,
                                                const float* __restrict__ rff,
                                                const float* __restrict__ W1,
                                                const float* __restrict__ b1) {
    __shared__ __align__(16) float sm[SMB_FLOATS];
    unsigned* ebits = (unsigned*)sm;
    int* eq = (int*)(sm + 2048);
    float* gs   = sm;
    float* zs   = sm + 7072;
    float* s_sh = sm + 9376;
    int*   ind_sh = (int*)(sm + 9584);
    float* W1s  = sm + 9792;
    float* b1s  = sm + 10816;
    float* qmws = sm + 10848;
    float* qmos = sm + 10880;
    float* rffs = sm + 10912;
    int*   hist = (int*)(sm + 10944);
    unsigned* um = (unsigned*)(sm + 11200);
    float* red  = sm + 11208;

    int q = blockIdx.x, tid = threadIdx.x;
    float qp0 = qp[2 * q], qp1 = qp[2 * q + 1];

    // stage constants + init misc
    for (int l = tid; l < 1024; l += 256) W1s[l] = W1[l];
    if (tid < 32) {
        b1s[tid] = b1[tid];
        qmws[tid] = qmw[q * 32 + tid];
        qmos[tid] = qmo[q * 32 + tid];
        rffs[tid] = rff[tid];
    }
    if (tid == 0) {
        um[0] = 0; um[1] = 0; um[2] = 0xFFFFFFFFu; um[3] = 0;
        ((int*)um)[4] = KK;
    }
    __syncthreads();

    // ---- phase 1: edist bits + global min ----
    unsigned mymin = 0xFFFFFFFFu;
#pragma unroll
    for (int it = 0; it < 8; it++) {
        int n = tid + it * 256;
        float2 p = ((const float2*)pos)[n];
        float d0 = wrapd(qp0 - p.x);
        float d1 = wrapd(qp1 - p.y);
        float e = d0 * d0 + d1 * d1;
        unsigned eb = __float_as_uint(e);   // e >= 0 -> uint order == float order
        ebits[n] = eb;
        mymin = min(mymin, eb);
    }
#pragma unroll
    for (int o = 16; o; o >>= 1) mymin = min(mymin, __shfl_xor_sync(0xffffffffu, mymin, o));
    if ((tid & 31) == 0) atomicMin(&um[2], mymin);

    // ---- phase 2: 4-pass radix select for rank-KK smallest edist ----
    for (int pass = 0; pass < 4; pass++) {
        int sh = 24 - 8 * pass;
        if (tid < 256) hist[tid] = 0;
        __syncthreads();
        unsigned pref = um[3];
        unsigned hm = pass ? (0xFFFFFFFFu << (sh + 8)) : 0u;
#pragma unroll
        for (int it = 0; it < 8; it++) {
            unsigned e = ebits[tid + it * 256];
            if ((e & hm) == pref) atomicAdd(&hist[(e >> sh) & 255], 1);
        }
        __syncthreads();
        if (tid < 32) {
            int loc[8]; int s0 = 0;
#pragma unroll
            for (int i = 0; i < 8; i++) { loc[i] = hist[tid * 8 + i]; s0 += loc[i]; }
            int inc = s0;
#pragma unroll
            for (int o = 1; o < 32; o <<= 1) {
                int v = __shfl_up_sync(0xffffffffu, inc, o);
                if (tid >= o) inc += v;
            }
            int exc = inc - s0;
            int rk = ((int*)um)[4];
            if (rk > exc && rk <= inc) {
                int rr = rk - exc;
#pragma unroll
                for (int i = 0; i < 8; i++) {
                    if (rr > loc[i]) rr -= loc[i];
                    else { um[3] = pref | ((unsigned)(tid * 8 + i) << sh); ((int*)um)[4] = rr; break; }
                }
            }
        }
        __syncthreads();
    }
    unsigned vsel = um[3];
    int rsel = ((int*)um)[4];

    // ---- phase 3: compaction (set semantics; order irrelevant downstream) ----
#pragma unroll
    for (int it = 0; it < 8; it++) {
        int n = tid + it * 256;
        unsigned e = ebits[n];
        if (e < vsel)       { int p = atomicAdd((int*)&um[0], 1); ind_sh[p] = n; }
        else if (e == vsel) { int p = atomicAdd((int*)&um[1], 1); eq[p] = n; }
    }
    __syncthreads();
    {   // pick rsel smallest indices among equals (JAX tie-break)
        int m = (int)um[1], base = (int)um[0];
        for (int t = tid; t < m; t += 256) {
            int my = eq[t], c = 0;
            for (int i = 0; i < m; i++) c += (eq[i] < my);
            if (c < rsel) ind_sh[base + c] = my;
        }
    }
    if (tid >= KK && tid < KPAD) ind_sh[tid] = 0;
    __syncthreads();

    // ---- phase 4: softmax weights over normalized ed ----
    float ed0 = __uint_as_float(um[2]);
    float edK = __uint_as_float(vsel);
    float invden = 1.0f / ((edK - ed0) + 1e-8f);
    float w = 0.0f; int indv = 0;
    if (tid < KK) {
        indv = ind_sh[tid];
        float e = __uint_as_float(ebits[indv]);
        w = __expf(-(e - ed0) * invden);
    }
    float ws = w;
#pragma unroll
    for (int o = 16; o; o >>= 1) ws += __shfl_xor_sync(0xffffffffu, ws, o);
    if ((tid & 31) == 0) red[tid >> 5] = ws;
    __syncthreads();
    if (tid < 8) {
        float v = red[tid];
        v += __shfl_xor_sync(0x000000ffu, v, 4);
        v += __shfl_xor_sync(0x000000ffu, v, 2);
        v += __shfl_xor_sync(0x000000ffu, v, 1);
        if (tid == 0) red[0] = v;
    }
    __syncthreads();
    float sk = (tid < KK) ? (w / red[0]) : 0.0f;
    if (tid < KPAD) s_sh[tid] = sk;
    __syncthreads();   // ebits fully consumed; gs region may be overwritten

    // ---- phase 5: per-k RFF features -> h -> gelu -> gs = g * s (f32x2) ----
    if (tid < KK) {
        float2 pp = ((const float2*)pos)[indv];
        float d0 = wrapd(qp0 - pp.x);
        float d1 = wrapd(qp1 - pp.y);
        float ft[32];
#pragma unroll
        for (int f = 0; f < 16; f++) {
            float p = TWO_PI * (d0 * rffs[f] + d1 * rffs[16 + f]);
            __sincosf(p, &ft[f], &ft[f + 16]);
        }
        unsigned long long h2[16];
        const unsigned long long* b1p = (const unsigned long long*)b1s;
#pragma unroll
        for (int jp = 0; jp < 16; jp++) h2[jp] = b1p[jp];
#pragma unroll 4
        for (int i = 0; i < 32; i++) {
            unsigned long long fi = pk2(ft[i], ft[i]);
            const unsigned long long* w1p = (const unsigned long long*)(W1s + i * 32);
#pragma unroll
            for (int jp = 0; jp < 16; jp++) fma2(h2[jp], fi, w1p[jp]);
        }
        unsigned long long* grow = (unsigned long long*)(gs + tid * GSTR);
#pragma unroll
        for (int jp = 0; jp < 16; jp++) {
            float2 hv = up2(h2[jp]);
            int j0 = 2 * jp;
            float a0 = gelu_exact(hv.x * qmws[j0] + qmos[j0]) * sk;
            float a1 = gelu_exact(hv.y * qmws[j0 + 1] + qmos[j0 + 1]) * sk;
            grow[jp] = pk2(a0, a1);
        }
    } else if (tid < KPAD) {
        unsigned long long* grow = (unsigned long long*)(gs + tid * GSTR);
#pragma unroll
        for (int jp = 0; jp < 16; jp++) grow[jp] = 0ull;
    }
    __syncthreads();

    // ---- phase 6: M[b,j,c] = sum_k gs[k,j]*xl[b,ind[k],c]; zc = sum_k s*xl ----
    unsigned long long acc2[16];
#pragma unroll
    for (int i = 0; i < 16; i++) acc2[i] = 0ull;
    float zca = 0.0f;
    int b = tid >> 5, j = tid & 31;

    for (int k0 = 0; k0 < KPAD; k0 += 8) {
        __syncthreads();   // protect zs from previous iteration's readers
        for (int l = tid; l < 512; l += 256) {
            int kk = l >> 6, bb = (l >> 3) & 7, c4 = l & 7;
            int n = ind_sh[k0 + kk];
            const float4* src = (const float4*)(g_xl + ((bb * NN + n) << 5));
            ((float4*)(zs + (kk * 8 + bb) * ZSTR))[c4] = src[c4];
        }
        __syncthreads();
#pragma unroll
        for (int kk = 0; kk < 8; kk++) {
            float gv = gs[(k0 + kk) * GSTR + j];
            unsigned long long gv2 = pk2(gv, gv);
            const float* zr = zs + (kk * 8 + b) * ZSTR;
            zca = fmaf(s_sh[k0 + kk], zr[j], zca);
            const ulonglong2* zr2 = (const ulonglong2*)zr;
#pragma unroll
            for (int c4 = 0; c4 < 8; c4++) {
                ulonglong2 zz = zr2[c4];
                fma2(acc2[2 * c4], gv2, zz.x);
                fma2(acc2[2 * c4 + 1], gv2, zz.y);
            }
        }
    }
    float4* Mout = (float4*)(g_M + ((q * 8 + b) * 32 + j) * 32);
#pragma unroll
    for (int c4 = 0; c4 < 8; c4++) {
        float2 lo = up2(acc2[2 * c4]);
        float2 hi = up2(acc2[2 * c4 + 1]);
        Mout[c4] = make_float4(lo.x, lo.y, hi.x, hi.y);
    }
    g_zc[(q * 8 + b) * 32 + j] = zca;
}

// ---------------- Kernel C: Y1 = M@W2r + zc@filt ; y = gelu(Y1 + bias) ------
__global__ __launch_bounds__(256) void kernC(const float* __restrict__ W2,
                                             const float* __restrict__ filt,
                                             const float* __restrict__ bias) {
    __shared__ float W2t[32 * 64];
    __shared__ float Mt[16 * 32];
    __shared__ float filts[2048];
    __shared__ float zct[16 * 32];
    __shared__ float biass[64];
    int tid = threadIdx.x;
    int rowbase = blockIdx.x * 16;   // rows r = q*8+b ; grid = 128

    for (int l = tid; l < 2048; l += 256) filts[l] = filt[l];
    for (int l = tid; l < 512; l += 256) zct[l] = g_zc[rowbase * 32 + l];
    if (tid < 64) biass[tid] = bias[tid];

    int rg = tid >> 5, d0 = tid & 31;
    float a00 = 0.f, a01 = 0.f, a10 = 0.f, a11 = 0.f;   // rows {rg, rg+8} x cols {d0, d0+32}

    for (int jc0 = 0; jc0 < 1024; jc0 += 32) {
        __syncthreads();
        for (int l = tid; l < 2048; l += 256) {
            int jcl = l >> 6, dd = l & 63;
            int jcg = jc0 + jcl;
            W2t[l] = W2[(jcg >> 5) * 2048 + (jcg & 31) * 64 + dd];
        }
        for (int l = tid; l < 512; l += 256) {
            int rl = l >> 5, jcl = l & 31;
            Mt[l] = g_M[(rowbase + rl) * 1024 + jc0 + jcl];
        }
        __syncthreads();
#pragma unroll 8
        for (int jcl = 0; jcl < 32; jcl++) {
            float w0 = W2t[jcl * 64 + d0], w1 = W2t[jcl * 64 + d0 + 32];
            float m0 = Mt[rg * 32 + jcl],  m1 = Mt[(rg + 8) * 32 + jcl];
            a00 = fmaf(m0, w0, a00); a01 = fmaf(m0, w1, a01);
            a10 = fmaf(m1, w0, a10); a11 = fmaf(m1, w1, a11);
        }
    }
#pragma unroll 8
    for (int c = 0; c < 32; c++) {
        float w0 = filts[c * 64 + d0], w1 = filts[c * 64 + d0 + 32];
        float m0 = zct[rg * 32 + c],   m1 = zct[(rg + 8) * 32 + c];
        a00 = fmaf(m0, w0, a00); a01 = fmaf(m0, w1, a01);
        a10 = fmaf(m1, w0, a10); a11 = fmaf(m1, w1, a11);
    }
    int r0 = rowbase + rg, r1 = rowbase + rg + 8;
    int q0 = r0 >> 3, b0 = r0 & 7, q1 = r1 >> 3, b1v = r1 & 7;
    g_y[(b0 * QQ + q0) * 64 + d0]      = gelu_exact(a00 + biass[d0]);
    g_y[(b0 * QQ + q0) * 64 + d0 + 32] = gelu_exact(a01 + biass[d0 + 32]);
    g_y[(b1v * QQ + q1) * 64 + d0]      = gelu_exact(a10 + biass[d0]);
    g_y[(b1v * QQ + q1) * 64 + d0 + 32] = gelu_exact(a11 + biass[d0 + 32]);
}

// ---------------- Kernel D: out = gelu(y@Wm1+bm1)@Wm2 + bm2 + y -------------
__global__ __launch_bounds__(512) void kernD(const float* __restrict__ Wm1,
                                             const float* __restrict__ bm1,
                                             const float* __restrict__ Wm2,
                                             const float* __restrict__ bm2,
                                             float* __restrict__ out) {
    __shared__ float yr[8 * 64];
    __shared__ float ts[8 * 256];
    int tid = threadIdx.x;
    int rb = blockIdx.x * 8;   // rows rbq = b*256+q ; grid = 256
    if (tid < 512) yr[tid] = g_y[rb * 64 + tid];
    __syncthreads();
    {
        int lg = tid >> 8;      // 0..1 -> rows lg*4 .. lg*4+3
        int i  = tid & 255;
        float bb = bm1[i];
        float a0 = bb, a1 = bb, a2 = bb, a3 = bb;
        const float* yb = yr + lg * 4 * 64;
#pragma unroll 8
        for (int d = 0; d < 64; d++) {
            float wv = Wm1[d * 256 + i];
            a0 = fmaf(yb[d],        wv, a0);
            a1 = fmaf(yb[64 + d],   wv, a1);
            a2 = fmaf(yb[128 + d],  wv, a2);
            a3 = fmaf(yb[192 + d],  wv, a3);
        }
        float* tb = ts + lg * 4 * 256;
        tb[i]       = gelu_exact(a0);
        tb[256 + i] = gelu_exact(a1);
        tb[512 + i] = gelu_exact(a2);
        tb[768 + i] = gelu_exact(a3);
    }
    __syncthreads();
    {
        int d = tid & 63, l = tid >> 6;   // 8 rows, 1 per thread
        const float* tr = ts + l * 256;
        float a0 = 0.f, a1 = 0.f, a2 = 0.f, a3 = 0.f;
#pragma unroll 4
        for (int i = 0; i < 256; i += 4) {
            a0 = fmaf(tr[i],     Wm2[i * 64 + d],       a0);
            a1 = fmaf(tr[i + 1], Wm2[(i + 1) * 64 + d], a1);
            a2 = fmaf(tr[i + 2], Wm2[(i + 2) * 64 + d], a2);
            a3 = fmaf(tr[i + 3], Wm2[(i + 3) * 64 + d], a3);
        }
        out[(rb + l) * 64 + d] = bm2[d] + yr[l * 64 + d] + ((a0 + a1) + (a2 + a3));
    }
}

// ---------------- launch ----------------------------------------------------
extern "C" void kernel_launch(void* const* d_in, const int* in_sizes, int n_in,
                              void* d_out, int out_size) {
    const float* x    = (const float*)d_in[0];
    const float* pos  = (const float*)d_in[1];
    const float* qp   = (const float*)d_in[2];
    const float* qmw  = (const float*)d_in[3];
    const float* qmo  = (const float*)d_in[4];
    const float* W_lin = (const float*)d_in[5];
    const float* b_lin = (const float*)d_in[6];
    const float* rff  = (const float*)d_in[7];
    const float* W1   = (const float*)d_in[8];
    const float* b1   = (const float*)d_in[9];
    const float* W2   = (const float*)d_in[10];
    const float* filt = (const float*)d_in[11];
    const float* bias = (const float*)d_in[12];
    const float* Wm1  = (const float*)d_in[13];
    const float* bm1  = (const float*)d_in[14];
    const float* Wm2  = (const float*)d_in[15];
    const float* bm2  = (const float*)d_in[16];
    float* out = (float*)d_out;

    kernA<<<2048, 256>>>(x, W_lin, b_lin, qp, out, out_size);
    kernB<<<QQ, 256>>>(pos, qp, qmw, qmo, rff, W1, b1);
    kernC<<<128, 256>>>(W2, filt, bias);
    kernD<<<256, 512>>>(Wm1, bm1, Wm2, bm2, out);
}

// round 3
// speedup vs baseline: 1.7443x; 1.4697x over previous
#include <cuda_runtime.h>
#include <cuda_bf16.h>
#include <math.h>

// Problem constants
#define BB 8
#define NN 2048
#define CC 32
#define DD 64
#define QQ 256
#define KK 205
#define KPAD 208
#define TWO_PI 6.28318530717958647692f

// ---------------- scratch (device globals; no allocations) ----------------
__device__ float g_xl[BB * NN * CC];          // 2 MB   xl[b][n][c]
__device__ float g_M[QQ * BB * CC * CC];      // 8 MB   M[(q*8+b)][j][c]  (row stride 1024)
__device__ float g_zc[QQ * BB * CC];          // 256 KB zc[(q*8+b)][c]
__device__ float g_y[BB * QQ * DD];           // 512 KB y[(b*256+q)][d]

__device__ __forceinline__ float gelu_exact(float v) {
    return 0.5f * v * (1.0f + erff(v * 0.70710678118654752440f));
}
__device__ __forceinline__ float wrapd(float d) {
    float t = d + 0.5f;
    t -= floorf(t);
    return t - 0.5f;
}

// ---- packed f32x2 helpers (sm_100+) ----
__device__ __forceinline__ unsigned long long pk2(float lo, float hi) {
    unsigned long long r;
    asm("mov.b64 %0, {%1,%2};" : "=l"(r) : "f"(lo), "f"(hi));
    return r;
}
__device__ __forceinline__ void fma2(unsigned long long& d, unsigned long long a, unsigned long long b) {
    asm("fma.rn.f32x2 %0, %1, %2, %0;" : "+l"(d) : "l"(a), "l"(b));
}
__device__ __forceinline__ float2 up2(unsigned long long v) {
    float lo, hi;
    asm("mov.b64 {%0,%1}, %2;" : "=f"(lo), "=f"(hi) : "l"(v));
    return make_float2(lo, hi);
}

// ---- cp.async helpers ----
__device__ __forceinline__ void cpa16(float* dst, const float* src) {
    unsigned s = (unsigned)__cvta_generic_to_shared(dst);
    asm volatile("cp.async.cg.shared.global [%0], [%1], 16;" :: "r"(s), "l"(src));
}
__device__ __forceinline__ void cpa_commit() { asm volatile("cp.async.commit_group;" ::: "memory"); }
__device__ __forceinline__ void cpa_wait1() { asm volatile("cp.async.wait_group 1;" ::: "memory"); }
__device__ __forceinline__ void cpa_wait0() { asm volatile("cp.async.wait_group 0;" ::: "memory"); }

// ---------------- Kernel A: xl = x @ W_lin + b_lin ; copy query_pos tail ----
__global__ __launch_bounds__(256) void kernA(const float* __restrict__ x,
                                             const float* __restrict__ W_lin,
                                             const float* __restrict__ b_lin,
                                             const float* __restrict__ qp,
                                             float* __restrict__ out, int out_size) {
    __shared__ float Ws[CC * CC];
    __shared__ float xr[1024];
    __shared__ float bs[CC];
    int tid = threadIdx.x;
    int rowbase = blockIdx.x * 32;   // 32 rows of (b*N+n) per block, grid=512
    for (int l = tid; l < CC * CC; l += 256) Ws[l] = W_lin[l];
    if (tid < CC) bs[tid] = b_lin[tid];
    ((float4*)xr)[tid] = ((const float4*)(x + rowbase * CC))[tid];
    __syncthreads();
    int rg = tid >> 5, c = tid & 31;
    float acc[4];
#pragma unroll
    for (int l = 0; l < 4; l++) acc[l] = bs[c];
#pragma unroll
    for (int i = 0; i < CC; i++) {
        float wv = Ws[i * CC + c];
#pragma unroll
        for (int l = 0; l < 4; l++) acc[l] = fmaf(xr[(rg * 4 + l) * CC + i], wv, acc[l]);
    }
#pragma unroll
    for (int l = 0; l < 4; l++) g_xl[(rowbase + rg * 4 + l) * CC + c] = acc[l];
    if (blockIdx.x == 0) {
        for (int l = tid; l < QQ * 2; l += 256) out[out_size - QQ * 2 + l] = qp[l];
    }
}

// ---------------- Kernel B: per-query topK (radix select) + features + M/zc --
#define GSTR 34
// shared layout (floats), total 11584 = 46.3KB:
//  [0 .. 7071]      gs[KPAD*GSTR]   aliases: ebits[2048]@0, eq[2048]@2048
//  [7072 ..11167]   zs[2][8*8*32]   aliases (dead by phase 6):
//                     W1s@7072(1024) b1s@8096 qmws@8128 qmos@8160 rffs@8192
//                     hist@8224(256 int) um@8480(8) red@8488(8)
//  [11168..11375]   s_sh[KPAD]
//  [11376..11583]   ind_sh[KPAD] (int)
#define SMB_FLOATS 11584
__global__ __launch_bounds__(256, 2) void kernB(const float* __restrict__ pos,
                                                const float* __restrict__ qp,
                                                const float* __restrict__ qmw,
                                                const float* __restrict__ qmo,
                                                const float* __restrict__ rff,
                                                const float* __restrict__ W1,
                                                const float* __restrict__ b1) {
    __shared__ __align__(16) float sm[SMB_FLOATS];
    unsigned* ebits = (unsigned*)sm;
    int* eq = (int*)(sm + 2048);
    float* gs   = sm;
    float* zs   = sm + 7072;
    float* W1s  = sm + 7072;
    float* b1s  = sm + 8096;
    float* qmws = sm + 8128;
    float* qmos = sm + 8160;
    float* rffs = sm + 8192;
    int*   hist = (int*)(sm + 8224);
    unsigned* um = (unsigned*)(sm + 8480);
    float* red  = sm + 8488;
    float* s_sh = sm + 11168;
    int*   ind_sh = (int*)(sm + 11376);

    int q = blockIdx.x, tid = threadIdx.x;
    int lane = tid & 31;
    float qp0 = qp[2 * q], qp1 = qp[2 * q + 1];

    // stage constants + init misc
    for (int l = tid; l < 1024; l += 256) W1s[l] = W1[l];
    if (tid < 32) {
        b1s[tid] = b1[tid];
        qmws[tid] = qmw[q * 32 + tid];
        qmos[tid] = qmo[q * 32 + tid];
        rffs[tid] = rff[tid];
    }
    if (tid == 0) {
        um[0] = 0; um[1] = 0; um[2] = 0xFFFFFFFFu; um[3] = 0;
        ((int*)um)[4] = KK;
    }
    __syncthreads();

    // ---- phase 1: edist bits + global min ----
    unsigned mymin = 0xFFFFFFFFu;
#pragma unroll
    for (int it = 0; it < 8; it++) {
        int n = tid + it * 256;
        float2 p = ((const float2*)pos)[n];
        float d0 = wrapd(qp0 - p.x);
        float d1 = wrapd(qp1 - p.y);
        float e = d0 * d0 + d1 * d1;
        unsigned eb = __float_as_uint(e);   // e >= 0 -> uint order == float order
        ebits[n] = eb;
        mymin = min(mymin, eb);
    }
#pragma unroll
    for (int o = 16; o; o >>= 1) mymin = min(mymin, __shfl_xor_sync(0xffffffffu, mymin, o));
    if (lane == 0) atomicMin(&um[2], mymin);

    // ---- phase 2: 4-pass radix select for rank-KK smallest edist ----
    for (int pass = 0; pass < 4; pass++) {
        int sh = 24 - 8 * pass;
        if (tid < 256) hist[tid] = 0;
        __syncthreads();
        unsigned pref = um[3];
        unsigned hm = pass ? (0xFFFFFFFFu << (sh + 8)) : 0u;
#pragma unroll
        for (int it = 0; it < 8; it++) {
            unsigned e = ebits[tid + it * 256];
            bool p = ((e & hm) == pref);
            unsigned act = __ballot_sync(0xffffffffu, p);
            if (p) {
                int bin = (e >> sh) & 255;
                unsigned m = __match_any_sync(act, bin);
                if ((__ffs(m) - 1) == lane) atomicAdd(&hist[bin], __popc(m));
            }
        }
        __syncthreads();
        if (tid < 32) {
            int loc[8]; int s0 = 0;
#pragma unroll
            for (int i = 0; i < 8; i++) { loc[i] = hist[tid * 8 + i]; s0 += loc[i]; }
            int inc = s0;
#pragma unroll
            for (int o = 1; o < 32; o <<= 1) {
                int v = __shfl_up_sync(0xffffffffu, inc, o);
                if (tid >= o) inc += v;
            }
            int exc = inc - s0;
            int rk = ((int*)um)[4];
            if (rk > exc && rk <= inc) {
                int rr = rk - exc;
#pragma unroll
                for (int i = 0; i < 8; i++) {
                    if (rr > loc[i]) rr -= loc[i];
                    else { um[3] = pref | ((unsigned)(tid * 8 + i) << sh); ((int*)um)[4] = rr; break; }
                }
            }
        }
        __syncthreads();
    }
    unsigned vsel = um[3];
    int rsel = ((int*)um)[4];

    // ---- phase 3: compaction (set semantics; order irrelevant downstream) ----
#pragma unroll
    for (int it = 0; it < 8; it++) {
        int n = tid + it * 256;
        unsigned e = ebits[n];
        if (e < vsel)       { int p = atomicAdd((int*)&um[0], 1); ind_sh[p] = n; }
        else if (e == vsel) { int p = atomicAdd((int*)&um[1], 1); eq[p] = n; }
    }
    __syncthreads();
    {   // pick rsel smallest indices among equals (JAX tie-break)
        int m = (int)um[1], base = (int)um[0];
        for (int t = tid; t < m; t += 256) {
            int my = eq[t], c = 0;
            for (int i = 0; i < m; i++) c += (eq[i] < my);
            if (c < rsel) ind_sh[base + c] = my;
        }
    }
    if (tid >= KK && tid < KPAD) ind_sh[tid] = 0;
    __syncthreads();

    // ---- phase 4: softmax weights over normalized ed ----
    float ed0 = __uint_as_float(um[2]);
    float edK = __uint_as_float(vsel);
    float invden = 1.0f / ((edK - ed0) + 1e-8f);
    float w = 0.0f; int indv = 0;
    if (tid < KK) {
        indv = ind_sh[tid];
        float e = __uint_as_float(ebits[indv]);
        w = __expf(-(e - ed0) * invden);
    }
    float ws = w;
#pragma unroll
    for (int o = 16; o; o >>= 1) ws += __shfl_xor_sync(0xffffffffu, ws, o);
    if (lane == 0) red[tid >> 5] = ws;
    __syncthreads();
    if (tid < 8) {
        float v = red[tid];
        v += __shfl_xor_sync(0x000000ffu, v, 4);
        v += __shfl_xor_sync(0x000000ffu, v, 2);
        v += __shfl_xor_sync(0x000000ffu, v, 1);
        if (tid == 0) red[0] = v;
    }
    __syncthreads();
    float sk = (tid < KK) ? (w / red[0]) : 0.0f;
    if (tid < KPAD) s_sh[tid] = sk;
    __syncthreads();   // ebits consumed; gs region may be overwritten

    // ---- phase 5: per-k RFF features -> h -> gelu -> gs = g * s (f32x2) ----
    if (tid < KK) {
        float2 pp = ((const float2*)pos)[indv];
        float d0 = wrapd(qp0 - pp.x);
        float d1 = wrapd(qp1 - pp.y);
        float ft[32];
#pragma unroll
        for (int f = 0; f < 16; f++) {
            float p = TWO_PI * (d0 * rffs[f] + d1 * rffs[16 + f]);
            __sincosf(p, &ft[f], &ft[f + 16]);
        }
        unsigned long long h2[16];
        const unsigned long long* b1p = (const unsigned long long*)b1s;
#pragma unroll
        for (int jp = 0; jp < 16; jp++) h2[jp] = b1p[jp];
#pragma unroll 4
        for (int i = 0; i < 32; i++) {
            unsigned long long fi = pk2(ft[i], ft[i]);
            const unsigned long long* w1p = (const unsigned long long*)(W1s + i * 32);
#pragma unroll
            for (int jp = 0; jp < 16; jp++) fma2(h2[jp], fi, w1p[jp]);
        }
        unsigned long long* grow = (unsigned long long*)(gs + tid * GSTR);
#pragma unroll
        for (int jp = 0; jp < 16; jp++) {
            float2 hv = up2(h2[jp]);
            int j0 = 2 * jp;
            float a0 = gelu_exact(hv.x * qmws[j0] + qmos[j0]) * sk;
            float a1 = gelu_exact(hv.y * qmws[j0 + 1] + qmos[j0 + 1]) * sk;
            grow[jp] = pk2(a0, a1);
        }
    } else if (tid < KPAD) {
        unsigned long long* grow = (unsigned long long*)(gs + tid * GSTR);
#pragma unroll
        for (int jp = 0; jp < 16; jp++) grow[jp] = 0ull;
    }
    __syncthreads();   // W1s/b1s/... dead; zs region free for pipeline

    // ---- phase 6: pipelined M/zc accumulation (cp.async double buffer) ----
    unsigned long long acc2[16];
#pragma unroll
    for (int i = 0; i < 16; i++) acc2[i] = 0ull;
    float zca = 0.0f;
    int b = tid >> 5, j = tid & 31;

    // prologue: prefetch tile 0
    {
#pragma unroll
        for (int it = 0; it < 2; it++) {
            int l = tid + it * 256;
            int kk = l >> 6, bb = (l >> 3) & 7, c4 = l & 7;
            int n = ind_sh[kk];
            cpa16(zs + ((kk * 8 + bb) << 5) + c4 * 4,
                  g_xl + ((bb * NN + n) << 5) + c4 * 4);
        }
        cpa_commit();
    }
    for (int t = 0; t < 26; t++) {
        if (t < 25) {
            int k0n = (t + 1) * 8;
            float* nbuf = zs + ((t + 1) & 1) * 2048;
#pragma unroll
            for (int it = 0; it < 2; it++) {
                int l = tid + it * 256;
                int kk = l >> 6, bb = (l >> 3) & 7, c4 = l & 7;
                int n = ind_sh[k0n + kk];
                cpa16(nbuf + ((kk * 8 + bb) << 5) + c4 * 4,
                      g_xl + ((bb * NN + n) << 5) + c4 * 4);
            }
            cpa_commit();
            cpa_wait1();
        } else {
            cpa_wait0();
        }
        __syncthreads();    // tile t visible to all; prior compute done before next overwrite
        const float* buf = zs + (t & 1) * 2048;
        int k0 = t * 8;
#pragma unroll
        for (int kk = 0; kk < 8; kk++) {
            float gv = gs[(k0 + kk) * GSTR + j];
            unsigned long long gv2 = pk2(gv, gv);
            const float* zr = buf + ((kk * 8 + b) << 5);
            zca = fmaf(s_sh[k0 + kk], zr[j], zca);
            const ulonglong2* zr2 = (const ulonglong2*)zr;
#pragma unroll
            for (int c4 = 0; c4 < 8; c4++) {
                ulonglong2 zz = zr2[c4];
                fma2(acc2[2 * c4], gv2, zz.x);
                fma2(acc2[2 * c4 + 1], gv2, zz.y);
            }
        }
        __syncthreads();
    }
    float4* Mout = (float4*)(g_M + ((q * 8 + b) * 32 + j) * 32);
#pragma unroll
    for (int c4 = 0; c4 < 8; c4++) {
        float2 lo = up2(acc2[2 * c4]);
        float2 hi = up2(acc2[2 * c4 + 1]);
        Mout[c4] = make_float4(lo.x, lo.y, hi.x, hi.y);
    }
    g_zc[(q * 8 + b) * 32 + j] = zca;
}

// ---------------- Kernel C: Y1 = M@W2r + zc@filt ; y = gelu(Y1 + bias) ------
__global__ __launch_bounds__(256) void kernC(const float* __restrict__ W2,
                                             const float* __restrict__ filt,
                                             const float* __restrict__ bias) {
    __shared__ float W2t[32 * 64];
    __shared__ float Mt[16 * 32];
    __shared__ float filts[2048];
    __shared__ float zct[16 * 32];
    __shared__ float biass[64];
    int tid = threadIdx.x;
    int rowbase = blockIdx.x * 16;   // rows r = q*8+b ; grid = 128

    for (int l = tid; l < 2048; l += 256) filts[l] = filt[l];
    for (int l = tid; l < 512; l += 256) zct[l] = g_zc[rowbase * 32 + l];
    if (tid < 64) biass[tid] = bias[tid];

    int rg = tid >> 5, d0 = tid & 31;
    float a00 = 0.f, a01 = 0.f, a10 = 0.f, a11 = 0.f;   // rows {rg, rg+8} x cols {d0, d0+32}

    float w2r[8], mr[2];
    // fetch tile 0 into regs
#pragma unroll
    for (int r = 0; r < 8; r++) {
        int l = tid + r * 256;
        int jcl = l >> 6, dd = l & 63;
        w2r[r] = W2[(jcl >> 5) * 2048 + (jcl & 31) * 64 + dd];
    }
#pragma unroll
    for (int r = 0; r < 2; r++) {
        int l = tid + r * 256;
        int rl = l >> 5, jcl = l & 31;
        mr[r] = g_M[(rowbase + rl) * 1024 + jcl];
    }

    for (int t = 0; t < 32; t++) {
        __syncthreads();
#pragma unroll
        for (int r = 0; r < 8; r++) W2t[tid + r * 256] = w2r[r];
#pragma unroll
        for (int r = 0; r < 2; r++) Mt[tid + r * 256] = mr[r];
        __syncthreads();
        if (t < 31) {
            int jc0 = (t + 1) * 32;
#pragma unroll
            for (int r = 0; r < 8; r++) {
                int l = tid + r * 256;
                int jcl = l >> 6, dd = l & 63;
                int jcg = jc0 + jcl;
                w2r[r] = W2[(jcg >> 5) * 2048 + (jcg & 31) * 64 + dd];
            }
#pragma unroll
            for (int r = 0; r < 2; r++) {
                int l = tid + r * 256;
                int rl = l >> 5, jcl = l & 31;
                mr[r] = g_M[(rowbase + rl) * 1024 + jc0 + jcl];
            }
        }
#pragma unroll 8
        for (int jcl = 0; jcl < 32; jcl++) {
            float w0 = W2t[jcl * 64 + d0], w1 = W2t[jcl * 64 + d0 + 32];
            float m0 = Mt[rg * 32 + jcl],  m1 = Mt[(rg + 8) * 32 + jcl];
            a00 = fmaf(m0, w0, a00); a01 = fmaf(m0, w1, a01);
            a10 = fmaf(m1, w0, a10); a11 = fmaf(m1, w1, a11);
        }
    }
#pragma unroll 8
    for (int c = 0; c < 32; c++) {
        float w0 = filts[c * 64 + d0], w1 = filts[c * 64 + d0 + 32];
        float m0 = zct[rg * 32 + c],   m1 = zct[(rg + 8) * 32 + c];
        a00 = fmaf(m0, w0, a00); a01 = fmaf(m0, w1, a01);
        a10 = fmaf(m1, w0, a10); a11 = fmaf(m1, w1, a11);
    }
    int r0 = rowbase + rg, r1 = rowbase + rg + 8;
    int q0 = r0 >> 3, b0 = r0 & 7, q1 = r1 >> 3, b1v = r1 & 7;
    g_y[(b0 * QQ + q0) * 64 + d0]      = gelu_exact(a00 + biass[d0]);
    g_y[(b0 * QQ + q0) * 64 + d0 + 32] = gelu_exact(a01 + biass[d0 + 32]);
    g_y[(b1v * QQ + q1) * 64 + d0]      = gelu_exact(a10 + biass[d0]);
    g_y[(b1v * QQ + q1) * 64 + d0 + 32] = gelu_exact(a11 + biass[d0 + 32]);
}

// ---------------- Kernel D: out = gelu(y@Wm1+bm1)@Wm2 + bm2 + y -------------
__global__ __launch_bounds__(512) void kernD(const float* __restrict__ Wm1,
                                             const float* __restrict__ bm1,
                                             const float* __restrict__ Wm2,
                                             const float* __restrict__ bm2,
                                             float* __restrict__ out) {
    __shared__ float yr[8 * 64];
    __shared__ float ts[8 * 256];
    __shared__ float wsm[4096];
    int tid = threadIdx.x;
    int rb = blockIdx.x * 8;   // rows rbq = b*256+q ; grid = 256
    yr[tid] = g_y[rb * 64 + tid];

    // phase 1: h[l,i] = gelu(bm1[i] + sum_d yr[l,d]*Wm1[d,i])
    int i = tid & 255, lg = tid >> 8;   // lg 0..1 -> rows lg*4..lg*4+3
    float acc[4];
    float bb = bm1[i];
#pragma unroll
    for (int l = 0; l < 4; l++) acc[l] = bb;
    for (int d0 = 0; d0 < 64; d0 += 16) {
        __syncthreads();   // wsm free (also covers yr visibility on first iter)
        for (int l = tid * 4; l < 4096; l += 2048)
            *(float4*)(wsm + l) = *(const float4*)(Wm1 + d0 * 256 + l);
        __syncthreads();
#pragma unroll
        for (int dd = 0; dd < 16; dd++) {
            float wv = wsm[dd * 256 + i];
#pragma unroll
            for (int l = 0; l < 4; l++)
                acc[l] = fmaf(yr[(lg * 4 + l) * 64 + d0 + dd], wv, acc[l]);
        }
    }
#pragma unroll
    for (int l = 0; l < 4; l++) ts[(lg * 4 + l) * 256 + i] = gelu_exact(acc[l]);

    // phase 2: out[l,d] = bm2[d] + yr[l,d] + sum_i ts[l,i]*Wm2[i,d]
    int d = tid & 63, l2 = tid >> 6;    // one row per 64-thread group
    float a0 = 0.f, a1 = 0.f, a2 = 0.f, a3 = 0.f;
    const float* tr = ts + l2 * 256;
    for (int i0 = 0; i0 < 256; i0 += 64) {
        __syncthreads();   // ts written (first iter) / wsm free
        for (int l = tid * 4; l < 4096; l += 2048)
            *(float4*)(wsm + l) = *(const float4*)(Wm2 + i0 * 64 + l);
        __syncthreads();
#pragma unroll
        for (int ii = 0; ii < 64; ii += 4) {
            a0 = fmaf(tr[i0 + ii],     wsm[ii * 64 + d],       a0);
            a1 = fmaf(tr[i0 + ii + 1], wsm[(ii + 1) * 64 + d], a1);
            a2 = fmaf(tr[i0 + ii + 2], wsm[(ii + 2) * 64 + d], a2);
            a3 = fmaf(tr[i0 + ii + 3], wsm[(ii + 3) * 64 + d], a3);
        }
    }
    out[(rb + l2) * 64 + d] = bm2[d] + yr[l2 * 64 + d] + ((a0 + a1) + (a2 + a3));
}

// ---------------- launch ----------------------------------------------------
extern "C" void kernel_launch(void* const* d_in, const int* in_sizes, int n_in,
                              void* d_out, int out_size) {
    const float* x    = (const float*)d_in[0];
    const float* pos  = (const float*)d_in[1];
    const float* qp   = (const float*)d_in[2];
    const float* qmw  = (const float*)d_in[3];
    const float* qmo  = (const float*)d_in[4];
    const float* W_lin = (const float*)d_in[5];
    const float* b_lin = (const float*)d_in[6];
    const float* rff  = (const float*)d_in[7];
    const float* W1   = (const float*)d_in[8];
    const float* b1   = (const float*)d_in[9];
    const float* W2   = (const float*)d_in[10];
    const float* filt = (const float*)d_in[11];
    const float* bias = (const float*)d_in[12];
    const float* Wm1  = (const float*)d_in[13];
    const float* bm1  = (const float*)d_in[14];
    const float* Wm2  = (const float*)d_in[15];
    const float* bm2  = (const float*)d_in[16];
    float* out = (float*)d_out;

    kernA<<<512, 256>>>(x, W_lin, b_lin, qp, out, out_size);
    kernB<<<QQ, 256>>>(pos, qp, qmw, qmo, rff, W1, b1);
    kernC<<<128, 256>>>(W2, filt, bias);
    kernD<<<256, 512>>>(Wm1, bm1, Wm2, bm2, out);
}

// round 4
// speedup vs baseline: 1.8467x; 1.0587x over previous
#include <cuda_runtime.h>
#include <cuda_bf16.h>
#include <math.h>

// Problem constants
#define BB 8
#define NN 2048
#define CC 32
#define DD 64
#define QQ 256
#define KK 205
#define KPAD 208
#define TWO_PI 6.28318530717958647692f

// ---------------- scratch (device globals; no allocations) ----------------
__device__ float g_xl[BB * NN * CC];          // 2 MB   xl[b][n][c]
__device__ float g_M[QQ * BB * CC * CC];      // 8 MB   M[(q*8+b)][j][c]  (row stride 1024)
__device__ float g_zc[QQ * BB * CC];          // 256 KB zc[(q*8+b)][c]
__device__ float g_y[BB * QQ * DD];           // 512 KB y[(b*256+q)][d]

__device__ __forceinline__ float gelu_exact(float v) {
    return 0.5f * v * (1.0f + erff(v * 0.70710678118654752440f));
}
__device__ __forceinline__ float wrapd(float d) {
    float t = d + 0.5f;
    t -= floorf(t);
    return t - 0.5f;
}

// ---- packed f32x2 helpers (sm_100+) ----
__device__ __forceinline__ unsigned long long pk2(float lo, float hi) {
    unsigned long long r;
    asm("mov.b64 %0, {%1,%2};" : "=l"(r) : "f"(lo), "f"(hi));
    return r;
}
__device__ __forceinline__ void fma2(unsigned long long& d, unsigned long long a, unsigned long long b) {
    asm("fma.rn.f32x2 %0, %1, %2, %0;" : "+l"(d) : "l"(a), "l"(b));
}
__device__ __forceinline__ float2 up2(unsigned long long v) {
    float lo, hi;
    asm("mov.b64 {%0,%1}, %2;" : "=f"(lo), "=f"(hi) : "l"(v));
    return make_float2(lo, hi);
}

// ---- cp.async helpers ----
__device__ __forceinline__ void cpa16(float* dst, const float* src) {
    unsigned s = (unsigned)__cvta_generic_to_shared(dst);
    asm volatile("cp.async.cg.shared.global [%0], [%1], 16;" :: "r"(s), "l"(src));
}
__device__ __forceinline__ void cpa_commit() { asm volatile("cp.async.commit_group;" ::: "memory"); }
__device__ __forceinline__ void cpa_wait1() { asm volatile("cp.async.wait_group 1;" ::: "memory"); }
__device__ __forceinline__ void cpa_wait0() { asm volatile("cp.async.wait_group 0;" ::: "memory"); }

// ---------------- Kernel A: xl = x @ W_lin + b_lin ; copy query_pos tail ----
__global__ __launch_bounds__(256) void kernA(const float* __restrict__ x,
                                             const float* __restrict__ W_lin,
                                             const float* __restrict__ b_lin,
                                             const float* __restrict__ qp,
                                             float* __restrict__ out, int out_size) {
    __shared__ float Ws[CC * CC];
    __shared__ float xr[1024];
    __shared__ float bs[CC];
    int tid = threadIdx.x;
    int rowbase = blockIdx.x * 32;   // 32 rows of (b*N+n) per block, grid=512
    for (int l = tid; l < CC * CC; l += 256) Ws[l] = W_lin[l];
    if (tid < CC) bs[tid] = b_lin[tid];
    ((float4*)xr)[tid] = ((const float4*)(x + rowbase * CC))[tid];
    __syncthreads();
    int rg = tid >> 5, c = tid & 31;
    float acc[4];
#pragma unroll
    for (int l = 0; l < 4; l++) acc[l] = bs[c];
#pragma unroll
    for (int i = 0; i < CC; i++) {
        float wv = Ws[i * CC + c];
#pragma unroll
        for (int l = 0; l < 4; l++) acc[l] = fmaf(xr[(rg * 4 + l) * CC + i], wv, acc[l]);
    }
#pragma unroll
    for (int l = 0; l < 4; l++) g_xl[(rowbase + rg * 4 + l) * CC + c] = acc[l];
    if (blockIdx.x == 0) {
        for (int l = tid; l < QQ * 2; l += 256) out[out_size - QQ * 2 + l] = qp[l];
    }
}

// ---------------- Kernel B: per-query topK (radix select) + features + M/zc --
#define GSTR 34
// shared layout (floats), total 11584 = 46.3KB:
//  [0 .. 7071]      gs[KPAD*GSTR]   aliases: ebits[2048]@0, eq[2048]@2048
//  [7072 ..11167]   zs[8 warps][2 slots][8 k][32 c]   aliases (dead by phase 6):
//                     W1s@7072(1024) b1s@8096 qmws@8128 qmos@8160 rffs@8192
//                     hist@8224(256 int) um@8480(8) red@8488(8)
//  [11168..11375]   s_sh[KPAD]
//  [11376..11583]   ind_sh[KPAD] (int)
#define SMB_FLOATS 11584
__global__ __launch_bounds__(256, 2) void kernB(const float* __restrict__ pos,
                                                const float* __restrict__ qp,
                                                const float* __restrict__ qmw,
                                                const float* __restrict__ qmo,
                                                const float* __restrict__ rff,
                                                const float* __restrict__ W1,
                                                const float* __restrict__ b1) {
    __shared__ __align__(16) float sm[SMB_FLOATS];
    unsigned* ebits = (unsigned*)sm;
    int* eq = (int*)(sm + 2048);
    float* gs   = sm;
    float* zs   = sm + 7072;
    float* W1s  = sm + 7072;
    float* b1s  = sm + 8096;
    float* qmws = sm + 8128;
    float* qmos = sm + 8160;
    float* rffs = sm + 8192;
    int*   hist = (int*)(sm + 8224);
    unsigned* um = (unsigned*)(sm + 8480);
    float* red  = sm + 8488;
    float* s_sh = sm + 11168;
    int*   ind_sh = (int*)(sm + 11376);

    int q = blockIdx.x, tid = threadIdx.x;
    int lane = tid & 31;
    float qp0 = qp[2 * q], qp1 = qp[2 * q + 1];

    // stage constants + init misc
    for (int l = tid; l < 1024; l += 256) W1s[l] = W1[l];
    if (tid < 32) {
        b1s[tid] = b1[tid];
        qmws[tid] = qmw[q * 32 + tid];
        qmos[tid] = qmo[q * 32 + tid];
        rffs[tid] = rff[tid];
    }
    if (tid == 0) {
        um[0] = 0; um[1] = 0; um[2] = 0xFFFFFFFFu; um[3] = 0;
        ((int*)um)[4] = KK;
    }
    __syncthreads();

    // ---- phase 1: edist bits + global min ----
    unsigned mymin = 0xFFFFFFFFu;
#pragma unroll
    for (int it = 0; it < 8; it++) {
        int n = tid + it * 256;
        float2 p = ((const float2*)pos)[n];
        float d0 = wrapd(qp0 - p.x);
        float d1 = wrapd(qp1 - p.y);
        float e = d0 * d0 + d1 * d1;
        unsigned eb = __float_as_uint(e);   // e >= 0 -> uint order == float order
        ebits[n] = eb;
        mymin = min(mymin, eb);
    }
#pragma unroll
    for (int o = 16; o; o >>= 1) mymin = min(mymin, __shfl_xor_sync(0xffffffffu, mymin, o));
    if (lane == 0) atomicMin(&um[2], mymin);

    // ---- phase 2: 4-pass radix select for rank-KK smallest edist ----
    for (int pass = 0; pass < 4; pass++) {
        int sh = 24 - 8 * pass;
        if (tid < 256) hist[tid] = 0;
        __syncthreads();
        unsigned pref = um[3];
        unsigned hm = pass ? (0xFFFFFFFFu << (sh + 8)) : 0u;
#pragma unroll
        for (int it = 0; it < 8; it++) {
            unsigned e = ebits[tid + it * 256];
            bool p = ((e & hm) == pref);
            unsigned act = __ballot_sync(0xffffffffu, p);
            if (p) {
                int bin = (e >> sh) & 255;
                unsigned m = __match_any_sync(act, bin);
                if ((__ffs(m) - 1) == lane) atomicAdd(&hist[bin], __popc(m));
            }
        }
        __syncthreads();
        if (tid < 32) {
            int loc[8]; int s0 = 0;
#pragma unroll
            for (int i = 0; i < 8; i++) { loc[i] = hist[tid * 8 + i]; s0 += loc[i]; }
            int inc = s0;
#pragma unroll
            for (int o = 1; o < 32; o <<= 1) {
                int v = __shfl_up_sync(0xffffffffu, inc, o);
                if (tid >= o) inc += v;
            }
            int exc = inc - s0;
            int rk = ((int*)um)[4];
            if (rk > exc && rk <= inc) {
                int rr = rk - exc;
#pragma unroll
                for (int i = 0; i < 8; i++) {
                    if (rr > loc[i]) rr -= loc[i];
                    else { um[3] = pref | ((unsigned)(tid * 8 + i) << sh); ((int*)um)[4] = rr; break; }
                }
            }
        }
        __syncthreads();
    }
    unsigned vsel = um[3];
    int rsel = ((int*)um)[4];

    // ---- phase 3: compaction (set semantics; order irrelevant downstream) ----
#pragma unroll
    for (int it = 0; it < 8; it++) {
        int n = tid + it * 256;
        unsigned e = ebits[n];
        if (e < vsel)       { int p = atomicAdd((int*)&um[0], 1); ind_sh[p] = n; }
        else if (e == vsel) { int p = atomicAdd((int*)&um[1], 1); eq[p] = n; }
    }
    __syncthreads();
    {   // pick rsel smallest indices among equals (JAX tie-break)
        int m = (int)um[1], base = (int)um[0];
        for (int t = tid; t < m; t += 256) {
            int my = eq[t], c = 0;
            for (int i = 0; i < m; i++) c += (eq[i] < my);
            if (c < rsel) ind_sh[base + c] = my;
        }
    }
    if (tid >= KK && tid < KPAD) ind_sh[tid] = 0;
    __syncthreads();

    // ---- phase 4: softmax weights over normalized ed ----
    float ed0 = __uint_as_float(um[2]);
    float edK = __uint_as_float(vsel);
    float invden = 1.0f / ((edK - ed0) + 1e-8f);
    float w = 0.0f; int indv = 0;
    if (tid < KK) {
        indv = ind_sh[tid];
        float e = __uint_as_float(ebits[indv]);
        w = __expf(-(e - ed0) * invden);
    }
    float ws = w;
#pragma unroll
    for (int o = 16; o; o >>= 1) ws += __shfl_xor_sync(0xffffffffu, ws, o);
    if (lane == 0) red[tid >> 5] = ws;
    __syncthreads();
    if (tid < 8) {
        float v = red[tid];
        v += __shfl_xor_sync(0x000000ffu, v, 4);
        v += __shfl_xor_sync(0x000000ffu, v, 2);
        v += __shfl_xor_sync(0x000000ffu, v, 1);
        if (tid == 0) red[0] = v;
    }
    __syncthreads();
    float sk = (tid < KK) ? (w / red[0]) : 0.0f;
    if (tid < KPAD) s_sh[tid] = sk;
    __syncthreads();   // ebits consumed; gs region may be overwritten

    // ---- phase 5: per-k RFF features -> h -> gelu -> gs = g * s (f32x2) ----
    if (tid < KK) {
        float2 pp = ((const float2*)pos)[indv];
        float d0 = wrapd(qp0 - pp.x);
        float d1 = wrapd(qp1 - pp.y);
        float ft[32];
#pragma unroll
        for (int f = 0; f < 16; f++) {
            float p = TWO_PI * (d0 * rffs[f] + d1 * rffs[16 + f]);
            __sincosf(p, &ft[f], &ft[f + 16]);
        }
        unsigned long long h2[16];
        const unsigned long long* b1p = (const unsigned long long*)b1s;
#pragma unroll
        for (int jp = 0; jp < 16; jp++) h2[jp] = b1p[jp];
#pragma unroll 4
        for (int i = 0; i < 32; i++) {
            unsigned long long fi = pk2(ft[i], ft[i]);
            const unsigned long long* w1p = (const unsigned long long*)(W1s + i * 32);
#pragma unroll
            for (int jp = 0; jp < 16; jp++) fma2(h2[jp], fi, w1p[jp]);
        }
        unsigned long long* grow = (unsigned long long*)(gs + tid * GSTR);
#pragma unroll
        for (int jp = 0; jp < 16; jp++) {
            float2 hv = up2(h2[jp]);
            int j0 = 2 * jp;
            float a0 = gelu_exact(hv.x * qmws[j0] + qmos[j0]) * sk;
            float a1 = gelu_exact(hv.y * qmws[j0 + 1] + qmos[j0 + 1]) * sk;
            grow[jp] = pk2(a0, a1);
        }
    } else if (tid < KPAD) {
        unsigned long long* grow = (unsigned long long*)(gs + tid * GSTR);
#pragma unroll
        for (int jp = 0; jp < 16; jp++) grow[jp] = 0ull;
    }
    __syncthreads();   // W1s/... dead; zs region free; gs/s_sh/ind_sh stable

    // ---- phase 6: WARP-LOCAL pipelined M/zc accumulation (no block barriers) --
    // warp b reads only its own gathered rows -> private double buffer per warp.
    unsigned long long acc2[16];
#pragma unroll
    for (int i = 0; i < 16; i++) acc2[i] = 0ull;
    float zca = 0.0f;
    int b = tid >> 5, j = tid & 31;
    float* zw = zs + b * 512;         // [2 slots][8 k][32 c]
    int kkl = j >> 2, c4l = j & 3;    // lane covers row kkl, chunks {c4l, c4l+4}

    // prologue: tile 0 -> slot 0
    {
        int n = ind_sh[kkl];
        const float* src = g_xl + ((b * NN + n) << 5);
        cpa16(zw + kkl * 32 + c4l * 4,       src + c4l * 4);
        cpa16(zw + kkl * 32 + (c4l + 4) * 4, src + (c4l + 4) * 4);
        cpa_commit();
    }
    for (int t = 0; t < 26; t++) {
        __syncwarp();   // all lanes done computing tile t-1 -> safe to overwrite its slot
        if (t < 25) {
            int k0n = (t + 1) * 8;
            float* nb = zw + ((t + 1) & 1) * 256;
            int n = ind_sh[k0n + kkl];
            const float* src = g_xl + ((b * NN + n) << 5);
            cpa16(nb + kkl * 32 + c4l * 4,       src + c4l * 4);
            cpa16(nb + kkl * 32 + (c4l + 4) * 4, src + (c4l + 4) * 4);
            cpa_commit();
            cpa_wait1();
        } else {
            cpa_wait0();
        }
        __syncwarp();   // tile t from all lanes visible
        const float* buf = zw + (t & 1) * 256;
        int k0 = t * 8;
#pragma unroll
        for (int kk = 0; kk < 8; kk++) {
            float gv = gs[(k0 + kk) * GSTR + j];
            unsigned long long gv2 = pk2(gv, gv);
            const float* zr = buf + (kk << 5);
            zca = fmaf(s_sh[k0 + kk], zr[j], zca);
            const ulonglong2* zr2 = (const ulonglong2*)zr;
#pragma unroll
            for (int c4 = 0; c4 < 8; c4++) {
                ulonglong2 zz = zr2[c4];
                fma2(acc2[2 * c4], gv2, zz.x);
                fma2(acc2[2 * c4 + 1], gv2, zz.y);
            }
        }
    }
    float4* Mout = (float4*)(g_M + ((q * 8 + b) * 32 + j) * 32);
#pragma unroll
    for (int c4 = 0; c4 < 8; c4++) {
        float2 lo = up2(acc2[2 * c4]);
        float2 hi = up2(acc2[2 * c4 + 1]);
        Mout[c4] = make_float4(lo.x, lo.y, hi.x, hi.y);
    }
    g_zc[(q * 8 + b) * 32 + j] = zca;
}

// ---------------- Kernel C: Y1 = M@W2r + zc@filt ; y = gelu(Y1 + bias) ------
// 3-stage cp.async ring, ONE barrier per tile.
__global__ __launch_bounds__(256) void kernC(const float* __restrict__ W2,
                                             const float* __restrict__ filt,
                                             const float* __restrict__ bias) {
    __shared__ __align__(16) float W2t[3 * 2048];
    __shared__ __align__(16) float Mt[3 * 512];
    __shared__ float filts[2048];
    __shared__ float zct[16 * 32];
    __shared__ float biass[64];
    int tid = threadIdx.x;
    int rowbase = blockIdx.x * 16;   // rows r = q*8+b ; grid = 128

    for (int l = tid; l < 2048; l += 256) filts[l] = filt[l];
    for (int l = tid; l < 512; l += 256) zct[l] = g_zc[rowbase * 32 + l];
    if (tid < 64) biass[tid] = bias[tid];

    int rg = tid >> 5, d0 = tid & 31;
    float a00 = 0.f, a01 = 0.f, a10 = 0.f, a11 = 0.f;   // rows {rg, rg+8} x cols {d0, d0+32}

    // tile issuer: tile jc0 = tt*32 -> slot tt%3
    auto issue = [&](int tt) {
        float* Wd = W2t + (tt % 3) * 2048;
        float* Md = Mt + (tt % 3) * 512;
        int jc0 = tt * 32;
#pragma unroll
        for (int r = 0; r < 2; r++) {
            int ch = tid + r * 256;                  // 512 chunks of 4 floats
            int jcl = ch >> 4, dd4 = (ch & 15) * 4;
            int jcg = jc0 + jcl;
            cpa16(Wd + jcl * 64 + dd4, W2 + (jcg >> 5) * 2048 + (jcg & 31) * 64 + dd4);
        }
        if (tid < 128) {
            int rl = tid >> 3, j4 = (tid & 7) * 4;   // 128 chunks of 4 floats
            cpa16(Md + rl * 32 + j4, g_M + (rowbase + rl) * 1024 + jc0 + j4);
        }
        cpa_commit();
    };

    issue(0);
    for (int t = 0; t < 32; t++) {
        if (t < 31) { issue(t + 1); cpa_wait1(); }
        else cpa_wait0();
        __syncthreads();
        const float* Wb = W2t + (t % 3) * 2048;
        const float* Mb = Mt + (t % 3) * 512;
#pragma unroll 8
        for (int jcl = 0; jcl < 32; jcl++) {
            float w0 = Wb[jcl * 64 + d0], w1 = Wb[jcl * 64 + d0 + 32];
            float m0 = Mb[rg * 32 + jcl], m1 = Mb[(rg + 8) * 32 + jcl];
            a00 = fmaf(m0, w0, a00); a01 = fmaf(m0, w1, a01);
            a10 = fmaf(m1, w0, a10); a11 = fmaf(m1, w1, a11);
        }
    }
#pragma unroll 8
    for (int c = 0; c < 32; c++) {
        float w0 = filts[c * 64 + d0], w1 = filts[c * 64 + d0 + 32];
        float m0 = zct[rg * 32 + c],   m1 = zct[(rg + 8) * 32 + c];
        a00 = fmaf(m0, w0, a00); a01 = fmaf(m0, w1, a01);
        a10 = fmaf(m1, w0, a10); a11 = fmaf(m1, w1, a11);
    }
    int r0 = rowbase + rg, r1 = rowbase + rg + 8;
    int q0 = r0 >> 3, b0 = r0 & 7, q1 = r1 >> 3, b1v = r1 & 7;
    g_y[(b0 * QQ + q0) * 64 + d0]      = gelu_exact(a00 + biass[d0]);
    g_y[(b0 * QQ + q0) * 64 + d0 + 32] = gelu_exact(a01 + biass[d0 + 32]);
    g_y[(b1v * QQ + q1) * 64 + d0]      = gelu_exact(a10 + biass[d0]);
    g_y[(b1v * QQ + q1) * 64 + d0 + 32] = gelu_exact(a11 + biass[d0 + 32]);
}

// ---------------- Kernel D: out = gelu(y@Wm1+bm1)@Wm2 + bm2 + y -------------
// 3-stage cp.async weight streaming, one barrier per 8KB chunk.
__global__ __launch_bounds__(512) void kernD(const float* __restrict__ Wm1,
                                             const float* __restrict__ bm1,
                                             const float* __restrict__ Wm2,
                                             const float* __restrict__ bm2,
                                             float* __restrict__ out) {
    __shared__ float yr[8 * 64];
    __shared__ float ts[8 * 256];
    __shared__ __align__(16) float wsm[3 * 2048];
    int tid = threadIdx.x;
    int rb = blockIdx.x * 8;   // rows rbq = b*256+q ; grid = 256
    yr[tid] = g_y[rb * 64 + tid];

    // ---- phase 1: h[l,i] = gelu(bm1[i] + sum_d yr[l,d]*Wm1[d,i]) ----
    int i = tid & 255, lg = tid >> 8;   // lg 0..1 -> rows lg*4..lg*4+3
    float acc[4];
    float bb = bm1[i];
#pragma unroll
    for (int l = 0; l < 4; l++) acc[l] = bb;

    // chunks: 8 chunks of 8 d-rows (2048 floats each)
    auto issue1 = [&](int tt) {
        cpa16(wsm + (tt % 3) * 2048 + tid * 4, Wm1 + tt * 2048 + tid * 4);
        cpa_commit();
    };
    issue1(0);
    for (int t = 0; t < 8; t++) {
        if (t < 7) { issue1(t + 1); cpa_wait1(); }
        else cpa_wait0();
        __syncthreads();      // first one also covers yr visibility
        const float* wb = wsm + (t % 3) * 2048;
        int d0 = t * 8;
#pragma unroll
        for (int dd = 0; dd < 8; dd++) {
            float wv = wb[dd * 256 + i];
#pragma unroll
            for (int l = 0; l < 4; l++)
                acc[l] = fmaf(yr[(lg * 4 + l) * 64 + d0 + dd], wv, acc[l]);
        }
    }
#pragma unroll
    for (int l = 0; l < 4; l++) ts[(lg * 4 + l) * 256 + i] = gelu_exact(acc[l]);
    __syncthreads();          // ts ready; wsm slots free for phase 2

    // ---- phase 2: out[l,d] = bm2[d] + yr[l,d] + sum_i ts[l,i]*Wm2[i,d] ----
    int d = tid & 63, l2 = tid >> 6;    // one row per 64-thread group
    float a0 = 0.f, a1 = 0.f, a2 = 0.f, a3 = 0.f;
    const float* tr = ts + l2 * 256;
    auto issue2 = [&](int tt) {
        cpa16(wsm + (tt % 3) * 2048 + tid * 4, Wm2 + tt * 2048 + tid * 4);
        cpa_commit();
    };
    issue2(0);
    for (int t = 0; t < 8; t++) {
        if (t < 7) { issue2(t + 1); cpa_wait1(); }
        else cpa_wait0();
        __syncthreads();
        const float* wb = wsm + (t % 3) * 2048;
        int i0 = t * 32;
#pragma unroll
        for (int ii = 0; ii < 32; ii += 4) {
            a0 = fmaf(tr[i0 + ii],     wb[ii * 64 + d],       a0);
            a1 = fmaf(tr[i0 + ii + 1], wb[(ii + 1) * 64 + d], a1);
            a2 = fmaf(tr[i0 + ii + 2], wb[(ii + 2) * 64 + d], a2);
            a3 = fmaf(tr[i0 + ii + 3], wb[(ii + 3) * 64 + d], a3);
        }
    }
    out[(rb + l2) * 64 + d] = bm2[d] + yr[l2 * 64 + d] + ((a0 + a1) + (a2 + a3));
}

// ---------------- launch ----------------------------------------------------
extern "C" void kernel_launch(void* const* d_in, const int* in_sizes, int n_in,
                              void* d_out, int out_size) {
    const float* x    = (const float*)d_in[0];
    const float* pos  = (const float*)d_in[1];
    const float* qp   = (const float*)d_in[2];
    const float* qmw  = (const float*)d_in[3];
    const float* qmo  = (const float*)d_in[4];
    const float* W_lin = (const float*)d_in[5];
    const float* b_lin = (const float*)d_in[6];
    const float* rff  = (const float*)d_in[7];
    const float* W1   = (const float*)d_in[8];
    const float* b1   = (const float*)d_in[9];
    const float* W2   = (const float*)d_in[10];
    const float* filt = (const float*)d_in[11];
    const float* bias = (const float*)d_in[12];
    const float* Wm1  = (const float*)d_in[13];
    const float* bm1  = (const float*)d_in[14];
    const float* Wm2  = (const float*)d_in[15];
    const float* bm2  = (const float*)d_in[16];
    float* out = (float*)d_out;

    kernA<<<512, 256>>>(x, W_lin, b_lin, qp, out, out_size);
    kernB<<<QQ, 256>>>(pos, qp, qmw, qmo, rff, W1, b1);
    kernC<<<128, 256>>>(W2, filt, bias);
    kernD<<<256, 512>>>(Wm1, bm1, Wm2, bm2, out);
}

// round 5
// speedup vs baseline: 2.3435x; 1.2690x over previous
#include <cuda_runtime.h>
#include <cuda_bf16.h>
#include <math.h>

// Problem constants
#define BB 8
#define NN 2048
#define CC 32
#define DD 64
#define QQ 256
#define KK 205
#define KPAD 208
#define TWO_PI 6.28318530717958647692f

// ---------------- scratch (device globals; no allocations) ----------------
__device__ float g_xl[BB * NN * CC];          // 2 MB   xl[b][n][c]  (tf32-rounded)
__device__ float g_M[QQ * BB * CC * CC];      // 8 MB   M[(q*8+b)][j][c]
__device__ float g_zc[QQ * BB * CC];          // 256 KB zc[(q*8+b)][c]
__device__ float g_y[BB * QQ * DD];           // 512 KB y[(b*256+q)][d]

__device__ __forceinline__ float gelu_exact(float v) {
    return 0.5f * v * (1.0f + erff(v * 0.70710678118654752440f));
}
__device__ __forceinline__ float wrapd(float d) {
    float t = d + 0.5f;
    t -= floorf(t);
    return t - 0.5f;
}

// ---- packed f32x2 helpers (sm_100+) ----
__device__ __forceinline__ unsigned long long pk2(float lo, float hi) {
    unsigned long long r;
    asm("mov.b64 %0, {%1,%2};" : "=l"(r) : "f"(lo), "f"(hi));
    return r;
}
__device__ __forceinline__ void fma2(unsigned long long& d, unsigned long long a, unsigned long long b) {
    asm("fma.rn.f32x2 %0, %1, %2, %0;" : "+l"(d) : "l"(a), "l"(b));
}
__device__ __forceinline__ float2 up2(unsigned long long v) {
    float lo, hi;
    asm("mov.b64 {%0,%1}, %2;" : "=f"(lo), "=f"(hi) : "l"(v));
    return make_float2(lo, hi);
}
__device__ __forceinline__ unsigned cvt_tf32(float f) {
    unsigned u;
    asm("cvt.rna.tf32.f32 %0, %1;" : "=r"(u) : "f"(f));
    return u;
}
// tf32 warp MMA: D(16x8) += A(16x8) * B(8x8)
__device__ __forceinline__ void mma_tf32(float* d, unsigned a0, unsigned a1,
                                         unsigned a2, unsigned a3,
                                         unsigned b0, unsigned b1) {
    asm volatile(
        "mma.sync.aligned.m16n8k8.row.col.f32.tf32.tf32.f32 "
        "{%0,%1,%2,%3}, {%4,%5,%6,%7}, {%8,%9}, {%0,%1,%2,%3};"
        : "+f"(d[0]), "+f"(d[1]), "+f"(d[2]), "+f"(d[3])
        : "r"(a0), "r"(a1), "r"(a2), "r"(a3), "r"(b0), "r"(b1));
}

// ---- cp.async helpers ----
__device__ __forceinline__ void cpa16(float* dst, const float* src) {
    unsigned s = (unsigned)__cvta_generic_to_shared(dst);
    asm volatile("cp.async.cg.shared.global [%0], [%1], 16;" :: "r"(s), "l"(src));
}
__device__ __forceinline__ void cpa_commit() { asm volatile("cp.async.commit_group;" ::: "memory"); }
__device__ __forceinline__ void cpa_wait1() { asm volatile("cp.async.wait_group 1;" ::: "memory"); }
__device__ __forceinline__ void cpa_wait0() { asm volatile("cp.async.wait_group 0;" ::: "memory"); }

// ---------------- Kernel A: xl = tf32(x @ W_lin + b_lin) ; copy query_pos ---
__global__ __launch_bounds__(256) void kernA(const float* __restrict__ x,
                                             const float* __restrict__ W_lin,
                                             const float* __restrict__ b_lin,
                                             const float* __restrict__ qp,
                                             float* __restrict__ out, int out_size) {
    __shared__ float Ws[CC * CC];
    __shared__ float xr[1024];
    __shared__ float bs[CC];
    int tid = threadIdx.x;
    int rowbase = blockIdx.x * 32;   // 32 rows of (b*N+n) per block, grid=512
    for (int l = tid; l < CC * CC; l += 256) Ws[l] = W_lin[l];
    if (tid < CC) bs[tid] = b_lin[tid];
    ((float4*)xr)[tid] = ((const float4*)(x + rowbase * CC))[tid];
    __syncthreads();
    int rg = tid >> 5, c = tid & 31;
    float acc[4];
#pragma unroll
    for (int l = 0; l < 4; l++) acc[l] = bs[c];
#pragma unroll
    for (int i = 0; i < CC; i++) {
        float wv = Ws[i * CC + c];
#pragma unroll
        for (int l = 0; l < 4; l++) acc[l] = fmaf(xr[(rg * 4 + l) * CC + i], wv, acc[l]);
    }
#pragma unroll
    for (int l = 0; l < 4; l++)
        g_xl[(rowbase + rg * 4 + l) * CC + c] = __uint_as_float(cvt_tf32(acc[l]));
    if (blockIdx.x == 0) {
        for (int l = tid; l < QQ * 2; l += 256) out[out_size - QQ * 2 + l] = qp[l];
    }
}

// ---------------- Kernel B: per-query topK (radix select) + features + M/zc --
#define GSTR 34
// shared layout (floats), total 11584 = 46.3KB:
//  [0 .. 7071]      gs[KPAD*GSTR]  (tf32 bits)  aliases: ebits[2048]@0, eq[2048]@2048
//  [7072 ..11167]   zs[8 warps][2 slots][8 k][32 c swizzled]   aliases (dead by ph6):
//                     W1s@7072(1024) b1s@8096 qmws@8128 qmos@8160 rffs@8192
//                     hist@8224(256 int) um@8480(8) red@8488(8)
//  [11168..11375]   s_sh[KPAD]
//  [11376..11583]   ind_sh[KPAD] (int)
#define SMB_FLOATS 11584
__global__ __launch_bounds__(256, 2) void kernB(const float* __restrict__ pos,
                                                const float* __restrict__ qp,
                                                const float* __restrict__ qmw,
                                                const float* __restrict__ qmo,
                                                const float* __restrict__ rff,
                                                const float* __restrict__ W1,
                                                const float* __restrict__ b1) {
    __shared__ __align__(16) float sm[SMB_FLOATS];
    unsigned* ebits = (unsigned*)sm;
    int* eq = (int*)(sm + 2048);
    float* gs   = sm;
    float* zs   = sm + 7072;
    float* W1s  = sm + 7072;
    float* b1s  = sm + 8096;
    float* qmws = sm + 8128;
    float* qmos = sm + 8160;
    float* rffs = sm + 8192;
    int*   hist = (int*)(sm + 8224);
    unsigned* um = (unsigned*)(sm + 8480);
    float* red  = sm + 8488;
    float* s_sh = sm + 11168;
    int*   ind_sh = (int*)(sm + 11376);

    int q = blockIdx.x, tid = threadIdx.x;
    int lane = tid & 31;
    float qp0 = qp[2 * q], qp1 = qp[2 * q + 1];

    // stage constants + init misc
    for (int l = tid; l < 1024; l += 256) W1s[l] = W1[l];
    if (tid < 32) {
        b1s[tid] = b1[tid];
        qmws[tid] = qmw[q * 32 + tid];
        qmos[tid] = qmo[q * 32 + tid];
        rffs[tid] = rff[tid];
    }
    if (tid == 0) {
        um[0] = 0; um[1] = 0; um[2] = 0xFFFFFFFFu; um[3] = 0;
        ((int*)um)[4] = KK;
    }
    __syncthreads();

    // ---- phase 1: edist bits + global min ----
    unsigned mymin = 0xFFFFFFFFu;
#pragma unroll
    for (int it = 0; it < 8; it++) {
        int n = tid + it * 256;
        float2 p = ((const float2*)pos)[n];
        float d0 = wrapd(qp0 - p.x);
        float d1 = wrapd(qp1 - p.y);
        float e = d0 * d0 + d1 * d1;
        unsigned eb = __float_as_uint(e);
        ebits[n] = eb;
        mymin = min(mymin, eb);
    }
#pragma unroll
    for (int o = 16; o; o >>= 1) mymin = min(mymin, __shfl_xor_sync(0xffffffffu, mymin, o));
    if (lane == 0) atomicMin(&um[2], mymin);

    // ---- phase 2: 4-pass radix select for rank-KK smallest edist ----
    for (int pass = 0; pass < 4; pass++) {
        int sh = 24 - 8 * pass;
        if (tid < 256) hist[tid] = 0;
        __syncthreads();
        unsigned pref = um[3];
        unsigned hm = pass ? (0xFFFFFFFFu << (sh + 8)) : 0u;
#pragma unroll
        for (int it = 0; it < 8; it++) {
            unsigned e = ebits[tid + it * 256];
            bool p = ((e & hm) == pref);
            unsigned act = __ballot_sync(0xffffffffu, p);
            if (p) {
                int bin = (e >> sh) & 255;
                unsigned m = __match_any_sync(act, bin);
                if ((__ffs(m) - 1) == lane) atomicAdd(&hist[bin], __popc(m));
            }
        }
        __syncthreads();
        if (tid < 32) {
            int loc[8]; int s0 = 0;
#pragma unroll
            for (int i = 0; i < 8; i++) { loc[i] = hist[tid * 8 + i]; s0 += loc[i]; }
            int inc = s0;
#pragma unroll
            for (int o = 1; o < 32; o <<= 1) {
                int v = __shfl_up_sync(0xffffffffu, inc, o);
                if (tid >= o) inc += v;
            }
            int exc = inc - s0;
            int rk = ((int*)um)[4];
            if (rk > exc && rk <= inc) {
                int rr = rk - exc;
#pragma unroll
                for (int i = 0; i < 8; i++) {
                    if (rr > loc[i]) rr -= loc[i];
                    else { um[3] = pref | ((unsigned)(tid * 8 + i) << sh); ((int*)um)[4] = rr; break; }
                }
            }
        }
        __syncthreads();
    }
    unsigned vsel = um[3];
    int rsel = ((int*)um)[4];

    // ---- phase 3: compaction ----
#pragma unroll
    for (int it = 0; it < 8; it++) {
        int n = tid + it * 256;
        unsigned e = ebits[n];
        if (e < vsel)       { int p = atomicAdd((int*)&um[0], 1); ind_sh[p] = n; }
        else if (e == vsel) { int p = atomicAdd((int*)&um[1], 1); eq[p] = n; }
    }
    __syncthreads();
    {   // pick rsel smallest indices among equals (JAX tie-break)
        int m = (int)um[1], base = (int)um[0];
        for (int t = tid; t < m; t += 256) {
            int my = eq[t], c = 0;
            for (int i = 0; i < m; i++) c += (eq[i] < my);
            if (c < rsel) ind_sh[base + c] = my;
        }
    }
    if (tid >= KK && tid < KPAD) ind_sh[tid] = 0;
    __syncthreads();

    // ---- phase 4: softmax weights over normalized ed ----
    float ed0 = __uint_as_float(um[2]);
    float edK = __uint_as_float(vsel);
    float invden = 1.0f / ((edK - ed0) + 1e-8f);
    float w = 0.0f; int indv = 0;
    if (tid < KK) {
        indv = ind_sh[tid];
        float e = __uint_as_float(ebits[indv]);
        w = __expf(-(e - ed0) * invden);
    }
    float ws = w;
#pragma unroll
    for (int o = 16; o; o >>= 1) ws += __shfl_xor_sync(0xffffffffu, ws, o);
    if (lane == 0) red[tid >> 5] = ws;
    __syncthreads();
    if (tid < 8) {
        float v = red[tid];
        v += __shfl_xor_sync(0x000000ffu, v, 4);
        v += __shfl_xor_sync(0x000000ffu, v, 2);
        v += __shfl_xor_sync(0x000000ffu, v, 1);
        if (tid == 0) red[0] = v;
    }
    __syncthreads();
    float sk = (tid < KK) ? (w / red[0]) : 0.0f;
    if (tid < KPAD) s_sh[tid] = sk;
    __syncthreads();   // ebits consumed; gs region may be overwritten

    // ---- phase 5: per-k RFF features -> h -> gelu -> gs = tf32(g * s) ----
    if (tid < KK) {
        float2 pp = ((const float2*)pos)[indv];
        float d0 = wrapd(qp0 - pp.x);
        float d1 = wrapd(qp1 - pp.y);
        float ft[32];
#pragma unroll
        for (int f = 0; f < 16; f++) {
            float p = TWO_PI * (d0 * rffs[f] + d1 * rffs[16 + f]);
            __sincosf(p, &ft[f], &ft[f + 16]);
        }
        unsigned long long h2[16];
        const unsigned long long* b1p = (const unsigned long long*)b1s;
#pragma unroll
        for (int jp = 0; jp < 16; jp++) h2[jp] = b1p[jp];
#pragma unroll 4
        for (int i = 0; i < 32; i++) {
            unsigned long long fi = pk2(ft[i], ft[i]);
            const unsigned long long* w1p = (const unsigned long long*)(W1s + i * 32);
#pragma unroll
            for (int jp = 0; jp < 16; jp++) fma2(h2[jp], fi, w1p[jp]);
        }
        unsigned long long* grow = (unsigned long long*)(gs + tid * GSTR);
#pragma unroll
        for (int jp = 0; jp < 16; jp++) {
            float2 hv = up2(h2[jp]);
            int j0 = 2 * jp;
            float a0 = gelu_exact(hv.x * qmws[j0] + qmos[j0]) * sk;
            float a1 = gelu_exact(hv.y * qmws[j0 + 1] + qmos[j0 + 1]) * sk;
            unsigned u0 = cvt_tf32(a0), u1 = cvt_tf32(a1);
            grow[jp] = ((unsigned long long)u1 << 32) | u0;
        }
    } else if (tid < KPAD) {
        unsigned long long* grow = (unsigned long long*)(gs + tid * GSTR);
#pragma unroll
        for (int jp = 0; jp < 16; jp++) grow[jp] = 0ull;
    }
    __syncthreads();   // W1s/... dead; zs free; gs/s_sh/ind_sh stable

    // ---- phase 6: tf32 tensor-core M accumulation, warp-local gather -------
    // Warp b: M[b](32j x 32c) = gs^T(32j x 208k) @ xg[b](208k x 32c)
    // zs row swizzle: chunk c4 of row kk stored at chunk (c4 ^ (2*(kk&3))).
    int b = tid >> 5;
    int tg = lane >> 2, tc = lane & 3;
    float* zw = zs + b * 512;                 // [2 slots][8 rows][32 c]
    int kkl = lane >> 2, c4l = lane & 3;      // gather role
    int swA = ((c4l ^ (2 * (kkl & 3))) & 7) * 4;
    int swB = (((c4l + 4) ^ (2 * (kkl & 3))) & 7) * 4;

    float dacc[2][4][4];
#pragma unroll
    for (int mt = 0; mt < 2; mt++)
#pragma unroll
        for (int nt = 0; nt < 4; nt++)
#pragma unroll
            for (int r = 0; r < 4; r++) dacc[mt][nt][r] = 0.0f;
    float zca = 0.0f;

    // prologue: tile 0 -> slot 0
    {
        int n = ind_sh[kkl];
        const float* src = g_xl + ((b * NN + n) << 5);
        cpa16(zw + kkl * 32 + swA, src + c4l * 4);
        cpa16(zw + kkl * 32 + swB, src + (c4l + 4) * 4);
        cpa_commit();
    }
    for (int t = 0; t < 26; t++) {
        __syncwarp();   // prior reads of the slot being overwritten are done
        if (t < 25) {
            int k0n = (t + 1) * 8;
            float* nb = zw + ((t + 1) & 1) * 256;
            int n = ind_sh[k0n + kkl];
            const float* src = g_xl + ((b * NN + n) << 5);
            cpa16(nb + kkl * 32 + swA, src + c4l * 4);
            cpa16(nb + kkl * 32 + swB, src + (c4l + 4) * 4);
            cpa_commit();
            cpa_wait1();
        } else {
            cpa_wait0();
        }
        __syncwarp();
        const float* buf = zw + (t & 1) * 256;
        int k0 = t * 8;
        // zc accumulation (lane = column)
#pragma unroll
        for (int kk = 0; kk < 8; kk++)
            zca = fmaf(s_sh[k0 + kk], buf[kk * 32 + (lane ^ (8 * (kk & 3)))], zca);
        // B fragments (k8 x n8), rows tc / tc+4, cols cb+tg
        unsigned bf[4][2];
#pragma unroll
        for (int nt = 0; nt < 4; nt++) {
            int cw = ((nt * 8 + tg) ^ (8 * tc));
            bf[nt][0] = __float_as_uint(buf[tc * 32 + cw]);
            bf[nt][1] = __float_as_uint(buf[(tc + 4) * 32 + cw]);
        }
        // A fragments + MMAs
#pragma unroll
        for (int mt = 0; mt < 2; mt++) {
            const float* g0 = gs + (k0 + tc) * GSTR + mt * 16;
            const float* g4 = g0 + 4 * GSTR;
            unsigned a0 = __float_as_uint(g0[tg]);
            unsigned a1 = __float_as_uint(g0[tg + 8]);
            unsigned a2 = __float_as_uint(g4[tg]);
            unsigned a3 = __float_as_uint(g4[tg + 8]);
#pragma unroll
            for (int nt = 0; nt < 4; nt++)
                mma_tf32(dacc[mt][nt], a0, a1, a2, a3, bf[nt][0], bf[nt][1]);
        }
    }
    // epilogue: write M fragments
    int q8b = q * 8 + b;
#pragma unroll
    for (int mt = 0; mt < 2; mt++) {
#pragma unroll
        for (int nt = 0; nt < 4; nt++) {
            float* base = g_M + (q8b * 32 + mt * 16 + tg) * 32 + nt * 8 + 2 * tc;
            *(float2*)base = make_float2(dacc[mt][nt][0], dacc[mt][nt][1]);
            *(float2*)(base + 8 * 32) = make_float2(dacc[mt][nt][2], dacc[mt][nt][3]);
        }
    }
    g_zc[q8b * 32 + lane] = zca;
}

// ---------------- Kernel C: Y1 = M@W2r + zc@filt ; y = gelu(Y1 + bias) ------
// 3-stage cp.async ring, one barrier per tile; f32x2 d-pair packed compute.
__global__ __launch_bounds__(256) void kernC(const float* __restrict__ W2,
                                             const float* __restrict__ filt,
                                             const float* __restrict__ bias) {
    __shared__ __align__(16) float W2t[3 * 2048];
    __shared__ __align__(16) float Mt[3 * 512];
    __shared__ float filts[2048];
    __shared__ float zct[16 * 32];
    __shared__ float biass[64];
    int tid = threadIdx.x;
    int rowbase = blockIdx.x * 16;   // rows r = q*8+b ; grid = 128

    for (int l = tid; l < 2048; l += 256) filts[l] = filt[l];
    for (int l = tid; l < 512; l += 256) zct[l] = g_zc[rowbase * 32 + l];
    if (tid < 64) biass[tid] = bias[tid];

    int rg = tid >> 5, dp = tid & 31;   // rows {rg, rg+8}, cols {2dp, 2dp+1}
    unsigned long long A0 = 0ull, A1 = 0ull;

    auto issue = [&](int tt) {
        float* Wd = W2t + (tt % 3) * 2048;
        float* Md = Mt + (tt % 3) * 512;
        int jc0 = tt * 32;
#pragma unroll
        for (int r = 0; r < 2; r++) {
            int ch = tid + r * 256;
            int jcl = ch >> 4, dd4 = (ch & 15) * 4;
            int jcg = jc0 + jcl;
            cpa16(Wd + jcl * 64 + dd4, W2 + (jcg >> 5) * 2048 + (jcg & 31) * 64 + dd4);
        }
        if (tid < 128) {
            int rl = tid >> 3, j4 = (tid & 7) * 4;
            cpa16(Md + rl * 32 + j4, g_M + (rowbase + rl) * 1024 + jc0 + j4);
        }
        cpa_commit();
    };

    issue(0);
    for (int t = 0; t < 32; t++) {
        if (t < 31) { issue(t + 1); cpa_wait1(); }
        else cpa_wait0();
        __syncthreads();
        const float* Wb = W2t + (t % 3) * 2048;
        const float* Mb = Mt + (t % 3) * 512;
#pragma unroll 8
        for (int jcl = 0; jcl < 32; jcl++) {
            float m0 = Mb[rg * 32 + jcl], m1 = Mb[(rg + 8) * 32 + jcl];
            unsigned long long wp = *(const unsigned long long*)(Wb + jcl * 64 + 2 * dp);
            fma2(A0, pk2(m0, m0), wp);
            fma2(A1, pk2(m1, m1), wp);
        }
    }
#pragma unroll 8
    for (int c = 0; c < 32; c++) {
        float m0 = zct[rg * 32 + c], m1 = zct[(rg + 8) * 32 + c];
        unsigned long long wp = *(const unsigned long long*)(filts + c * 64 + 2 * dp);
        fma2(A0, pk2(m0, m0), wp);
        fma2(A1, pk2(m1, m1), wp);
    }
    float2 v0 = up2(A0), v1 = up2(A1);
    int r0 = rowbase + rg, r1 = r0 + 8;
    int q0 = r0 >> 3, b0 = r0 & 7, q1 = r1 >> 3, b1v = r1 & 7;
    float bx = biass[2 * dp], by = biass[2 * dp + 1];
    *(float2*)(g_y + (b0 * QQ + q0) * 64 + 2 * dp) =
        make_float2(gelu_exact(v0.x + bx), gelu_exact(v0.y + by));
    *(float2*)(g_y + (b1v * QQ + q1) * 64 + 2 * dp) =
        make_float2(gelu_exact(v1.x + bx), gelu_exact(v1.y + by));
}

// ---------------- Kernel D: out = gelu(y@Wm1+bm1)@Wm2 + bm2 + y -------------
__global__ __launch_bounds__(512) void kernD(const float* __restrict__ Wm1,
                                             const float* __restrict__ bm1,
                                             const float* __restrict__ Wm2,
                                             const float* __restrict__ bm2,
                                             float* __restrict__ out) {
    __shared__ float yr[8 * 64];
    __shared__ float ts[8 * 256];
    __shared__ __align__(16) float wsm[3 * 2048];
    int tid = threadIdx.x;
    int rb = blockIdx.x * 8;   // rows rbq = b*256+q ; grid = 256
    yr[tid] = g_y[rb * 64 + tid];

    // ---- phase 1: h[l,i] = gelu(bm1[i] + sum_d yr[l,d]*Wm1[d,i]) ----
    int i = tid & 255, lg = tid >> 8;
    float acc[4];
    float bb = bm1[i];
#pragma unroll
    for (int l = 0; l < 4; l++) acc[l] = bb;

    auto issue1 = [&](int tt) {
        cpa16(wsm + (tt % 3) * 2048 + tid * 4, Wm1 + tt * 2048 + tid * 4);
        cpa_commit();
    };
    issue1(0);
    for (int t = 0; t < 8; t++) {
        if (t < 7) { issue1(t + 1); cpa_wait1(); }
        else cpa_wait0();
        __syncthreads();
        const float* wb = wsm + (t % 3) * 2048;
        int d0 = t * 8;
#pragma unroll
        for (int dd = 0; dd < 8; dd++) {
            float wv = wb[dd * 256 + i];
#pragma unroll
            for (int l = 0; l < 4; l++)
                acc[l] = fmaf(yr[(lg * 4 + l) * 64 + d0 + dd], wv, acc[l]);
        }
    }
#pragma unroll
    for (int l = 0; l < 4; l++) ts[(lg * 4 + l) * 256 + i] = gelu_exact(acc[l]);
    __syncthreads();

    // ---- phase 2: out[l,d] = bm2[d] + yr[l,d] + sum_i ts[l,i]*Wm2[i,d] ----
    // f32x2: 256 workers, each row l2 = tid>>5, d-pair dp = tid&31.
    int dp = tid & 31, l2 = tid >> 5;    // valid for tid < 256
    unsigned long long A = 0ull;
    const float* tr = ts + (l2 & 7) * 256;
    auto issue2 = [&](int tt) {
        cpa16(wsm + (tt % 3) * 2048 + tid * 4, Wm2 + tt * 2048 + tid * 4);
        cpa_commit();
    };
    issue2(0);
    for (int t = 0; t < 8; t++) {
        if (t < 7) { issue2(t + 1); cpa_wait1(); }
        else cpa_wait0();
        __syncthreads();
        const float* wb = wsm + (t % 3) * 2048;
        int i0 = t * 32;
        if (tid < 256) {
#pragma unroll 8
            for (int ii = 0; ii < 32; ii++) {
                float tv = tr[i0 + ii];
                unsigned long long wp = *(const unsigned long long*)(wb + ii * 64 + 2 * dp);
                fma2(A, pk2(tv, tv), wp);
            }
        }
    }
    if (tid < 256) {
        float2 r = up2(A);
        float2 o;
        o.x = bm2[2 * dp] + yr[l2 * 64 + 2 * dp] + r.x;
        o.y = bm2[2 * dp + 1] + yr[l2 * 64 + 2 * dp + 1] + r.y;
        *(float2*)(out + (rb + l2) * 64 + 2 * dp) = o;
    }
}

// ---------------- launch ----------------------------------------------------
extern "C" void kernel_launch(void* const* d_in, const int* in_sizes, int n_in,
                              void* d_out, int out_size) {
    const float* x    = (const float*)d_in[0];
    const float* pos  = (const float*)d_in[1];
    const float* qp   = (const float*)d_in[2];
    const float* qmw  = (const float*)d_in[3];
    const float* qmo  = (const float*)d_in[4];
    const float* W_lin = (const float*)d_in[5];
    const float* b_lin = (const float*)d_in[6];
    const float* rff  = (const float*)d_in[7];
    const float* W1   = (const float*)d_in[8];
    const float* b1   = (const float*)d_in[9];
    const float* W2   = (const float*)d_in[10];
    const float* filt = (const float*)d_in[11];
    const float* bias = (const float*)d_in[12];
    const float* Wm1  = (const float*)d_in[13];
    const float* bm1  = (const float*)d_in[14];
    const float* Wm2  = (const float*)d_in[15];
    const float* bm2  = (const float*)d_in[16];
    float* out = (float*)d_out;

    kernA<<<512, 256>>>(x, W_lin, b_lin, qp, out, out_size);
    kernB<<<QQ, 256>>>(pos, qp, qmw, qmo, rff, W1, b1);
    kernC<<<128, 256>>>(W2, filt, bias);
    kernD<<<256, 512>>>(Wm1, bm1, Wm2, bm2, out);
}

// round 8
// speedup vs baseline: 2.5433x; 1.0853x over previous
#include <cuda_runtime.h>
#include <cuda_bf16.h>
#include <math.h>

// Problem constants
#define BB 8
#define NN 2048
#define CC 32
#define DD 64
#define QQ 256
#define KK 205
#define KPAD 208
#define TWO_PI 6.28318530717958647692f

// ---------------- scratch (device globals; no allocations) ----------------
__device__ float g_xl[BB * NN * CC];          // 2 MB   xl[b][n][c]  (tf32-rounded)
__device__ float g_M[QQ * BB * CC * CC];      // 8 MB   M[(q*8+b)][j][c]
__device__ float g_zc[QQ * BB * CC];          // 256 KB zc[(q*8+b)][c]
__device__ float g_y[BB * QQ * DD];           // 512 KB y[(b*256+q)][d]

__device__ __forceinline__ float gelu_exact(float v) {
    return 0.5f * v * (1.0f + erff(v * 0.70710678118654752440f));
}
__device__ __forceinline__ float wrapd(float d) {
    float t = d + 0.5f;
    t -= floorf(t);
    return t - 0.5f;
}

// ---- packed f32x2 helpers (sm_100+) ----
__device__ __forceinline__ unsigned long long pk2(float lo, float hi) {
    unsigned long long r;
    asm("mov.b64 %0, {%1,%2};" : "=l"(r) : "f"(lo), "f"(hi));
    return r;
}
__device__ __forceinline__ void fma2(unsigned long long& d, unsigned long long a, unsigned long long b) {
    asm("fma.rn.f32x2 %0, %1, %2, %0;" : "+l"(d) : "l"(a), "l"(b));
}
__device__ __forceinline__ float2 up2(unsigned long long v) {
    float lo, hi;
    asm("mov.b64 {%0,%1}, %2;" : "=f"(lo), "=f"(hi) : "l"(v));
    return make_float2(lo, hi);
}
__device__ __forceinline__ unsigned cvt_tf32(float f) {
    unsigned u;
    asm("cvt.rna.tf32.f32 %0, %1;" : "=r"(u) : "f"(f));
    return u;
}
// split v into tf32 high + tf32 residual (3xTF32 scheme)
__device__ __forceinline__ void split_tf32(float v, unsigned& h, unsigned& l) {
    h = cvt_tf32(v);
    l = cvt_tf32(v - __uint_as_float(h));
}
// tf32 warp MMA: D(16x8) += A(16x8) * B(8x8)
__device__ __forceinline__ void mma_tf32(float* d, unsigned a0, unsigned a1,
                                         unsigned a2, unsigned a3,
                                         unsigned b0, unsigned b1) {
    asm volatile(
        "mma.sync.aligned.m16n8k8.row.col.f32.tf32.tf32.f32 "
        "{%0,%1,%2,%3}, {%4,%5,%6,%7}, {%8,%9}, {%0,%1,%2,%3};"
        : "+f"(d[0]), "+f"(d[1]), "+f"(d[2]), "+f"(d[3])
        : "r"(a0), "r"(a1), "r"(a2), "r"(a3), "r"(b0), "r"(b1));
}

// ---- cp.async helpers ----
__device__ __forceinline__ void cpa16(float* dst, const float* src) {
    unsigned s = (unsigned)__cvta_generic_to_shared(dst);
    asm volatile("cp.async.cg.shared.global [%0], [%1], 16;" :: "r"(s), "l"(src));
}
__device__ __forceinline__ void cpa_commit() { asm volatile("cp.async.commit_group;" ::: "memory"); }
__device__ __forceinline__ void cpa_wait1() { asm volatile("cp.async.wait_group 1;" ::: "memory"); }
__device__ __forceinline__ void cpa_wait0() { asm volatile("cp.async.wait_group 0;" ::: "memory"); }

// ---------------- Kernel A: xl = tf32(x @ W_lin + b_lin) ; copy query_pos ---
__global__ __launch_bounds__(256) void kernA(const float* __restrict__ x,
                                             const float* __restrict__ W_lin,
                                             const float* __restrict__ b_lin,
                                             const float* __restrict__ qp,
                                             float* __restrict__ out, int out_size) {
    __shared__ float Ws[CC * CC];
    __shared__ float xr[1024];
    __shared__ float bs[CC];
    int tid = threadIdx.x;
    int rowbase = blockIdx.x * 32;
    for (int l = tid; l < CC * CC; l += 256) Ws[l] = W_lin[l];
    if (tid < CC) bs[tid] = b_lin[tid];
    ((float4*)xr)[tid] = ((const float4*)(x + rowbase * CC))[tid];
    __syncthreads();
    int rg = tid >> 5, c = tid & 31;
    float acc[4];
#pragma unroll
    for (int l = 0; l < 4; l++) acc[l] = bs[c];
#pragma unroll
    for (int i = 0; i < CC; i++) {
        float wv = Ws[i * CC + c];
#pragma unroll
        for (int l = 0; l < 4; l++) acc[l] = fmaf(xr[(rg * 4 + l) * CC + i], wv, acc[l]);
    }
#pragma unroll
    for (int l = 0; l < 4; l++)
        g_xl[(rowbase + rg * 4 + l) * CC + c] = __uint_as_float(cvt_tf32(acc[l]));
    if (blockIdx.x == 0) {
        for (int l = tid; l < QQ * 2; l += 256) out[out_size - QQ * 2 + l] = qp[l];
    }
}

// ---------------- Kernel B: per-query topK (radix select) + features + M/zc --
#define GSTR 34
#define SMB_FLOATS 11584
__global__ __launch_bounds__(256, 2) void kernB(const float* __restrict__ pos,
                                                const float* __restrict__ qp,
                                                const float* __restrict__ qmw,
                                                const float* __restrict__ qmo,
                                                const float* __restrict__ rff,
                                                const float* __restrict__ W1,
                                                const float* __restrict__ b1) {
    __shared__ __align__(16) float sm[SMB_FLOATS];
    unsigned* ebits = (unsigned*)sm;
    int* eq = (int*)(sm + 2048);
    float* gs   = sm;
    float* zs   = sm + 7072;
    float* W1s  = sm + 7072;
    float* b1s  = sm + 8096;
    float* qmws = sm + 8128;
    float* qmos = sm + 8160;
    float* rffs = sm + 8192;
    int*   hist = (int*)(sm + 8224);
    unsigned* um = (unsigned*)(sm + 8480);
    float* red  = sm + 8488;
    float* s_sh = sm + 11168;
    int*   ind_sh = (int*)(sm + 11376);

    int q = blockIdx.x, tid = threadIdx.x;
    int lane = tid & 31;
    float qp0 = qp[2 * q], qp1 = qp[2 * q + 1];

    for (int l = tid; l < 1024; l += 256) W1s[l] = W1[l];
    if (tid < 32) {
        b1s[tid] = b1[tid];
        qmws[tid] = qmw[q * 32 + tid];
        qmos[tid] = qmo[q * 32 + tid];
        rffs[tid] = rff[tid];
    }
    if (tid == 0) {
        um[0] = 0; um[1] = 0; um[2] = 0xFFFFFFFFu; um[3] = 0;
        ((int*)um)[4] = KK;
    }
    __syncthreads();

    // ---- phase 1: edist bits + global min ----
    unsigned mymin = 0xFFFFFFFFu;
#pragma unroll
    for (int it = 0; it < 8; it++) {
        int n = tid + it * 256;
        float2 p = ((const float2*)pos)[n];
        float d0 = wrapd(qp0 - p.x);
        float d1 = wrapd(qp1 - p.y);
        float e = d0 * d0 + d1 * d1;
        unsigned eb = __float_as_uint(e);
        ebits[n] = eb;
        mymin = min(mymin, eb);
    }
#pragma unroll
    for (int o = 16; o; o >>= 1) mymin = min(mymin, __shfl_xor_sync(0xffffffffu, mymin, o));
    if (lane == 0) atomicMin(&um[2], mymin);

    // ---- phase 2: 4-pass radix select ----
    for (int pass = 0; pass < 4; pass++) {
        int sh = 24 - 8 * pass;
        if (tid < 256) hist[tid] = 0;
        __syncthreads();
        unsigned pref = um[3];
        unsigned hm = pass ? (0xFFFFFFFFu << (sh + 8)) : 0u;
#pragma unroll
        for (int it = 0; it < 8; it++) {
            unsigned e = ebits[tid + it * 256];
            bool p = ((e & hm) == pref);
            unsigned act = __ballot_sync(0xffffffffu, p);
            if (p) {
                int bin = (e >> sh) & 255;
                unsigned m = __match_any_sync(act, bin);
                if ((__ffs(m) - 1) == lane) atomicAdd(&hist[bin], __popc(m));
            }
        }
        __syncthreads();
        if (tid < 32) {
            int loc[8]; int s0 = 0;
#pragma unroll
            for (int i = 0; i < 8; i++) { loc[i] = hist[tid * 8 + i]; s0 += loc[i]; }
            int inc = s0;
#pragma unroll
            for (int o = 1; o < 32; o <<= 1) {
                int v = __shfl_up_sync(0xffffffffu, inc, o);
                if (tid >= o) inc += v;
            }
            int exc = inc - s0;
            int rk = ((int*)um)[4];
            if (rk > exc && rk <= inc) {
                int rr = rk - exc;
#pragma unroll
                for (int i = 0; i < 8; i++) {
                    if (rr > loc[i]) rr -= loc[i];
                    else { um[3] = pref | ((unsigned)(tid * 8 + i) << sh); ((int*)um)[4] = rr; break; }
                }
            }
        }
        __syncthreads();
    }
    unsigned vsel = um[3];
    int rsel = ((int*)um)[4];

    // ---- phase 3: compaction ----
#pragma unroll
    for (int it = 0; it < 8; it++) {
        int n = tid + it * 256;
        unsigned e = ebits[n];
        if (e < vsel)       { int p = atomicAdd((int*)&um[0], 1); ind_sh[p] = n; }
        else if (e == vsel) { int p = atomicAdd((int*)&um[1], 1); eq[p] = n; }
    }
    __syncthreads();
    {
        int m = (int)um[1], base = (int)um[0];
        for (int t = tid; t < m; t += 256) {
            int my = eq[t], c = 0;
            for (int i = 0; i < m; i++) c += (eq[i] < my);
            if (c < rsel) ind_sh[base + c] = my;
        }
    }
    if (tid >= KK && tid < KPAD) ind_sh[tid] = 0;
    __syncthreads();

    // ---- phase 4: softmax weights ----
    float ed0 = __uint_as_float(um[2]);
    float edK = __uint_as_float(vsel);
    float invden = 1.0f / ((edK - ed0) + 1e-8f);
    float w = 0.0f; int indv = 0;
    if (tid < KK) {
        indv = ind_sh[tid];
        float e = __uint_as_float(ebits[indv]);
        w = __expf(-(e - ed0) * invden);
    }
    float ws = w;
#pragma unroll
    for (int o = 16; o; o >>= 1) ws += __shfl_xor_sync(0xffffffffu, ws, o);
    if (lane == 0) red[tid >> 5] = ws;
    __syncthreads();
    if (tid < 8) {
        float v = red[tid];
        v += __shfl_xor_sync(0x000000ffu, v, 4);
        v += __shfl_xor_sync(0x000000ffu, v, 2);
        v += __shfl_xor_sync(0x000000ffu, v, 1);
        if (tid == 0) red[0] = v;
    }
    __syncthreads();
    float sk = (tid < KK) ? (w / red[0]) : 0.0f;
    if (tid < KPAD) s_sh[tid] = sk;
    __syncthreads();

    // ---- phase 5: per-k RFF features -> h -> gelu -> gs = tf32(g * s) ----
    if (tid < KK) {
        float2 pp = ((const float2*)pos)[indv];
        float d0 = wrapd(qp0 - pp.x);
        float d1 = wrapd(qp1 - pp.y);
        float ft[32];
#pragma unroll
        for (int f = 0; f < 16; f++) {
            float p = TWO_PI * (d0 * rffs[f] + d1 * rffs[16 + f]);
            __sincosf(p, &ft[f], &ft[f + 16]);
        }
        unsigned long long h2[16];
        const unsigned long long* b1p = (const unsigned long long*)b1s;
#pragma unroll
        for (int jp = 0; jp < 16; jp++) h2[jp] = b1p[jp];
#pragma unroll 4
        for (int i = 0; i < 32; i++) {
            unsigned long long fi = pk2(ft[i], ft[i]);
            const unsigned long long* w1p = (const unsigned long long*)(W1s + i * 32);
#pragma unroll
            for (int jp = 0; jp < 16; jp++) fma2(h2[jp], fi, w1p[jp]);
        }
        unsigned long long* grow = (unsigned long long*)(gs + tid * GSTR);
#pragma unroll
        for (int jp = 0; jp < 16; jp++) {
            float2 hv = up2(h2[jp]);
            int j0 = 2 * jp;
            float a0 = gelu_exact(hv.x * qmws[j0] + qmos[j0]) * sk;
            float a1 = gelu_exact(hv.y * qmws[j0 + 1] + qmos[j0 + 1]) * sk;
            unsigned u0 = cvt_tf32(a0), u1 = cvt_tf32(a1);
            grow[jp] = ((unsigned long long)u1 << 32) | u0;
        }
    } else if (tid < KPAD) {
        unsigned long long* grow = (unsigned long long*)(gs + tid * GSTR);
#pragma unroll
        for (int jp = 0; jp < 16; jp++) grow[jp] = 0ull;
    }
    __syncthreads();

    // ---- phase 6: tf32 tensor-core M accumulation, warp-local gather -------
    int b = tid >> 5;
    int tg = lane >> 2, tc = lane & 3;
    float* zw = zs + b * 512;
    int kkl = lane >> 2, c4l = lane & 3;
    int swA = ((c4l ^ (2 * (kkl & 3))) & 7) * 4;
    int swB = (((c4l + 4) ^ (2 * (kkl & 3))) & 7) * 4;

    float dacc[2][4][4];
#pragma unroll
    for (int mt = 0; mt < 2; mt++)
#pragma unroll
        for (int nt = 0; nt < 4; nt++)
#pragma unroll
            for (int r = 0; r < 4; r++) dacc[mt][nt][r] = 0.0f;
    float zca = 0.0f;

    {
        int n = ind_sh[kkl];
        const float* src = g_xl + ((b * NN + n) << 5);
        cpa16(zw + kkl * 32 + swA, src + c4l * 4);
        cpa16(zw + kkl * 32 + swB, src + (c4l + 4) * 4);
        cpa_commit();
    }
    for (int t = 0; t < 26; t++) {
        __syncwarp();
        if (t < 25) {
            int k0n = (t + 1) * 8;
            float* nb = zw + ((t + 1) & 1) * 256;
            int n = ind_sh[k0n + kkl];
            const float* src = g_xl + ((b * NN + n) << 5);
            cpa16(nb + kkl * 32 + swA, src + c4l * 4);
            cpa16(nb + kkl * 32 + swB, src + (c4l + 4) * 4);
            cpa_commit();
            cpa_wait1();
        } else {
            cpa_wait0();
        }
        __syncwarp();
        const float* buf = zw + (t & 1) * 256;
        int k0 = t * 8;
#pragma unroll
        for (int kk = 0; kk < 8; kk++)
            zca = fmaf(s_sh[k0 + kk], buf[kk * 32 + (lane ^ (8 * (kk & 3)))], zca);
        unsigned bf[4][2];
#pragma unroll
        for (int nt = 0; nt < 4; nt++) {
            int cw = ((nt * 8 + tg) ^ (8 * tc));
            bf[nt][0] = __float_as_uint(buf[tc * 32 + cw]);
            bf[nt][1] = __float_as_uint(buf[(tc + 4) * 32 + cw]);
        }
#pragma unroll
        for (int mt = 0; mt < 2; mt++) {
            const float* g0 = gs + (k0 + tc) * GSTR + mt * 16;
            const float* g4 = g0 + 4 * GSTR;
            unsigned a0 = __float_as_uint(g0[tg]);
            unsigned a1 = __float_as_uint(g0[tg + 8]);
            unsigned a2 = __float_as_uint(g4[tg]);
            unsigned a3 = __float_as_uint(g4[tg + 8]);
#pragma unroll
            for (int nt = 0; nt < 4; nt++)
                mma_tf32(dacc[mt][nt], a0, a1, a2, a3, bf[nt][0], bf[nt][1]);
        }
    }
    int q8b = q * 8 + b;
#pragma unroll
    for (int mt = 0; mt < 2; mt++) {
#pragma unroll
        for (int nt = 0; nt < 4; nt++) {
            float* base = g_M + (q8b * 32 + mt * 16 + tg) * 32 + nt * 8 + 2 * tc;
            *(float2*)base = make_float2(dacc[mt][nt][0], dacc[mt][nt][1]);
            *(float2*)(base + 8 * 32) = make_float2(dacc[mt][nt][2], dacc[mt][nt][3]);
        }
    }
    g_zc[q8b * 32 + lane] = zca;
}

// ---------------- Kernel C: Y1 = M@W2r + zc@filt ; y = gelu(Y1 + bias) ------
// 3xTF32 MMA (residual-compensated; ~fp32 accuracy on the tensor pipe).
__global__ __launch_bounds__(256) void kernC(const float* __restrict__ W2,
                                             const float* __restrict__ filt,
                                             const float* __restrict__ bias) {
    __shared__ __align__(16) float W2t[3 * 2304];   // 32 x 72 per slot
    __shared__ __align__(16) float Mt[3 * 576];     // 16 x 36 per slot
    __shared__ float filts[2048];
    __shared__ float zct[16 * 33];
    __shared__ float biass[64];
    int tid = threadIdx.x;
    int lane = tid & 31, w = tid >> 5, tg = lane >> 2, tc = lane & 3;
    int rowbase = blockIdx.x * 16;

    for (int l = tid; l < 2048; l += 256) filts[l] = filt[l];
    for (int l = tid; l < 512; l += 256) zct[(l >> 5) * 33 + (l & 31)] = g_zc[rowbase * 32 + l];
    if (tid < 64) biass[tid] = bias[tid];

    auto issue = [&](int tt) {
        float* Wd = W2t + (tt % 3) * 2304;
        float* Md = Mt + (tt % 3) * 576;
        int jc0 = tt * 32;
#pragma unroll
        for (int r = 0; r < 2; r++) {
            int ch = tid + r * 256;
            int jcl = ch >> 4, dd4 = (ch & 15) * 4;
            int jcg = jc0 + jcl;
            cpa16(Wd + jcl * 72 + dd4, W2 + (jcg >> 5) * 2048 + (jcg & 31) * 64 + dd4);
        }
        if (tid < 128) {
            int rl = tid >> 3, j4 = (tid & 7) * 4;
            cpa16(Md + rl * 36 + j4, g_M + (rowbase + rl) * 1024 + jc0 + j4);
        }
        cpa_commit();
    };

    float dacc[4] = {0.f, 0.f, 0.f, 0.f};
    int nb = w * 8 + tg;

    issue(0);
    for (int t = 0; t < 32; t++) {
        if (t < 31) { issue(t + 1); cpa_wait1(); }
        else cpa_wait0();
        __syncthreads();
        const float* Wb = W2t + (t % 3) * 2304;
        const float* Mb = Mt + (t % 3) * 576;
#pragma unroll
        for (int ks = 0; ks < 4; ks++) {
            int k = ks * 8;
            unsigned a0h, a0l, a1h, a1l, a2h, a2l, a3h, a3l, b0h, b0l, b1h, b1l;
            split_tf32(Mb[tg * 36 + k + tc],           a0h, a0l);
            split_tf32(Mb[(tg + 8) * 36 + k + tc],     a1h, a1l);
            split_tf32(Mb[tg * 36 + k + tc + 4],       a2h, a2l);
            split_tf32(Mb[(tg + 8) * 36 + k + tc + 4], a3h, a3l);
            split_tf32(Wb[(k + tc) * 72 + nb],         b0h, b0l);
            split_tf32(Wb[(k + tc + 4) * 72 + nb],     b1h, b1l);
            mma_tf32(dacc, a0h, a1h, a2h, a3h, b0l, b1l);
            mma_tf32(dacc, a0l, a1l, a2l, a3l, b0h, b1h);
            mma_tf32(dacc, a0h, a1h, a2h, a3h, b0h, b1h);
        }
    }
    // epilogue: + zc@filt + bias, gelu, store (fp32 f32x2)
    int c0 = w * 8 + 2 * tc;
    unsigned long long F0 = 0ull, F1 = 0ull;
#pragma unroll 8
    for (int c = 0; c < 32; c++) {
        unsigned long long wp = *(const unsigned long long*)(filts + c * 64 + c0);
        float z0 = zct[tg * 33 + c], z1 = zct[(tg + 8) * 33 + c];
        fma2(F0, pk2(z0, z0), wp);
        fma2(F1, pk2(z1, z1), wp);
    }
    float2 f0 = up2(F0), f1 = up2(F1);
    int r0 = rowbase + tg, r1 = r0 + 8;
    int q0 = r0 >> 3, b0r = r0 & 7, q1 = r1 >> 3, b1r = r1 & 7;
    float bx = biass[c0], by = biass[c0 + 1];
    *(float2*)(g_y + (b0r * QQ + q0) * 64 + c0) =
        make_float2(gelu_exact(dacc[0] + f0.x + bx), gelu_exact(dacc[1] + f0.y + by));
    *(float2*)(g_y + (b1r * QQ + q1) * 64 + c0) =
        make_float2(gelu_exact(dacc[2] + f1.x + bx), gelu_exact(dacc[3] + f1.y + by));
}

// ---------------- Kernel D: out = gelu(y@Wm1+bm1)@Wm2 + bm2 + y -------------
// 3xTF32 MMA for both GEMMs; 16 rows/block, grid=128.
__global__ __launch_bounds__(256) void kernD(const float* __restrict__ Wm1,
                                             const float* __restrict__ bm1,
                                             const float* __restrict__ Wm2,
                                             const float* __restrict__ bm2,
                                             float* __restrict__ out) {
    __shared__ __align__(16) float yr[16 * 68];
    __shared__ __align__(16) float ts[16 * 260];
    __shared__ __align__(16) float ring[6912];
    int tid = threadIdx.x;
    int lane = tid & 31, w = tid >> 5, tg = lane >> 2, tc = lane & 3;
    int rb = blockIdx.x * 16;

    {
        int r = tid >> 4, d4 = (tid & 15) * 4;
        *(float4*)(yr + r * 68 + d4) = *(const float4*)(g_y + (rb + r) * 64 + d4);
    }

    // ---- phase 1: ts = gelu(yr @ Wm1 + bm1), tiles of 8 k-rows ----
    auto issue1 = [&](int tt) {
        float* dst = ring + (tt % 3) * 2112;
#pragma unroll
        for (int r = 0; r < 2; r++) {
            int ch = tid + r * 256;
            int kk = ch >> 6, n4 = (ch & 63) * 4;
            cpa16(dst + kk * 264 + n4, Wm1 + (tt * 8 + kk) * 256 + n4);
        }
        cpa_commit();
    };
    float d1acc[4][4];
#pragma unroll
    for (int nt = 0; nt < 4; nt++)
#pragma unroll
        for (int r = 0; r < 4; r++) d1acc[nt][r] = 0.0f;

    issue1(0);
    for (int t = 0; t < 8; t++) {
        if (t < 7) { issue1(t + 1); cpa_wait1(); }
        else cpa_wait0();
        __syncthreads();
        const float* wb = ring + (t % 3) * 2112;
        int k = t * 8;
        unsigned a0h, a0l, a1h, a1l, a2h, a2l, a3h, a3l;
        split_tf32(yr[tg * 68 + k + tc],           a0h, a0l);
        split_tf32(yr[(tg + 8) * 68 + k + tc],     a1h, a1l);
        split_tf32(yr[tg * 68 + k + tc + 4],       a2h, a2l);
        split_tf32(yr[(tg + 8) * 68 + k + tc + 4], a3h, a3l);
#pragma unroll
        for (int nt = 0; nt < 4; nt++) {
            int n = (w * 4 + nt) * 8 + tg;
            unsigned b0h, b0l, b1h, b1l;
            split_tf32(wb[tc * 264 + n],       b0h, b0l);
            split_tf32(wb[(tc + 4) * 264 + n], b1h, b1l);
            mma_tf32(d1acc[nt], a0h, a1h, a2h, a3h, b0l, b1l);
            mma_tf32(d1acc[nt], a0l, a1l, a2l, a3l, b0h, b1h);
            mma_tf32(d1acc[nt], a0h, a1h, a2h, a3h, b0h, b1h);
        }
    }
#pragma unroll
    for (int nt = 0; nt < 4; nt++) {
        int i0 = (w * 4 + nt) * 8 + 2 * tc;
        ts[tg * 260 + i0]           = gelu_exact(d1acc[nt][0] + bm1[i0]);
        ts[tg * 260 + i0 + 1]       = gelu_exact(d1acc[nt][1] + bm1[i0 + 1]);
        ts[(tg + 8) * 260 + i0]     = gelu_exact(d1acc[nt][2] + bm1[i0]);
        ts[(tg + 8) * 260 + i0 + 1] = gelu_exact(d1acc[nt][3] + bm1[i0 + 1]);
    }
    __syncthreads();

    // ---- phase 2: out = ts @ Wm2 + bm2 + yr, tiles of 32 k-rows ----
    auto issue2 = [&](int tt) {
        float* dst = ring + (tt % 3) * 2304;
#pragma unroll
        for (int r = 0; r < 2; r++) {
            int ch = tid + r * 256;
            int kk = ch >> 4, n4 = (ch & 15) * 4;
            cpa16(dst + kk * 72 + n4, Wm2 + (tt * 32 + kk) * 64 + n4);
        }
        cpa_commit();
    };
    float d2acc[4] = {0.f, 0.f, 0.f, 0.f};
    int nb = w * 8 + tg;

    issue2(0);
    for (int t = 0; t < 8; t++) {
        if (t < 7) { issue2(t + 1); cpa_wait1(); }
        else cpa_wait0();
        __syncthreads();
        const float* wb = ring + (t % 3) * 2304;
#pragma unroll
        for (int ks = 0; ks < 4; ks++) {
            int kg = t * 32 + ks * 8;
            unsigned a0h, a0l, a1h, a1l, a2h, a2l, a3h, a3l, b0h, b0l, b1h, b1l;
            split_tf32(ts[tg * 260 + kg + tc],           a0h, a0l);
            split_tf32(ts[(tg + 8) * 260 + kg + tc],     a1h, a1l);
            split_tf32(ts[tg * 260 + kg + tc + 4],       a2h, a2l);
            split_tf32(ts[(tg + 8) * 260 + kg + tc + 4], a3h, a3l);
            split_tf32(wb[(ks * 8 + tc) * 72 + nb],      b0h, b0l);
            split_tf32(wb[(ks * 8 + tc + 4) * 72 + nb],  b1h, b1l);
            mma_tf32(d2acc, a0h, a1h, a2h, a3h, b0l, b1l);
            mma_tf32(d2acc, a0l, a1l, a2l, a3l, b0h, b1h);
            mma_tf32(d2acc, a0h, a1h, a2h, a3h, b0h, b1h);
        }
    }
    int c0 = w * 8 + 2 * tc;
    float bx = bm2[c0], by = bm2[c0 + 1];
    *(float2*)(out + (rb + tg) * 64 + c0) =
        make_float2(d2acc[0] + bx + yr[tg * 68 + c0],
                    d2acc[1] + by + yr[tg * 68 + c0 + 1]);
    *(float2*)(out + (rb + tg + 8) * 64 + c0) =
        make_float2(d2acc[2] + bx + yr[(tg + 8) * 68 + c0],
                    d2acc[3] + by + yr[(tg + 8) * 68 + c0 + 1]);
}

// ---------------- launch ----------------------------------------------------
extern "C" void kernel_launch(void* const* d_in, const int* in_sizes, int n_in,
                              void* d_out, int out_size) {
    const float* x    = (const float*)d_in[0];
    const float* pos  = (const float*)d_in[1];
    const float* qp   = (const float*)d_in[2];
    const float* qmw  = (const float*)d_in[3];
    const float* qmo  = (const float*)d_in[4];
    const float* W_lin = (const float*)d_in[5];
    const float* b_lin = (const float*)d_in[6];
    const float* rff  = (const float*)d_in[7];
    const float* W1   = (const float*)d_in[8];
    const float* b1   = (const float*)d_in[9];
    const float* W2   = (const float*)d_in[10];
    const float* filt = (const float*)d_in[11];
    const float* bias = (const float*)d_in[12];
    const float* Wm1  = (const float*)d_in[13];
    const float* bm1  = (const float*)d_in[14];
    const float* Wm2  = (const float*)d_in[15];
    const float* bm2  = (const float*)d_in[16];
    float* out = (float*)d_out;

    kernA<<<512, 256>>>(x, W_lin, b_lin, qp, out, out_size);
    kernB<<<QQ, 256>>>(pos, qp, qmw, qmo, rff, W1, b1);
    kernC<<<128, 256>>>(W2, filt, bias);
    kernD<<<128, 256>>>(Wm1, bm1, Wm2, bm2, out);
}

// round 9
// speedup vs baseline: 2.6157x; 1.0285x over previous
#include <cuda_runtime.h>
#include <cuda_bf16.h>
#include <math.h>

// Problem constants
#define BB 8
#define NN 2048
#define CC 32
#define DD 64
#define QQ 256
#define KK 205
#define KPAD 208
#define TWO_PI 6.28318530717958647692f

// ---------------- scratch (device globals; no allocations) ----------------
__device__ float g_xl[BB * NN * CC];          // xl[b][n][c]  (tf32-rounded)
__device__ float g_M[QQ * BB * CC * CC];      // M[(q*8+b)][j][c]
__device__ float g_zc[QQ * BB * CC];          // zc[(q*8+b)][c]
__device__ float g_y[BB * QQ * DD];           // y[(b*256+q)][d]

__device__ __forceinline__ float gelu_exact(float v) {
    return 0.5f * v * (1.0f + erff(v * 0.70710678118654752440f));
}
__device__ __forceinline__ float wrapd(float d) {
    float t = d + 0.5f;
    t -= floorf(t);
    return t - 0.5f;
}

// ---- packed f32x2 helpers ----
__device__ __forceinline__ unsigned long long pk2(float lo, float hi) {
    unsigned long long r;
    asm("mov.b64 %0, {%1,%2};" : "=l"(r) : "f"(lo), "f"(hi));
    return r;
}
__device__ __forceinline__ void fma2(unsigned long long& d, unsigned long long a, unsigned long long b) {
    asm("fma.rn.f32x2 %0, %1, %2, %0;" : "+l"(d) : "l"(a), "l"(b));
}
__device__ __forceinline__ float2 up2(unsigned long long v) {
    float lo, hi;
    asm("mov.b64 {%0,%1}, %2;" : "=f"(lo), "=f"(hi) : "l"(v));
    return make_float2(lo, hi);
}
__device__ __forceinline__ unsigned cvt_tf32(float f) {
    unsigned u;
    asm("cvt.rna.tf32.f32 %0, %1;" : "=r"(u) : "f"(f));
    return u;
}
__device__ __forceinline__ void split_tf32(float v, unsigned& h, unsigned& l) {
    h = cvt_tf32(v);
    l = cvt_tf32(v - __uint_as_float(h));
}
__device__ __forceinline__ void mma_tf32(float* d, unsigned a0, unsigned a1,
                                         unsigned a2, unsigned a3,
                                         unsigned b0, unsigned b1) {
    asm volatile(
        "mma.sync.aligned.m16n8k8.row.col.f32.tf32.tf32.f32 "
        "{%0,%1,%2,%3}, {%4,%5,%6,%7}, {%8,%9}, {%0,%1,%2,%3};"
        : "+f"(d[0]), "+f"(d[1]), "+f"(d[2]), "+f"(d[3])
        : "r"(a0), "r"(a1), "r"(a2), "r"(a3), "r"(b0), "r"(b1));
}

// ---- cp.async helpers ----
__device__ __forceinline__ void cpa16(float* dst, const float* src) {
    unsigned s = (unsigned)__cvta_generic_to_shared(dst);
    asm volatile("cp.async.cg.shared.global [%0], [%1], 16;" :: "r"(s), "l"(src));
}
__device__ __forceinline__ void cpa_commit() { asm volatile("cp.async.commit_group;" ::: "memory"); }
__device__ __forceinline__ void cpa_wait2() { asm volatile("cp.async.wait_group 2;" ::: "memory"); }
__device__ __forceinline__ void cpa_wait1() { asm volatile("cp.async.wait_group 1;" ::: "memory"); }
__device__ __forceinline__ void cpa_wait0() { asm volatile("cp.async.wait_group 0;" ::: "memory"); }

// ---------------- Kernel A: xl = tf32(x @ W_lin + b_lin) ; copy query_pos ---
__global__ __launch_bounds__(256) void kernA(const float* __restrict__ x,
                                             const float* __restrict__ W_lin,
                                             const float* __restrict__ b_lin,
                                             const float* __restrict__ qp,
                                             float* __restrict__ out, int out_size) {
    __shared__ float Ws[CC * CC];
    __shared__ float xr[1024];
    __shared__ float bs[CC];
    int tid = threadIdx.x;
    int rowbase = blockIdx.x * 32;
    for (int l = tid; l < CC * CC; l += 256) Ws[l] = W_lin[l];
    if (tid < CC) bs[tid] = b_lin[tid];
    ((float4*)xr)[tid] = ((const float4*)(x + rowbase * CC))[tid];
    __syncthreads();
    int rg = tid >> 5, c = tid & 31;
    float acc[4];
#pragma unroll
    for (int l = 0; l < 4; l++) acc[l] = bs[c];
#pragma unroll
    for (int i = 0; i < CC; i++) {
        float wv = Ws[i * CC + c];
#pragma unroll
        for (int l = 0; l < 4; l++) acc[l] = fmaf(xr[(rg * 4 + l) * CC + i], wv, acc[l]);
    }
#pragma unroll
    for (int l = 0; l < 4; l++)
        g_xl[(rowbase + rg * 4 + l) * CC + c] = __uint_as_float(cvt_tf32(acc[l]));
    if (blockIdx.x == 0) {
        for (int l = tid; l < QQ * 2; l += 256) out[out_size - QQ * 2 + l] = qp[l];
    }
}

// ---------------- Kernel B: per-query topK (radix select) + features + M/zc --
#define GSTR 34
#define SMB_FLOATS 11584
__global__ __launch_bounds__(256, 2) void kernB(const float* __restrict__ pos,
                                                const float* __restrict__ qp,
                                                const float* __restrict__ qmw,
                                                const float* __restrict__ qmo,
                                                const float* __restrict__ rff,
                                                const float* __restrict__ W1,
                                                const float* __restrict__ b1) {
    __shared__ __align__(16) float sm[SMB_FLOATS];
    unsigned* ebits = (unsigned*)sm;
    int* eq = (int*)(sm + 2048);
    float* gs   = sm;
    float* zs   = sm + 7072;
    float* W1s  = sm + 7072;
    float* b1s  = sm + 8096;
    float* qmws = sm + 8128;
    float* qmos = sm + 8160;
    float* rffs = sm + 8192;
    int*   hist = (int*)(sm + 8224);
    unsigned* um = (unsigned*)(sm + 8480);
    float* red  = sm + 8488;
    float* s_sh = sm + 11168;
    int*   ind_sh = (int*)(sm + 11376);

    int q = blockIdx.x, tid = threadIdx.x;
    int lane = tid & 31;
    float qp0 = qp[2 * q], qp1 = qp[2 * q + 1];

    for (int l = tid; l < 1024; l += 256) W1s[l] = W1[l];
    if (tid < 32) {
        b1s[tid] = b1[tid];
        qmws[tid] = qmw[q * 32 + tid];
        qmos[tid] = qmo[q * 32 + tid];
        rffs[tid] = rff[tid];
    }
    if (tid == 0) {
        um[0] = 0; um[1] = 0; um[2] = 0xFFFFFFFFu; um[3] = 0;
        ((int*)um)[4] = KK;
    }
    __syncthreads();

    // ---- phase 1: edist bits + global min ----
    unsigned mymin = 0xFFFFFFFFu;
#pragma unroll
    for (int it = 0; it < 8; it++) {
        int n = tid + it * 256;
        float2 p = ((const float2*)pos)[n];
        float d0 = wrapd(qp0 - p.x);
        float d1 = wrapd(qp1 - p.y);
        float e = d0 * d0 + d1 * d1;
        unsigned eb = __float_as_uint(e);
        ebits[n] = eb;
        mymin = min(mymin, eb);
    }
#pragma unroll
    for (int o = 16; o; o >>= 1) mymin = min(mymin, __shfl_xor_sync(0xffffffffu, mymin, o));
    if (lane == 0) atomicMin(&um[2], mymin);

    // ---- phase 2: 4-pass radix select ----
    for (int pass = 0; pass < 4; pass++) {
        int sh = 24 - 8 * pass;
        if (tid < 256) hist[tid] = 0;
        __syncthreads();
        unsigned pref = um[3];
        unsigned hm = pass ? (0xFFFFFFFFu << (sh + 8)) : 0u;
#pragma unroll
        for (int it = 0; it < 8; it++) {
            unsigned e = ebits[tid + it * 256];
            bool p = ((e & hm) == pref);
            unsigned act = __ballot_sync(0xffffffffu, p);
            if (p) {
                int bin = (e >> sh) & 255;
                unsigned m = __match_any_sync(act, bin);
                if ((__ffs(m) - 1) == lane) atomicAdd(&hist[bin], __popc(m));
            }
        }
        __syncthreads();
        if (tid < 32) {
            int loc[8]; int s0 = 0;
#pragma unroll
            for (int i = 0; i < 8; i++) { loc[i] = hist[tid * 8 + i]; s0 += loc[i]; }
            int inc = s0;
#pragma unroll
            for (int o = 1; o < 32; o <<= 1) {
                int v = __shfl_up_sync(0xffffffffu, inc, o);
                if (tid >= o) inc += v;
            }
            int exc = inc - s0;
            int rk = ((int*)um)[4];
            if (rk > exc && rk <= inc) {
                int rr = rk - exc;
#pragma unroll
                for (int i = 0; i < 8; i++) {
                    if (rr > loc[i]) rr -= loc[i];
                    else { um[3] = pref | ((unsigned)(tid * 8 + i) << sh); ((int*)um)[4] = rr; break; }
                }
            }
        }
        __syncthreads();
    }
    unsigned vsel = um[3];
    int rsel = ((int*)um)[4];

    // ---- phase 3: compaction ----
#pragma unroll
    for (int it = 0; it < 8; it++) {
        int n = tid + it * 256;
        unsigned e = ebits[n];
        if (e < vsel)       { int p = atomicAdd((int*)&um[0], 1); ind_sh[p] = n; }
        else if (e == vsel) { int p = atomicAdd((int*)&um[1], 1); eq[p] = n; }
    }
    __syncthreads();
    {
        int m = (int)um[1], base = (int)um[0];
        for (int t = tid; t < m; t += 256) {
            int my = eq[t], c = 0;
            for (int i = 0; i < m; i++) c += (eq[i] < my);
            if (c < rsel) ind_sh[base + c] = my;
        }
    }
    if (tid >= KK && tid < KPAD) ind_sh[tid] = 0;
    __syncthreads();

    // ---- phase 4: softmax weights ----
    float ed0 = __uint_as_float(um[2]);
    float edK = __uint_as_float(vsel);
    float invden = 1.0f / ((edK - ed0) + 1e-8f);
    float w = 0.0f; int indv = 0;
    if (tid < KK) {
        indv = ind_sh[tid];
        float e = __uint_as_float(ebits[indv]);
        w = __expf(-(e - ed0) * invden);
    }
    float ws = w;
#pragma unroll
    for (int o = 16; o; o >>= 1) ws += __shfl_xor_sync(0xffffffffu, ws, o);
    if (lane == 0) red[tid >> 5] = ws;
    __syncthreads();
    if (tid < 8) {
        float v = red[tid];
        v += __shfl_xor_sync(0x000000ffu, v, 4);
        v += __shfl_xor_sync(0x000000ffu, v, 2);
        v += __shfl_xor_sync(0x000000ffu, v, 1);
        if (tid == 0) red[0] = v;
    }
    __syncthreads();
    float sk = (tid < KK) ? (w / red[0]) : 0.0f;
    if (tid < KPAD) s_sh[tid] = sk;
    __syncthreads();

    // ---- phase 5: per-k RFF features -> h -> gelu -> gs = tf32(g * s) ----
    if (tid < KK) {
        float2 pp = ((const float2*)pos)[indv];
        float d0 = wrapd(qp0 - pp.x);
        float d1 = wrapd(qp1 - pp.y);
        float ft[32];
#pragma unroll
        for (int f = 0; f < 16; f++) {
            float p = TWO_PI * (d0 * rffs[f] + d1 * rffs[16 + f]);
            __sincosf(p, &ft[f], &ft[f + 16]);
        }
        unsigned long long h2[16];
        const unsigned long long* b1p = (const unsigned long long*)b1s;
#pragma unroll
        for (int jp = 0; jp < 16; jp++) h2[jp] = b1p[jp];
#pragma unroll 4
        for (int i = 0; i < 32; i++) {
            unsigned long long fi = pk2(ft[i], ft[i]);
            const unsigned long long* w1p = (const unsigned long long*)(W1s + i * 32);
#pragma unroll
            for (int jp = 0; jp < 16; jp++) fma2(h2[jp], fi, w1p[jp]);
        }
        unsigned long long* grow = (unsigned long long*)(gs + tid * GSTR);
#pragma unroll
        for (int jp = 0; jp < 16; jp++) {
            float2 hv = up2(h2[jp]);
            int j0 = 2 * jp;
            float a0 = gelu_exact(hv.x * qmws[j0] + qmos[j0]) * sk;
            float a1 = gelu_exact(hv.y * qmws[j0 + 1] + qmos[j0 + 1]) * sk;
            unsigned u0 = cvt_tf32(a0), u1 = cvt_tf32(a1);
            grow[jp] = ((unsigned long long)u1 << 32) | u0;
        }
    } else if (tid < KPAD) {
        unsigned long long* grow = (unsigned long long*)(gs + tid * GSTR);
#pragma unroll
        for (int jp = 0; jp < 16; jp++) grow[jp] = 0ull;
    }
    __syncthreads();

    // ---- phase 6: tf32 tensor-core M accumulation, warp-local gather -------
    int b = tid >> 5;
    int tg = lane >> 2, tc = lane & 3;
    float* zw = zs + b * 512;
    int kkl = lane >> 2, c4l = lane & 3;
    int swA = ((c4l ^ (2 * (kkl & 3))) & 7) * 4;
    int swB = (((c4l + 4) ^ (2 * (kkl & 3))) & 7) * 4;

    float dacc[2][4][4];
#pragma unroll
    for (int mt = 0; mt < 2; mt++)
#pragma unroll
        for (int nt = 0; nt < 4; nt++)
#pragma unroll
            for (int r = 0; r < 4; r++) dacc[mt][nt][r] = 0.0f;
    float zca = 0.0f;

    {
        int n = ind_sh[kkl];
        const float* src = g_xl + ((b * NN + n) << 5);
        cpa16(zw + kkl * 32 + swA, src + c4l * 4);
        cpa16(zw + kkl * 32 + swB, src + (c4l + 4) * 4);
        cpa_commit();
    }
    for (int t = 0; t < 26; t++) {
        __syncwarp();
        if (t < 25) {
            int k0n = (t + 1) * 8;
            float* nb = zw + ((t + 1) & 1) * 256;
            int n = ind_sh[k0n + kkl];
            const float* src = g_xl + ((b * NN + n) << 5);
            cpa16(nb + kkl * 32 + swA, src + c4l * 4);
            cpa16(nb + kkl * 32 + swB, src + (c4l + 4) * 4);
            cpa_commit();
            cpa_wait1();
        } else {
            cpa_wait0();
        }
        __syncwarp();
        const float* buf = zw + (t & 1) * 256;
        int k0 = t * 8;
#pragma unroll
        for (int kk = 0; kk < 8; kk++)
            zca = fmaf(s_sh[k0 + kk], buf[kk * 32 + (lane ^ (8 * (kk & 3)))], zca);
        unsigned bf[4][2];
#pragma unroll
        for (int nt = 0; nt < 4; nt++) {
            int cw = ((nt * 8 + tg) ^ (8 * tc));
            bf[nt][0] = __float_as_uint(buf[tc * 32 + cw]);
            bf[nt][1] = __float_as_uint(buf[(tc + 4) * 32 + cw]);
        }
#pragma unroll
        for (int mt = 0; mt < 2; mt++) {
            const float* g0 = gs + (k0 + tc) * GSTR + mt * 16;
            const float* g4 = g0 + 4 * GSTR;
            unsigned a0 = __float_as_uint(g0[tg]);
            unsigned a1 = __float_as_uint(g0[tg + 8]);
            unsigned a2 = __float_as_uint(g4[tg]);
            unsigned a3 = __float_as_uint(g4[tg + 8]);
#pragma unroll
            for (int nt = 0; nt < 4; nt++)
                mma_tf32(dacc[mt][nt], a0, a1, a2, a3, bf[nt][0], bf[nt][1]);
        }
    }
    int q8b = q * 8 + b;
#pragma unroll
    for (int mt = 0; mt < 2; mt++) {
#pragma unroll
        for (int nt = 0; nt < 4; nt++) {
            float* base = g_M + (q8b * 32 + mt * 16 + tg) * 32 + nt * 8 + 2 * tc;
            *(float2*)base = make_float2(dacc[mt][nt][0], dacc[mt][nt][1]);
            *(float2*)(base + 8 * 32) = make_float2(dacc[mt][nt][2], dacc[mt][nt][3]);
        }
    }
    g_zc[q8b * 32 + lane] = zca;
}

// ---------------- Kernel C: 3xTF32, M-tile resident + warp-local W2 stream --
// dyn smem (floats): Mt[16][1028]@0 (16448) | wslots 8w x 2 x 256 @16448 (4096)
//                    | filts@20544 (2048) | zct@22592 (528) | bias@23120 (64)
#define KC_SMEM_FLOATS 23184
__global__ __launch_bounds__(256) void kernC(const float* __restrict__ W2,
                                             const float* __restrict__ filt,
                                             const float* __restrict__ bias) {
    extern __shared__ float dsm[];
    float* Mt    = dsm;                 // stride 1028 (conflict-free A frags)
    float* wsl   = dsm + 16448;         // per-warp double buffer [32][8]
    float* filts = dsm + 20544;
    float* zct   = dsm + 22592;         // stride 33
    float* biass = dsm + 23120;
    int tid = threadIdx.x;
    int lane = tid & 31, w = tid >> 5, tg = lane >> 2, tc = lane & 3;
    int rowbase = blockIdx.x * 16;
    float* myslot = wsl + w * 512;      // 2 slots x 256 floats

    // issue M tile (16 rows x 1024) -> Mt, stride 1028
    {
#pragma unroll
        for (int i = 0; i < 16; i++) {
            int ch = tid + i * 256;
            int row = ch >> 8, c4 = (ch & 255) * 4;
            cpa16(Mt + row * 1028 + c4, g_M + (rowbase + row) * 1024 + c4);
        }
        cpa_commit();   // group: M
    }
    // warp-local W2 tile issuer: tile tt -> slot tt&1. rows 32, cols [w*8,w*8+8)
    auto issueW = [&](int tt) {
#pragma unroll
        for (int r = 0; r < 2; r++) {
            int ch = lane + r * 32;                 // 64 chunks of 16B
            int row = ch >> 1, half = ch & 1;
            int jcg = tt * 32 + row;
            cpa16(myslot + (tt & 1) * 256 + row * 8 + half * 4,
                  W2 + (jcg >> 5) * 2048 + (jcg & 31) * 64 + w * 8 + half * 4);
        }
        cpa_commit();
    };
    issueW(0);
    issueW(1);

    for (int l = tid; l < 2048; l += 256) filts[l] = filt[l];
    for (int l = tid; l < 512; l += 256) zct[(l >> 5) * 33 + (l & 31)] = g_zc[rowbase * 32 + l];
    if (tid < 64) biass[tid] = bias[tid];

    cpa_wait2();        // M group done
    __syncthreads();    // Mt + filts/zct visible to all warps

    float dacc[4] = {0.f, 0.f, 0.f, 0.f};
    for (int t = 0; t < 32; t++) {
        if (t < 31) cpa_wait1(); else cpa_wait0();
        __syncwarp();
        const float* Wb = myslot + (t & 1) * 256;
#pragma unroll
        for (int ks = 0; ks < 4; ks++) {
            int k = t * 32 + ks * 8;
            unsigned a0h, a0l, a1h, a1l, a2h, a2l, a3h, a3l, b0h, b0l, b1h, b1l;
            split_tf32(Mt[tg * 1028 + k + tc],           a0h, a0l);
            split_tf32(Mt[(tg + 8) * 1028 + k + tc],     a1h, a1l);
            split_tf32(Mt[tg * 1028 + k + tc + 4],       a2h, a2l);
            split_tf32(Mt[(tg + 8) * 1028 + k + tc + 4], a3h, a3l);
            split_tf32(Wb[(ks * 8 + tc) * 8 + tg],       b0h, b0l);
            split_tf32(Wb[(ks * 8 + tc + 4) * 8 + tg],   b1h, b1l);
            mma_tf32(dacc, a0h, a1h, a2h, a3h, b0l, b1l);
            mma_tf32(dacc, a0l, a1l, a2l, a3l, b0h, b1h);
            mma_tf32(dacc, a0h, a1h, a2h, a3h, b0h, b1h);
        }
        __syncwarp();                       // all lanes done reading slot t&1
        if (t <= 29) issueW(t + 2);         // overwrite slot t&1
    }
    // epilogue: + zc@filt + bias, gelu, store
    int c0 = w * 8 + 2 * tc;
    unsigned long long F0 = 0ull, F1 = 0ull;
#pragma unroll 8
    for (int c = 0; c < 32; c++) {
        unsigned long long wp = *(const unsigned long long*)(filts + c * 64 + c0);
        float z0 = zct[tg * 33 + c], z1 = zct[(tg + 8) * 33 + c];
        fma2(F0, pk2(z0, z0), wp);
        fma2(F1, pk2(z1, z1), wp);
    }
    float2 f0 = up2(F0), f1 = up2(F1);
    int r0 = rowbase + tg, r1 = r0 + 8;
    int q0 = r0 >> 3, b0r = r0 & 7, q1 = r1 >> 3, b1r = r1 & 7;
    float bx = biass[c0], by = biass[c0 + 1];
    *(float2*)(g_y + (b0r * QQ + q0) * 64 + c0) =
        make_float2(gelu_exact(dacc[0] + f0.x + bx), gelu_exact(dacc[1] + f0.y + by));
    *(float2*)(g_y + (b1r * QQ + q1) * 64 + c0) =
        make_float2(gelu_exact(dacc[2] + f1.x + bx), gelu_exact(dacc[3] + f1.y + by));
}

// ---------------- Kernel D: 3xTF32, warp-resident weight slices -------------
// dyn smem (floats): yr[16][68]@0 (1088) | ts[16][260]@1088 (4160)
//                    | w1 8w x [64][40] @5248 (20480) | w2 8w x [256][8] @25728 (16384)
#define KD_SMEM_FLOATS 42112
__global__ __launch_bounds__(256) void kernD(const float* __restrict__ Wm1,
                                             const float* __restrict__ bm1,
                                             const float* __restrict__ Wm2,
                                             const float* __restrict__ bm2,
                                             float* __restrict__ out) {
    extern __shared__ float dsm[];
    float* yr  = dsm;                  // stride 68 (conflict-free A frags)
    float* ts  = dsm + 1088;           // stride 260
    float* w1s = dsm + 5248;           // per-warp [64][40] (conflict-free B frags)
    float* w2s = dsm + 25728;          // per-warp [256][8] (conflict-free B frags)
    int tid = threadIdx.x;
    int lane = tid & 31, w = tid >> 5, tg = lane >> 2, tc = lane & 3;
    int rb = blockIdx.x * 16;
    float* myw1 = w1s + w * 2560;
    float* myw2 = w2s + w * 2048;

    {   // load 16 rows of y into padded smem
        int r = tid >> 4, d4 = (tid & 15) * 4;
        *(float4*)(yr + r * 68 + d4) = *(const float4*)(g_y + (rb + r) * 64 + d4);
    }
    // issue whole Wm1 warp slice: rows 0..63, cols [w*32, w*32+32)
#pragma unroll
    for (int i = 0; i < 16; i++) {
        int ch = lane + i * 32;                  // 512 chunks
        int row = ch >> 3, c4 = (ch & 7) * 4;
        cpa16(myw1 + row * 40 + c4, Wm1 + row * 256 + w * 32 + c4);
    }
    cpa_commit();   // group w1
    // issue whole Wm2 warp slice: rows 0..255, cols [w*8, w*8+8)
#pragma unroll
    for (int i = 0; i < 16; i++) {
        int ch = lane + i * 32;                  // 512 chunks
        int row = ch >> 1, half = ch & 1;
        cpa16(myw2 + row * 8 + half * 4, Wm2 + row * 64 + w * 8 + half * 4);
    }
    cpa_commit();   // group w2

    cpa_wait1();        // w1 slice resident
    __syncthreads();    // yr visible

    // ---- phase 1: ts = gelu(yr @ Wm1 + bm1) -- no syncs, all data resident --
    float d1acc[4][4];
#pragma unroll
    for (int nt = 0; nt < 4; nt++)
#pragma unroll
        for (int r = 0; r < 4; r++) d1acc[nt][r] = 0.0f;
#pragma unroll
    for (int t = 0; t < 8; t++) {
        int k = t * 8;
        unsigned a0h, a0l, a1h, a1l, a2h, a2l, a3h, a3l;
        split_tf32(yr[tg * 68 + k + tc],           a0h, a0l);
        split_tf32(yr[(tg + 8) * 68 + k + tc],     a1h, a1l);
        split_tf32(yr[tg * 68 + k + tc + 4],       a2h, a2l);
        split_tf32(yr[(tg + 8) * 68 + k + tc + 4], a3h, a3l);
#pragma unroll
        for (int nt = 0; nt < 4; nt++) {
            int nl = nt * 8 + tg;                // col local to warp slice
            unsigned b0h, b0l, b1h, b1l;
            split_tf32(myw1[(k + tc) * 40 + nl],     b0h, b0l);
            split_tf32(myw1[(k + tc + 4) * 40 + nl], b1h, b1l);
            mma_tf32(d1acc[nt], a0h, a1h, a2h, a3h, b0l, b1l);
            mma_tf32(d1acc[nt], a0l, a1l, a2l, a3l, b0h, b1h);
            mma_tf32(d1acc[nt], a0h, a1h, a2h, a3h, b0h, b1h);
        }
    }
#pragma unroll
    for (int nt = 0; nt < 4; nt++) {
        int i0 = (w * 4 + nt) * 8 + 2 * tc;
        ts[tg * 260 + i0]           = gelu_exact(d1acc[nt][0] + bm1[i0]);
        ts[tg * 260 + i0 + 1]       = gelu_exact(d1acc[nt][1] + bm1[i0 + 1]);
        ts[(tg + 8) * 260 + i0]     = gelu_exact(d1acc[nt][2] + bm1[i0]);
        ts[(tg + 8) * 260 + i0 + 1] = gelu_exact(d1acc[nt][3] + bm1[i0 + 1]);
    }
    __syncthreads();    // ts published
    cpa_wait0();        // w2 slice resident

    // ---- phase 2: out = ts @ Wm2 + bm2 + yr -- no syncs ----
    float d2acc[4] = {0.f, 0.f, 0.f, 0.f};
#pragma unroll
    for (int t = 0; t < 8; t++) {
#pragma unroll
        for (int ks = 0; ks < 4; ks++) {
            int kg = t * 32 + ks * 8;
            unsigned a0h, a0l, a1h, a1l, a2h, a2l, a3h, a3l, b0h, b0l, b1h, b1l;
            split_tf32(ts[tg * 260 + kg + tc],           a0h, a0l);
            split_tf32(ts[(tg + 8) * 260 + kg + tc],     a1h, a1l);
            split_tf32(ts[tg * 260 + kg + tc + 4],       a2h, a2l);
            split_tf32(ts[(tg + 8) * 260 + kg + tc + 4], a3h, a3l);
            split_tf32(myw2[(kg + tc) * 8 + tg],         b0h, b0l);
            split_tf32(myw2[(kg + tc + 4) * 8 + tg],     b1h, b1l);
            mma_tf32(d2acc, a0h, a1h, a2h, a3h, b0l, b1l);
            mma_tf32(d2acc, a0l, a1l, a2l, a3l, b0h, b1h);
            mma_tf32(d2acc, a0h, a1h, a2h, a3h, b0h, b1h);
        }
    }
    int c0 = w * 8 + 2 * tc;
    float bx = bm2[c0], by = bm2[c0 + 1];
    *(float2*)(out + (rb + tg) * 64 + c0) =
        make_float2(d2acc[0] + bx + yr[tg * 68 + c0],
                    d2acc[1] + by + yr[tg * 68 + c0 + 1]);
    *(float2*)(out + (rb + tg + 8) * 64 + c0) =
        make_float2(d2acc[2] + bx + yr[(tg + 8) * 68 + c0],
                    d2acc[3] + by + yr[(tg + 8) * 68 + c0 + 1]);
}

// ---------------- launch ----------------------------------------------------
extern "C" void kernel_launch(void* const* d_in, const int* in_sizes, int n_in,
                              void* d_out, int out_size) {
    const float* x    = (const float*)d_in[0];
    const float* pos  = (const float*)d_in[1];
    const float* qp   = (const float*)d_in[2];
    const float* qmw  = (const float*)d_in[3];
    const float* qmo  = (const float*)d_in[4];
    const float* W_lin = (const float*)d_in[5];
    const float* b_lin = (const float*)d_in[6];
    const float* rff  = (const float*)d_in[7];
    const float* W1   = (const float*)d_in[8];
    const float* b1   = (const float*)d_in[9];
    const float* W2   = (const float*)d_in[10];
    const float* filt = (const float*)d_in[11];
    const float* bias = (const float*)d_in[12];
    const float* Wm1  = (const float*)d_in[13];
    const float* bm1  = (const float*)d_in[14];
    const float* Wm2  = (const float*)d_in[15];
    const float* bm2  = (const float*)d_in[16];
    float* out = (float*)d_out;

    cudaFuncSetAttribute(kernC, cudaFuncAttributeMaxDynamicSharedMemorySize,
                         KC_SMEM_FLOATS * 4);
    cudaFuncSetAttribute(kernD, cudaFuncAttributeMaxDynamicSharedMemorySize,
                         KD_SMEM_FLOATS * 4);

    kernA<<<512, 256>>>(x, W_lin, b_lin, qp, out, out_size);
    kernB<<<QQ, 256>>>(pos, qp, qmw, qmo, rff, W1, b1);
    kernC<<<128, 256, KC_SMEM_FLOATS * 4>>>(W2, filt, bias);
    kernD<<<128, 256, KD_SMEM_FLOATS * 4>>>(Wm1, bm1, Wm2, bm2, out);
}

// round 10
// speedup vs baseline: 2.8686x; 1.0967x over previous
#include <cuda_runtime.h>
#include <cuda_bf16.h>
#include <math.h>

// Problem constants
#define BB 8
#define NN 2048
#define CC 32
#define DD 64
#define QQ 256
#define KK 205
#define KPAD 208
#define TWO_PI 6.28318530717958647692f

// ---------------- scratch (device globals; no allocations) ----------------
__device__ float g_xl[BB * NN * CC];          // xl[b][n][c]  (tf32-rounded)
__device__ float g_M[QQ * BB * CC * CC];      // M[(q*8+b)][j][c]
__device__ float g_zc[QQ * BB * CC];          // zc[(q*8+b)][c]
__device__ float g_y[BB * QQ * DD];           // y[(b*256+q)][d]

__device__ __forceinline__ float gelu_exact(float v) {
    return 0.5f * v * (1.0f + erff(v * 0.70710678118654752440f));
}
__device__ __forceinline__ float wrapd(float d) {
    float t = d + 0.5f;
    t -= floorf(t);
    return t - 0.5f;
}

// ---- packed f32x2 helpers ----
__device__ __forceinline__ unsigned long long pk2(float lo, float hi) {
    unsigned long long r;
    asm("mov.b64 %0, {%1,%2};" : "=l"(r) : "f"(lo), "f"(hi));
    return r;
}
__device__ __forceinline__ void fma2(unsigned long long& d, unsigned long long a, unsigned long long b) {
    asm("fma.rn.f32x2 %0, %1, %2, %0;" : "+l"(d) : "l"(a), "l"(b));
}
__device__ __forceinline__ float2 up2(unsigned long long v) {
    float lo, hi;
    asm("mov.b64 {%0,%1}, %2;" : "=f"(lo), "=f"(hi) : "l"(v));
    return make_float2(lo, hi);
}
__device__ __forceinline__ unsigned cvt_tf32(float f) {
    unsigned u;
    asm("cvt.rna.tf32.f32 %0, %1;" : "=r"(u) : "f"(f));
    return u;
}
// CVT-free 3xTF32 split: mma.tf32 ignores the low 13 bits of its operands,
// so high = masked bits (LOP3) and low = exact residual (FSUB), both fed raw.
__device__ __forceinline__ void split_tf32(float v, unsigned& h, unsigned& l) {
    h = __float_as_uint(v) & 0xFFFFE000u;
    l = __float_as_uint(v - __uint_as_float(h));
}
__device__ __forceinline__ void mma_tf32(float* d, unsigned a0, unsigned a1,
                                         unsigned a2, unsigned a3,
                                         unsigned b0, unsigned b1) {
    asm volatile(
        "mma.sync.aligned.m16n8k8.row.col.f32.tf32.tf32.f32 "
        "{%0,%1,%2,%3}, {%4,%5,%6,%7}, {%8,%9}, {%0,%1,%2,%3};"
        : "+f"(d[0]), "+f"(d[1]), "+f"(d[2]), "+f"(d[3])
        : "r"(a0), "r"(a1), "r"(a2), "r"(a3), "r"(b0), "r"(b1));
}

// ---- cp.async helpers ----
__device__ __forceinline__ void cpa16(float* dst, const float* src) {
    unsigned s = (unsigned)__cvta_generic_to_shared(dst);
    asm volatile("cp.async.cg.shared.global [%0], [%1], 16;" :: "r"(s), "l"(src));
}
__device__ __forceinline__ void cpa_commit() { asm volatile("cp.async.commit_group;" ::: "memory"); }
__device__ __forceinline__ void cpa_wait2() { asm volatile("cp.async.wait_group 2;" ::: "memory"); }
__device__ __forceinline__ void cpa_wait1() { asm volatile("cp.async.wait_group 1;" ::: "memory"); }
__device__ __forceinline__ void cpa_wait0() { asm volatile("cp.async.wait_group 0;" ::: "memory"); }

// ---------------- Kernel A: xl = tf32(x @ W_lin + b_lin) ; copy query_pos ---
__global__ __launch_bounds__(256) void kernA(const float* __restrict__ x,
                                             const float* __restrict__ W_lin,
                                             const float* __restrict__ b_lin,
                                             const float* __restrict__ qp,
                                             float* __restrict__ out, int out_size) {
    __shared__ float Ws[CC * CC];
    __shared__ float xr[1024];
    __shared__ float bs[CC];
    int tid = threadIdx.x;
    int rowbase = blockIdx.x * 32;
    for (int l = tid; l < CC * CC; l += 256) Ws[l] = W_lin[l];
    if (tid < CC) bs[tid] = b_lin[tid];
    ((float4*)xr)[tid] = ((const float4*)(x + rowbase * CC))[tid];
    __syncthreads();
    int rg = tid >> 5, c = tid & 31;
    float acc[4];
#pragma unroll
    for (int l = 0; l < 4; l++) acc[l] = bs[c];
#pragma unroll
    for (int i = 0; i < CC; i++) {
        float wv = Ws[i * CC + c];
#pragma unroll
        for (int l = 0; l < 4; l++) acc[l] = fmaf(xr[(rg * 4 + l) * CC + i], wv, acc[l]);
    }
#pragma unroll
    for (int l = 0; l < 4; l++)
        g_xl[(rowbase + rg * 4 + l) * CC + c] = __uint_as_float(cvt_tf32(acc[l]));
    if (blockIdx.x == 0) {
        for (int l = tid; l < QQ * 2; l += 256) out[out_size - QQ * 2 + l] = qp[l];
    }
}

// ---------------- Kernel B: per-query topK (radix select) + features + M/zc --
#define GSTR 34
#define SMB_FLOATS 11584
__global__ __launch_bounds__(256, 2) void kernB(const float* __restrict__ pos,
                                                const float* __restrict__ qp,
                                                const float* __restrict__ qmw,
                                                const float* __restrict__ qmo,
                                                const float* __restrict__ rff,
                                                const float* __restrict__ W1,
                                                const float* __restrict__ b1) {
    __shared__ __align__(16) float sm[SMB_FLOATS];
    unsigned* ebits = (unsigned*)sm;
    int* eq = (int*)(sm + 2048);
    float* gs   = sm;
    float* zs   = sm + 7072;
    float* W1s  = sm + 7072;
    float* b1s  = sm + 8096;
    float* qmws = sm + 8128;
    float* qmos = sm + 8160;
    float* rffs = sm + 8192;
    int*   hist = (int*)(sm + 8224);
    unsigned* um = (unsigned*)(sm + 8480);
    float* red  = sm + 8488;
    float* s_sh = sm + 11168;
    int*   ind_sh = (int*)(sm + 11376);

    int q = blockIdx.x, tid = threadIdx.x;
    int lane = tid & 31;
    float qp0 = qp[2 * q], qp1 = qp[2 * q + 1];

    for (int l = tid; l < 1024; l += 256) W1s[l] = W1[l];
    if (tid < 32) {
        b1s[tid] = b1[tid];
        qmws[tid] = qmw[q * 32 + tid];
        qmos[tid] = qmo[q * 32 + tid];
        rffs[tid] = rff[tid];
    }
    if (tid == 0) {
        um[0] = 0; um[1] = 0; um[2] = 0xFFFFFFFFu; um[3] = 0;
        ((int*)um)[4] = KK;
    }
    __syncthreads();

    // ---- phase 1: edist bits + global min ----
    unsigned mymin = 0xFFFFFFFFu;
#pragma unroll
    for (int it = 0; it < 8; it++) {
        int n = tid + it * 256;
        float2 p = ((const float2*)pos)[n];
        float d0 = wrapd(qp0 - p.x);
        float d1 = wrapd(qp1 - p.y);
        float e = d0 * d0 + d1 * d1;
        unsigned eb = __float_as_uint(e);
        ebits[n] = eb;
        mymin = min(mymin, eb);
    }
#pragma unroll
    for (int o = 16; o; o >>= 1) mymin = min(mymin, __shfl_xor_sync(0xffffffffu, mymin, o));
    if (lane == 0) atomicMin(&um[2], mymin);

    // ---- phase 2: 4-pass radix select ----
    for (int pass = 0; pass < 4; pass++) {
        int sh = 24 - 8 * pass;
        if (tid < 256) hist[tid] = 0;
        __syncthreads();
        unsigned pref = um[3];
        unsigned hm = pass ? (0xFFFFFFFFu << (sh + 8)) : 0u;
#pragma unroll
        for (int it = 0; it < 8; it++) {
            unsigned e = ebits[tid + it * 256];
            bool p = ((e & hm) == pref);
            unsigned act = __ballot_sync(0xffffffffu, p);
            if (p) {
                int bin = (e >> sh) & 255;
                unsigned m = __match_any_sync(act, bin);
                if ((__ffs(m) - 1) == lane) atomicAdd(&hist[bin], __popc(m));
            }
        }
        __syncthreads();
        if (tid < 32) {
            int loc[8]; int s0 = 0;
#pragma unroll
            for (int i = 0; i < 8; i++) { loc[i] = hist[tid * 8 + i]; s0 += loc[i]; }
            int inc = s0;
#pragma unroll
            for (int o = 1; o < 32; o <<= 1) {
                int v = __shfl_up_sync(0xffffffffu, inc, o);
                if (tid >= o) inc += v;
            }
            int exc = inc - s0;
            int rk = ((int*)um)[4];
            if (rk > exc && rk <= inc) {
                int rr = rk - exc;
#pragma unroll
                for (int i = 0; i < 8; i++) {
                    if (rr > loc[i]) rr -= loc[i];
                    else { um[3] = pref | ((unsigned)(tid * 8 + i) << sh); ((int*)um)[4] = rr; break; }
                }
            }
        }
        __syncthreads();
    }
    unsigned vsel = um[3];
    int rsel = ((int*)um)[4];

    // ---- phase 3: compaction ----
#pragma unroll
    for (int it = 0; it < 8; it++) {
        int n = tid + it * 256;
        unsigned e = ebits[n];
        if (e < vsel)       { int p = atomicAdd((int*)&um[0], 1); ind_sh[p] = n; }
        else if (e == vsel) { int p = atomicAdd((int*)&um[1], 1); eq[p] = n; }
    }
    __syncthreads();
    {
        int m = (int)um[1], base = (int)um[0];
        for (int t = tid; t < m; t += 256) {
            int my = eq[t], c = 0;
            for (int i = 0; i < m; i++) c += (eq[i] < my);
            if (c < rsel) ind_sh[base + c] = my;
        }
    }
    if (tid >= KK && tid < KPAD) ind_sh[tid] = 0;
    __syncthreads();

    // ---- phase 4: softmax weights ----
    float ed0 = __uint_as_float(um[2]);
    float edK = __uint_as_float(vsel);
    float invden = 1.0f / ((edK - ed0) + 1e-8f);
    float w = 0.0f; int indv = 0;
    if (tid < KK) {
        indv = ind_sh[tid];
        float e = __uint_as_float(ebits[indv]);
        w = __expf(-(e - ed0) * invden);
    }
    float ws = w;
#pragma unroll
    for (int o = 16; o; o >>= 1) ws += __shfl_xor_sync(0xffffffffu, ws, o);
    if (lane == 0) red[tid >> 5] = ws;
    __syncthreads();
    if (tid < 8) {
        float v = red[tid];
        v += __shfl_xor_sync(0x000000ffu, v, 4);
        v += __shfl_xor_sync(0x000000ffu, v, 2);
        v += __shfl_xor_sync(0x000000ffu, v, 1);
        if (tid == 0) red[0] = v;
    }
    __syncthreads();
    float sk = (tid < KK) ? (w / red[0]) : 0.0f;
    if (tid < KPAD) s_sh[tid] = sk;
    __syncthreads();

    // ---- phase 5: per-k RFF features -> h -> gelu -> gs = tf32(g * s) ----
    if (tid < KK) {
        float2 pp = ((const float2*)pos)[indv];
        float d0 = wrapd(qp0 - pp.x);
        float d1 = wrapd(qp1 - pp.y);
        float ft[32];
#pragma unroll
        for (int f = 0; f < 16; f++) {
            float p = TWO_PI * (d0 * rffs[f] + d1 * rffs[16 + f]);
            __sincosf(p, &ft[f], &ft[f + 16]);
        }
        unsigned long long h2[16];
        const unsigned long long* b1p = (const unsigned long long*)b1s;
#pragma unroll
        for (int jp = 0; jp < 16; jp++) h2[jp] = b1p[jp];
#pragma unroll 4
        for (int i = 0; i < 32; i++) {
            unsigned long long fi = pk2(ft[i], ft[i]);
            const unsigned long long* w1p = (const unsigned long long*)(W1s + i * 32);
#pragma unroll
            for (int jp = 0; jp < 16; jp++) fma2(h2[jp], fi, w1p[jp]);
        }
        unsigned long long* grow = (unsigned long long*)(gs + tid * GSTR);
#pragma unroll
        for (int jp = 0; jp < 16; jp++) {
            float2 hv = up2(h2[jp]);
            int j0 = 2 * jp;
            float a0 = gelu_exact(hv.x * qmws[j0] + qmos[j0]) * sk;
            float a1 = gelu_exact(hv.y * qmws[j0 + 1] + qmos[j0 + 1]) * sk;
            unsigned u0 = cvt_tf32(a0), u1 = cvt_tf32(a1);
            grow[jp] = ((unsigned long long)u1 << 32) | u0;
        }
    } else if (tid < KPAD) {
        unsigned long long* grow = (unsigned long long*)(gs + tid * GSTR);
#pragma unroll
        for (int jp = 0; jp < 16; jp++) grow[jp] = 0ull;
    }
    __syncthreads();

    // ---- phase 6: tf32 tensor-core M accumulation, warp-local gather -------
    int b = tid >> 5;
    int tg = lane >> 2, tc = lane & 3;
    float* zw = zs + b * 512;
    int kkl = lane >> 2, c4l = lane & 3;
    int swA = ((c4l ^ (2 * (kkl & 3))) & 7) * 4;
    int swB = (((c4l + 4) ^ (2 * (kkl & 3))) & 7) * 4;

    float dacc[2][4][4];
#pragma unroll
    for (int mt = 0; mt < 2; mt++)
#pragma unroll
        for (int nt = 0; nt < 4; nt++)
#pragma unroll
            for (int r = 0; r < 4; r++) dacc[mt][nt][r] = 0.0f;
    float zca = 0.0f;

    {
        int n = ind_sh[kkl];
        const float* src = g_xl + ((b * NN + n) << 5);
        cpa16(zw + kkl * 32 + swA, src + c4l * 4);
        cpa16(zw + kkl * 32 + swB, src + (c4l + 4) * 4);
        cpa_commit();
    }
    for (int t = 0; t < 26; t++) {
        __syncwarp();
        if (t < 25) {
            int k0n = (t + 1) * 8;
            float* nb = zw + ((t + 1) & 1) * 256;
            int n = ind_sh[k0n + kkl];
            const float* src = g_xl + ((b * NN + n) << 5);
            cpa16(nb + kkl * 32 + swA, src + c4l * 4);
            cpa16(nb + kkl * 32 + swB, src + (c4l + 4) * 4);
            cpa_commit();
            cpa_wait1();
        } else {
            cpa_wait0();
        }
        __syncwarp();
        const float* buf = zw + (t & 1) * 256;
        int k0 = t * 8;
#pragma unroll
        for (int kk = 0; kk < 8; kk++)
            zca = fmaf(s_sh[k0 + kk], buf[kk * 32 + (lane ^ (8 * (kk & 3)))], zca);
        unsigned bf[4][2];
#pragma unroll
        for (int nt = 0; nt < 4; nt++) {
            int cw = ((nt * 8 + tg) ^ (8 * tc));
            bf[nt][0] = __float_as_uint(buf[tc * 32 + cw]);
            bf[nt][1] = __float_as_uint(buf[(tc + 4) * 32 + cw]);
        }
#pragma unroll
        for (int mt = 0; mt < 2; mt++) {
            const float* g0 = gs + (k0 + tc) * GSTR + mt * 16;
            const float* g4 = g0 + 4 * GSTR;
            unsigned a0 = __float_as_uint(g0[tg]);
            unsigned a1 = __float_as_uint(g0[tg + 8]);
            unsigned a2 = __float_as_uint(g4[tg]);
            unsigned a3 = __float_as_uint(g4[tg + 8]);
#pragma unroll
            for (int nt = 0; nt < 4; nt++)
                mma_tf32(dacc[mt][nt], a0, a1, a2, a3, bf[nt][0], bf[nt][1]);
        }
    }
    int q8b = q * 8 + b;
#pragma unroll
    for (int mt = 0; mt < 2; mt++) {
#pragma unroll
        for (int nt = 0; nt < 4; nt++) {
            float* base = g_M + (q8b * 32 + mt * 16 + tg) * 32 + nt * 8 + 2 * tc;
            *(float2*)base = make_float2(dacc[mt][nt][0], dacc[mt][nt][1]);
            *(float2*)(base + 8 * 32) = make_float2(dacc[mt][nt][2], dacc[mt][nt][3]);
        }
    }
    g_zc[q8b * 32 + lane] = zca;
}

// ---------------- Kernel C: 3xTF32, M-tile resident + warp-local W2 stream --
#define KC_SMEM_FLOATS 23184
__global__ __launch_bounds__(256) void kernC(const float* __restrict__ W2,
                                             const float* __restrict__ filt,
                                             const float* __restrict__ bias) {
    extern __shared__ float dsm[];
    float* Mt    = dsm;                 // stride 1028 (conflict-free A frags)
    float* wsl   = dsm + 16448;         // per-warp double buffer [32][8]
    float* filts = dsm + 20544;
    float* zct   = dsm + 22592;         // stride 33
    float* biass = dsm + 23120;
    int tid = threadIdx.x;
    int lane = tid & 31, w = tid >> 5, tg = lane >> 2, tc = lane & 3;
    int rowbase = blockIdx.x * 16;
    float* myslot = wsl + w * 512;      // 2 slots x 256 floats

    {
#pragma unroll
        for (int i = 0; i < 16; i++) {
            int ch = tid + i * 256;
            int row = ch >> 8, c4 = (ch & 255) * 4;
            cpa16(Mt + row * 1028 + c4, g_M + (rowbase + row) * 1024 + c4);
        }
        cpa_commit();   // group: M
    }
    auto issueW = [&](int tt) {
#pragma unroll
        for (int r = 0; r < 2; r++) {
            int ch = lane + r * 32;
            int row = ch >> 1, half = ch & 1;
            int jcg = tt * 32 + row;
            cpa16(myslot + (tt & 1) * 256 + row * 8 + half * 4,
                  W2 + (jcg >> 5) * 2048 + (jcg & 31) * 64 + w * 8 + half * 4);
        }
        cpa_commit();
    };
    issueW(0);
    issueW(1);

    for (int l = tid; l < 2048; l += 256) filts[l] = filt[l];
    for (int l = tid; l < 512; l += 256) zct[(l >> 5) * 33 + (l & 31)] = g_zc[rowbase * 32 + l];
    if (tid < 64) biass[tid] = bias[tid];

    cpa_wait2();
    __syncthreads();

    float dacc[4] = {0.f, 0.f, 0.f, 0.f};
    for (int t = 0; t < 32; t++) {
        if (t < 31) cpa_wait1(); else cpa_wait0();
        __syncwarp();
        const float* Wb = myslot + (t & 1) * 256;
#pragma unroll
        for (int ks = 0; ks < 4; ks++) {
            int k = t * 32 + ks * 8;
            unsigned a0h, a0l, a1h, a1l, a2h, a2l, a3h, a3l, b0h, b0l, b1h, b1l;
            split_tf32(Mt[tg * 1028 + k + tc],           a0h, a0l);
            split_tf32(Mt[(tg + 8) * 1028 + k + tc],     a1h, a1l);
            split_tf32(Mt[tg * 1028 + k + tc + 4],       a2h, a2l);
            split_tf32(Mt[(tg + 8) * 1028 + k + tc + 4], a3h, a3l);
            split_tf32(Wb[(ks * 8 + tc) * 8 + tg],       b0h, b0l);
            split_tf32(Wb[(ks * 8 + tc + 4) * 8 + tg],   b1h, b1l);
            mma_tf32(dacc, a0h, a1h, a2h, a3h, b0l, b1l);
            mma_tf32(dacc, a0l, a1l, a2l, a3l, b0h, b1h);
            mma_tf32(dacc, a0h, a1h, a2h, a3h, b0h, b1h);
        }
        __syncwarp();
        if (t <= 29) issueW(t + 2);
    }
    int c0 = w * 8 + 2 * tc;
    unsigned long long F0 = 0ull, F1 = 0ull;
#pragma unroll 8
    for (int c = 0; c < 32; c++) {
        unsigned long long wp = *(const unsigned long long*)(filts + c * 64 + c0);
        float z0 = zct[tg * 33 + c], z1 = zct[(tg + 8) * 33 + c];
        fma2(F0, pk2(z0, z0), wp);
        fma2(F1, pk2(z1, z1), wp);
    }
    float2 f0 = up2(F0), f1 = up2(F1);
    int r0 = rowbase + tg, r1 = r0 + 8;
    int q0 = r0 >> 3, b0r = r0 & 7, q1 = r1 >> 3, b1r = r1 & 7;
    float bx = biass[c0], by = biass[c0 + 1];
    *(float2*)(g_y + (b0r * QQ + q0) * 64 + c0) =
        make_float2(gelu_exact(dacc[0] + f0.x + bx), gelu_exact(dacc[1] + f0.y + by));
    *(float2*)(g_y + (b1r * QQ + q1) * 64 + c0) =
        make_float2(gelu_exact(dacc[2] + f1.x + bx), gelu_exact(dacc[3] + f1.y + by));
}

// ---------------- Kernel D: 3xTF32, warp-resident weight slices -------------
#define KD_SMEM_FLOATS 42112
__global__ __launch_bounds__(256) void kernD(const float* __restrict__ Wm1,
                                             const float* __restrict__ bm1,
                                             const float* __restrict__ Wm2,
                                             const float* __restrict__ bm2,
                                             float* __restrict__ out) {
    extern __shared__ float dsm[];
    float* yr  = dsm;                  // stride 68
    float* ts  = dsm + 1088;           // stride 260
    float* w1s = dsm + 5248;           // per-warp [64][40]
    float* w2s = dsm + 25728;          // per-warp [256][8]
    int tid = threadIdx.x;
    int lane = tid & 31, w = tid >> 5, tg = lane >> 2, tc = lane & 3;
    int rb = blockIdx.x * 16;
    float* myw1 = w1s + w * 2560;
    float* myw2 = w2s + w * 2048;

    {
        int r = tid >> 4, d4 = (tid & 15) * 4;
        *(float4*)(yr + r * 68 + d4) = *(const float4*)(g_y + (rb + r) * 64 + d4);
    }
#pragma unroll
    for (int i = 0; i < 16; i++) {
        int ch = lane + i * 32;
        int row = ch >> 3, c4 = (ch & 7) * 4;
        cpa16(myw1 + row * 40 + c4, Wm1 + row * 256 + w * 32 + c4);
    }
    cpa_commit();   // group w1
#pragma unroll
    for (int i = 0; i < 16; i++) {
        int ch = lane + i * 32;
        int row = ch >> 1, half = ch & 1;
        cpa16(myw2 + row * 8 + half * 4, Wm2 + row * 64 + w * 8 + half * 4);
    }
    cpa_commit();   // group w2

    cpa_wait1();
    __syncthreads();

    // ---- phase 1: ts = gelu(yr @ Wm1 + bm1) ----
    float d1acc[4][4];
#pragma unroll
    for (int nt = 0; nt < 4; nt++)
#pragma unroll
        for (int r = 0; r < 4; r++) d1acc[nt][r] = 0.0f;
#pragma unroll
    for (int t = 0; t < 8; t++) {
        int k = t * 8;
        unsigned a0h, a0l, a1h, a1l, a2h, a2l, a3h, a3l;
        split_tf32(yr[tg * 68 + k + tc],           a0h, a0l);
        split_tf32(yr[(tg + 8) * 68 + k + tc],     a1h, a1l);
        split_tf32(yr[tg * 68 + k + tc + 4],       a2h, a2l);
        split_tf32(yr[(tg + 8) * 68 + k + tc + 4], a3h, a3l);
#pragma unroll
        for (int nt = 0; nt < 4; nt++) {
            int nl = nt * 8 + tg;
            unsigned b0h, b0l, b1h, b1l;
            split_tf32(myw1[(k + tc) * 40 + nl],     b0h, b0l);
            split_tf32(myw1[(k + tc + 4) * 40 + nl], b1h, b1l);
            mma_tf32(d1acc[nt], a0h, a1h, a2h, a3h, b0l, b1l);
            mma_tf32(d1acc[nt], a0l, a1l, a2l, a3l, b0h, b1h);
            mma_tf32(d1acc[nt], a0h, a1h, a2h, a3h, b0h, b1h);
        }
    }
#pragma unroll
    for (int nt = 0; nt < 4; nt++) {
        int i0 = (w * 4 + nt) * 8 + 2 * tc;
        ts[tg * 260 + i0]           = gelu_exact(d1acc[nt][0] + bm1[i0]);
        ts[tg * 260 + i0 + 1]       = gelu_exact(d1acc[nt][1] + bm1[i0 + 1]);
        ts[(tg + 8) * 260 + i0]     = gelu_exact(d1acc[nt][2] + bm1[i0]);
        ts[(tg + 8) * 260 + i0 + 1] = gelu_exact(d1acc[nt][3] + bm1[i0 + 1]);
    }
    __syncthreads();
    cpa_wait0();

    // ---- phase 2: out = ts @ Wm2 + bm2 + yr ----
    float d2acc[4] = {0.f, 0.f, 0.f, 0.f};
#pragma unroll
    for (int t = 0; t < 8; t++) {
#pragma unroll
        for (int ks = 0; ks < 4; ks++) {
            int kg = t * 32 + ks * 8;
            unsigned a0h, a0l, a1h, a1l, a2h, a2l, a3h, a3l, b0h, b0l, b1h, b1l;
            split_tf32(ts[tg * 260 + kg + tc],           a0h, a0l);
            split_tf32(ts[(tg + 8) * 260 + kg + tc],     a1h, a1l);
            split_tf32(ts[tg * 260 + kg + tc + 4],       a2h, a2l);
            split_tf32(ts[(tg + 8) * 260 + kg + tc + 4], a3h, a3l);
            split_tf32(myw2[(kg + tc) * 8 + tg],         b0h, b0l);
            split_tf32(myw2[(kg + tc + 4) * 8 + tg],     b1h, b1l);
            mma_tf32(d2acc, a0h, a1h, a2h, a3h, b0l, b1l);
            mma_tf32(d2acc, a0l, a1l, a2l, a3l, b0h, b1h);
            mma_tf32(d2acc, a0h, a1h, a2h, a3h, b0h, b1h);
        }
    }
    int c0 = w * 8 + 2 * tc;
    float bx = bm2[c0], by = bm2[c0 + 1];
    *(float2*)(out + (rb + tg) * 64 + c0) =
        make_float2(d2acc[0] + bx + yr[tg * 68 + c0],
                    d2acc[1] + by + yr[tg * 68 + c0 + 1]);
    *(float2*)(out + (rb + tg + 8) * 64 + c0) =
        make_float2(d2acc[2] + bx + yr[(tg + 8) * 68 + c0],
                    d2acc[3] + by + yr[(tg + 8) * 68 + c0 + 1]);
}

// ---------------- launch ----------------------------------------------------
extern "C" void kernel_launch(void* const* d_in, const int* in_sizes, int n_in,
                              void* d_out, int out_size) {
    const float* x    = (const float*)d_in[0];
    const float* pos  = (const float*)d_in[1];
    const float* qp   = (const float*)d_in[2];
    const float* qmw  = (const float*)d_in[3];
    const float* qmo  = (const float*)d_in[4];
    const float* W_lin = (const float*)d_in[5];
    const float* b_lin = (const float*)d_in[6];
    const float* rff  = (const float*)d_in[7];
    const float* W1   = (const float*)d_in[8];
    const float* b1   = (const float*)d_in[9];
    const float* W2   = (const float*)d_in[10];
    const float* filt = (const float*)d_in[11];
    const float* bias = (const float*)d_in[12];
    const float* Wm1  = (const float*)d_in[13];
    const float* bm1  = (const float*)d_in[14];
    const float* Wm2  = (const float*)d_in[15];
    const float* bm2  = (const float*)d_in[16];
    float* out = (float*)d_out;

    cudaFuncSetAttribute(kernC, cudaFuncAttributeMaxDynamicSharedMemorySize,
                         KC_SMEM_FLOATS * 4);
    cudaFuncSetAttribute(kernD, cudaFuncAttributeMaxDynamicSharedMemorySize,
                         KD_SMEM_FLOATS * 4);

    kernA<<<512, 256>>>(x, W_lin, b_lin, qp, out, out_size);
    kernB<<<QQ, 256>>>(pos, qp, qmw, qmo, rff, W1, b1);
    kernC<<<128, 256, KC_SMEM_FLOATS * 4>>>(W2, filt, bias);
    kernD<<<128, 256, KD_SMEM_FLOATS * 4>>>(Wm1, bm1, Wm2, bm2, out);
}

// round 11
// speedup vs baseline: 2.8715x; 1.0010x over previous
#include <cuda_runtime.h>
#include <cuda_bf16.h>
#include <math.h>

// Problem constants
#define BB 8
#define NN 2048
#define CC 32
#define DD 64
#define QQ 256
#define KK 205
#define KPAD 208
#define TWO_PI 6.28318530717958647692f

// ---------------- scratch (device globals; no allocations) ----------------
__device__ float g_xl[BB * NN * CC];          // xl[b][n][c]  (tf32-rounded)
__device__ float g_M[QQ * BB * CC * CC];      // M[(q*8+b)][j][c]
__device__ float g_zc[QQ * BB * CC];          // zc[(q*8+b)][c]
__device__ float g_y[BB * QQ * DD];           // y[(b*256+q)][d]

__device__ __forceinline__ float gelu_exact(float v) {
    return 0.5f * v * (1.0f + erff(v * 0.70710678118654752440f));
}
__device__ __forceinline__ float wrapd(float d) {
    float t = d + 0.5f;
    t -= floorf(t);
    return t - 0.5f;
}

// ---- packed f32x2 helpers ----
__device__ __forceinline__ unsigned long long pk2(float lo, float hi) {
    unsigned long long r;
    asm("mov.b64 %0, {%1,%2};" : "=l"(r) : "f"(lo), "f"(hi));
    return r;
}
__device__ __forceinline__ void fma2(unsigned long long& d, unsigned long long a, unsigned long long b) {
    asm("fma.rn.f32x2 %0, %1, %2, %0;" : "+l"(d) : "l"(a), "l"(b));
}
__device__ __forceinline__ float2 up2(unsigned long long v) {
    float lo, hi;
    asm("mov.b64 {%0,%1}, %2;" : "=f"(lo), "=f"(hi) : "l"(v));
    return make_float2(lo, hi);
}
__device__ __forceinline__ unsigned cvt_tf32(float f) {
    unsigned u;
    asm("cvt.rna.tf32.f32 %0, %1;" : "=r"(u) : "f"(f));
    return u;
}
// CVT-free 3xTF32 split: mma.tf32 ignores the low 13 bits of its operands.
__device__ __forceinline__ void split_tf32(float v, unsigned& h, unsigned& l) {
    h = __float_as_uint(v) & 0xFFFFE000u;
    l = __float_as_uint(v - __uint_as_float(h));
}
__device__ __forceinline__ void mma_tf32(float* d, unsigned a0, unsigned a1,
                                         unsigned a2, unsigned a3,
                                         unsigned b0, unsigned b1) {
    asm volatile(
        "mma.sync.aligned.m16n8k8.row.col.f32.tf32.tf32.f32 "
        "{%0,%1,%2,%3}, {%4,%5,%6,%7}, {%8,%9}, {%0,%1,%2,%3};"
        : "+f"(d[0]), "+f"(d[1]), "+f"(d[2]), "+f"(d[3])
        : "r"(a0), "r"(a1), "r"(a2), "r"(a3), "r"(b0), "r"(b1));
}

// ---- cp.async helpers ----
__device__ __forceinline__ void cpa16(float* dst, const float* src) {
    unsigned s = (unsigned)__cvta_generic_to_shared(dst);
    asm volatile("cp.async.cg.shared.global [%0], [%1], 16;" :: "r"(s), "l"(src));
}
__device__ __forceinline__ void cpa_commit() { asm volatile("cp.async.commit_group;" ::: "memory"); }
__device__ __forceinline__ void cpa_wait2() { asm volatile("cp.async.wait_group 2;" ::: "memory"); }
__device__ __forceinline__ void cpa_wait1() { asm volatile("cp.async.wait_group 1;" ::: "memory"); }
__device__ __forceinline__ void cpa_wait0() { asm volatile("cp.async.wait_group 0;" ::: "memory"); }

// ---------------- Kernel A: xl = tf32(x @ W_lin + b_lin) ; copy query_pos ---
__global__ __launch_bounds__(256) void kernA(const float* __restrict__ x,
                                             const float* __restrict__ W_lin,
                                             const float* __restrict__ b_lin,
                                             const float* __restrict__ qp,
                                             float* __restrict__ out, int out_size) {
    __shared__ float Ws[CC * CC];
    __shared__ float xr[1024];
    __shared__ float bs[CC];
    int tid = threadIdx.x;
    int rowbase = blockIdx.x * 32;
    for (int l = tid; l < CC * CC; l += 256) Ws[l] = W_lin[l];
    if (tid < CC) bs[tid] = b_lin[tid];
    ((float4*)xr)[tid] = ((const float4*)(x + rowbase * CC))[tid];
    __syncthreads();
    int rg = tid >> 5, c = tid & 31;
    float acc[4];
#pragma unroll
    for (int l = 0; l < 4; l++) acc[l] = bs[c];
#pragma unroll
    for (int i = 0; i < CC; i++) {
        float wv = Ws[i * CC + c];
#pragma unroll
        for (int l = 0; l < 4; l++) acc[l] = fmaf(xr[(rg * 4 + l) * CC + i], wv, acc[l]);
    }
#pragma unroll
    for (int l = 0; l < 4; l++)
        g_xl[(rowbase + rg * 4 + l) * CC + c] = __uint_as_float(cvt_tf32(acc[l]));
    if (blockIdx.x == 0) {
        for (int l = tid; l < QQ * 2; l += 256) out[out_size - QQ * 2 + l] = qp[l];
    }
}

// ---------------- Kernel B: per-query topK (radix select) + features + M/zc --
#define GSTR 34
#define SMB_FLOATS 11584
__global__ __launch_bounds__(256, 2) void kernB(const float* __restrict__ pos,
                                                const float* __restrict__ qp,
                                                const float* __restrict__ qmw,
                                                const float* __restrict__ qmo,
                                                const float* __restrict__ rff,
                                                const float* __restrict__ W1,
                                                const float* __restrict__ b1) {
    __shared__ __align__(16) float sm[SMB_FLOATS];
    unsigned* ebits = (unsigned*)sm;
    int* eq = (int*)(sm + 2048);
    float* gs   = sm;
    float* zs   = sm + 7072;
    float* W1s  = sm + 7072;
    float* b1s  = sm + 8096;
    float* qmws = sm + 8128;
    float* qmos = sm + 8160;
    float* rffs = sm + 8192;
    int*   hist = (int*)(sm + 8224);
    unsigned* um = (unsigned*)(sm + 8480);
    float* red  = sm + 8488;
    float* s_sh = sm + 11168;
    int*   ind_sh = (int*)(sm + 11376);

    int q = blockIdx.x, tid = threadIdx.x;
    int lane = tid & 31;
    float qp0 = qp[2 * q], qp1 = qp[2 * q + 1];

    for (int l = tid; l < 1024; l += 256) W1s[l] = W1[l];
    if (tid < 32) {
        b1s[tid] = b1[tid];
        qmws[tid] = qmw[q * 32 + tid];
        qmos[tid] = qmo[q * 32 + tid];
        rffs[tid] = rff[tid];
    }
    if (tid == 0) {
        um[0] = 0; um[1] = 0; um[2] = 0xFFFFFFFFu; um[3] = 0;
        ((int*)um)[4] = KK;
    }
    __syncthreads();

    // ---- phase 1: edist bits + global min ----
    unsigned mymin = 0xFFFFFFFFu;
#pragma unroll
    for (int it = 0; it < 8; it++) {
        int n = tid + it * 256;
        float2 p = ((const float2*)pos)[n];
        float d0 = wrapd(qp0 - p.x);
        float d1 = wrapd(qp1 - p.y);
        float e = d0 * d0 + d1 * d1;
        unsigned eb = __float_as_uint(e);
        ebits[n] = eb;
        mymin = min(mymin, eb);
    }
#pragma unroll
    for (int o = 16; o; o >>= 1) mymin = min(mymin, __shfl_xor_sync(0xffffffffu, mymin, o));
    if (lane == 0) atomicMin(&um[2], mymin);

    // ---- phase 2: 4-pass radix select ----
    for (int pass = 0; pass < 4; pass++) {
        int sh = 24 - 8 * pass;
        if (tid < 256) hist[tid] = 0;
        __syncthreads();
        unsigned pref = um[3];
        unsigned hm = pass ? (0xFFFFFFFFu << (sh + 8)) : 0u;
#pragma unroll
        for (int it = 0; it < 8; it++) {
            unsigned e = ebits[tid + it * 256];
            bool p = ((e & hm) == pref);
            unsigned act = __ballot_sync(0xffffffffu, p);
            if (p) {
                int bin = (e >> sh) & 255;
                unsigned m = __match_any_sync(act, bin);
                if ((__ffs(m) - 1) == lane) atomicAdd(&hist[bin], __popc(m));
            }
        }
        __syncthreads();
        if (tid < 32) {
            int loc[8]; int s0 = 0;
#pragma unroll
            for (int i = 0; i < 8; i++) { loc[i] = hist[tid * 8 + i]; s0 += loc[i]; }
            int inc = s0;
#pragma unroll
            for (int o = 1; o < 32; o <<= 1) {
                int v = __shfl_up_sync(0xffffffffu, inc, o);
                if (tid >= o) inc += v;
            }
            int exc = inc - s0;
            int rk = ((int*)um)[4];
            if (rk > exc && rk <= inc) {
                int rr = rk - exc;
#pragma unroll
                for (int i = 0; i < 8; i++) {
                    if (rr > loc[i]) rr -= loc[i];
                    else { um[3] = pref | ((unsigned)(tid * 8 + i) << sh); ((int*)um)[4] = rr; break; }
                }
            }
        }
        __syncthreads();
    }
    unsigned vsel = um[3];
    int rsel = ((int*)um)[4];

    // ---- phase 3: compaction ----
#pragma unroll
    for (int it = 0; it < 8; it++) {
        int n = tid + it * 256;
        unsigned e = ebits[n];
        if (e < vsel)       { int p = atomicAdd((int*)&um[0], 1); ind_sh[p] = n; }
        else if (e == vsel) { int p = atomicAdd((int*)&um[1], 1); eq[p] = n; }
    }
    __syncthreads();
    {
        int m = (int)um[1], base = (int)um[0];
        for (int t = tid; t < m; t += 256) {
            int my = eq[t], c = 0;
            for (int i = 0; i < m; i++) c += (eq[i] < my);
            if (c < rsel) ind_sh[base + c] = my;
        }
    }
    if (tid >= KK && tid < KPAD) ind_sh[tid] = 0;
    __syncthreads();

    // ---- phase 4: softmax weights ----
    float ed0 = __uint_as_float(um[2]);
    float edK = __uint_as_float(vsel);
    float invden = 1.0f / ((edK - ed0) + 1e-8f);
    float w = 0.0f; int indv = 0;
    if (tid < KK) {
        indv = ind_sh[tid];
        float e = __uint_as_float(ebits[indv]);
        w = __expf(-(e - ed0) * invden);
    }
    float ws = w;
#pragma unroll
    for (int o = 16; o; o >>= 1) ws += __shfl_xor_sync(0xffffffffu, ws, o);
    if (lane == 0) red[tid >> 5] = ws;
    __syncthreads();
    if (tid < 8) {
        float v = red[tid];
        v += __shfl_xor_sync(0x000000ffu, v, 4);
        v += __shfl_xor_sync(0x000000ffu, v, 2);
        v += __shfl_xor_sync(0x000000ffu, v, 1);
        if (tid == 0) red[0] = v;
    }
    __syncthreads();
    float sk = (tid < KK) ? (w / red[0]) : 0.0f;
    if (tid < KPAD) s_sh[tid] = sk;
    __syncthreads();

    // ---- phase 5: per-k RFF features -> h -> gelu -> gs = tf32(g * s) ----
    if (tid < KK) {
        float2 pp = ((const float2*)pos)[indv];
        float d0 = wrapd(qp0 - pp.x);
        float d1 = wrapd(qp1 - pp.y);
        float ft[32];
#pragma unroll
        for (int f = 0; f < 16; f++) {
            float p = TWO_PI * (d0 * rffs[f] + d1 * rffs[16 + f]);
            __sincosf(p, &ft[f], &ft[f + 16]);
        }
        unsigned long long h2[16];
        const unsigned long long* b1p = (const unsigned long long*)b1s;
#pragma unroll
        for (int jp = 0; jp < 16; jp++) h2[jp] = b1p[jp];
#pragma unroll 4
        for (int i = 0; i < 32; i++) {
            unsigned long long fi = pk2(ft[i], ft[i]);
            const unsigned long long* w1p = (const unsigned long long*)(W1s + i * 32);
#pragma unroll
            for (int jp = 0; jp < 16; jp++) fma2(h2[jp], fi, w1p[jp]);
        }
        unsigned long long* grow = (unsigned long long*)(gs + tid * GSTR);
#pragma unroll
        for (int jp = 0; jp < 16; jp++) {
            float2 hv = up2(h2[jp]);
            int j0 = 2 * jp;
            float a0 = gelu_exact(hv.x * qmws[j0] + qmos[j0]) * sk;
            float a1 = gelu_exact(hv.y * qmws[j0 + 1] + qmos[j0 + 1]) * sk;
            unsigned u0 = cvt_tf32(a0), u1 = cvt_tf32(a1);
            grow[jp] = ((unsigned long long)u1 << 32) | u0;
        }
    } else if (tid < KPAD) {
        unsigned long long* grow = (unsigned long long*)(gs + tid * GSTR);
#pragma unroll
        for (int jp = 0; jp < 16; jp++) grow[jp] = 0ull;
    }
    __syncthreads();

    // ---- phase 6: tf32 tensor-core M accumulation, warp-local gather -------
    int b = tid >> 5;
    int tg = lane >> 2, tc = lane & 3;
    float* zw = zs + b * 512;
    int kkl = lane >> 2, c4l = lane & 3;
    int swA = ((c4l ^ (2 * (kkl & 3))) & 7) * 4;
    int swB = (((c4l + 4) ^ (2 * (kkl & 3))) & 7) * 4;

    float dacc[2][4][4];
#pragma unroll
    for (int mt = 0; mt < 2; mt++)
#pragma unroll
        for (int nt = 0; nt < 4; nt++)
#pragma unroll
            for (int r = 0; r < 4; r++) dacc[mt][nt][r] = 0.0f;
    float zca = 0.0f;

    {
        int n = ind_sh[kkl];
        const float* src = g_xl + ((b * NN + n) << 5);
        cpa16(zw + kkl * 32 + swA, src + c4l * 4);
        cpa16(zw + kkl * 32 + swB, src + (c4l + 4) * 4);
        cpa_commit();
    }
    for (int t = 0; t < 26; t++) {
        __syncwarp();
        if (t < 25) {
            int k0n = (t + 1) * 8;
            float* nb = zw + ((t + 1) & 1) * 256;
            int n = ind_sh[k0n + kkl];
            const float* src = g_xl + ((b * NN + n) << 5);
            cpa16(nb + kkl * 32 + swA, src + c4l * 4);
            cpa16(nb + kkl * 32 + swB, src + (c4l + 4) * 4);
            cpa_commit();
            cpa_wait1();
        } else {
            cpa_wait0();
        }
        __syncwarp();
        const float* buf = zw + (t & 1) * 256;
        int k0 = t * 8;
#pragma unroll
        for (int kk = 0; kk < 8; kk++)
            zca = fmaf(s_sh[k0 + kk], buf[kk * 32 + (lane ^ (8 * (kk & 3)))], zca);
        unsigned bf[4][2];
#pragma unroll
        for (int nt = 0; nt < 4; nt++) {
            int cw = ((nt * 8 + tg) ^ (8 * tc));
            bf[nt][0] = __float_as_uint(buf[tc * 32 + cw]);
            bf[nt][1] = __float_as_uint(buf[(tc + 4) * 32 + cw]);
        }
#pragma unroll
        for (int mt = 0; mt < 2; mt++) {
            const float* g0 = gs + (k0 + tc) * GSTR + mt * 16;
            const float* g4 = g0 + 4 * GSTR;
            unsigned a0 = __float_as_uint(g0[tg]);
            unsigned a1 = __float_as_uint(g0[tg + 8]);
            unsigned a2 = __float_as_uint(g4[tg]);
            unsigned a3 = __float_as_uint(g4[tg + 8]);
#pragma unroll
            for (int nt = 0; nt < 4; nt++)
                mma_tf32(dacc[mt][nt], a0, a1, a2, a3, bf[nt][0], bf[nt][1]);
        }
    }
    int q8b = q * 8 + b;
#pragma unroll
    for (int mt = 0; mt < 2; mt++) {
#pragma unroll
        for (int nt = 0; nt < 4; nt++) {
            float* base = g_M + (q8b * 32 + mt * 16 + tg) * 32 + nt * 8 + 2 * tc;
            *(float2*)base = make_float2(dacc[mt][nt][0], dacc[mt][nt][1]);
            *(float2*)(base + 8 * 32) = make_float2(dacc[mt][nt][2], dacc[mt][nt][3]);
        }
    }
    g_zc[q8b * 32 + lane] = zca;
}

// ---------------- Kernel C: 512thr k-split warp pairs, 3xTF32 ---------------
// warp w: n-group ng=w&7 (cols ng*8..+8), k-half kh=w>>3 (tiles kh*16..+16)
// dyn smem (floats): Mt[16][1028]@0 | wsl 16w x 512 @16448 | filts@24640
//                    zct@26688 (stride33) | bias@27216 | part@27280 (1024)
#define KC_SMEM_FLOATS 28304
__global__ __launch_bounds__(512) void kernC(const float* __restrict__ W2,
                                             const float* __restrict__ filt,
                                             const float* __restrict__ bias) {
    extern __shared__ float dsm[];
    float* Mt    = dsm;
    float* wsl   = dsm + 16448;
    float* filts = dsm + 24640;
    float* zct   = dsm + 26688;
    float* biass = dsm + 27216;
    float* part  = dsm + 27280;
    int tid = threadIdx.x;
    int lane = tid & 31, w = tid >> 5, tg = lane >> 2, tc = lane & 3;
    int ng = w & 7, kh = w >> 3;
    int rowbase = blockIdx.x * 16;
    float* myslot = wsl + w * 512;

    {   // M tile: 16 x 1024, stride 1028
#pragma unroll
        for (int i = 0; i < 8; i++) {
            int ch = tid + i * 512;
            int row = ch >> 8, c4 = (ch & 255) * 4;
            cpa16(Mt + row * 1028 + c4, g_M + (rowbase + row) * 1024 + c4);
        }
        cpa_commit();   // group: M
    }
    auto issueW = [&](int tt) {      // tile tt -> slot tt&1 (32 rows x 8 cols)
#pragma unroll
        for (int r = 0; r < 2; r++) {
            int ch = lane + r * 32;
            int row = ch >> 1, half = ch & 1;
            int jcg = tt * 32 + row;
            cpa16(myslot + (tt & 1) * 256 + row * 8 + half * 4,
                  W2 + (jcg >> 5) * 2048 + (jcg & 31) * 64 + ng * 8 + half * 4);
        }
        cpa_commit();
    };
    issueW(kh * 16);
    issueW(kh * 16 + 1);

    for (int l = tid; l < 2048; l += 512) filts[l] = filt[l];
    for (int l = tid; l < 512; l += 512) zct[(l >> 5) * 33 + (l & 31)] = g_zc[rowbase * 32 + l];
    if (tid < 64) biass[tid] = bias[tid];

    cpa_wait2();
    __syncthreads();

    float dacc[4] = {0.f, 0.f, 0.f, 0.f};
    for (int tl = 0; tl < 16; tl++) {
        int t = kh * 16 + tl;
        if (tl < 15) cpa_wait1(); else cpa_wait0();
        __syncwarp();
        const float* Wb = myslot + (tl & 1) * 256;
#pragma unroll
        for (int ks = 0; ks < 4; ks++) {
            int k = t * 32 + ks * 8;
            unsigned a0h, a0l, a1h, a1l, a2h, a2l, a3h, a3l, b0h, b0l, b1h, b1l;
            split_tf32(Mt[tg * 1028 + k + tc],           a0h, a0l);
            split_tf32(Mt[(tg + 8) * 1028 + k + tc],     a1h, a1l);
            split_tf32(Mt[tg * 1028 + k + tc + 4],       a2h, a2l);
            split_tf32(Mt[(tg + 8) * 1028 + k + tc + 4], a3h, a3l);
            split_tf32(Wb[(ks * 8 + tc) * 8 + tg],       b0h, b0l);
            split_tf32(Wb[(ks * 8 + tc + 4) * 8 + tg],   b1h, b1l);
            mma_tf32(dacc, a0h, a1h, a2h, a3h, b0l, b1l);
            mma_tf32(dacc, a0l, a1l, a2l, a3l, b0h, b1h);
            mma_tf32(dacc, a0h, a1h, a2h, a3h, b0h, b1h);
        }
        __syncwarp();
        if (tl <= 13) issueW(t + 2);
    }
    // combine k-halves: kh=1 stores, kh=0 adds + epilogue
    if (kh == 1) *(float4*)(part + ng * 128 + lane * 4) = *(float4*)dacc;
    __syncthreads();
    if (kh == 0) {
        float4 p4 = *(float4*)(part + ng * 128 + lane * 4);
        dacc[0] += p4.x; dacc[1] += p4.y; dacc[2] += p4.z; dacc[3] += p4.w;

        int c0 = ng * 8 + 2 * tc;
        unsigned long long F0 = 0ull, F1 = 0ull;
#pragma unroll 8
        for (int c = 0; c < 32; c++) {
            unsigned long long wp = *(const unsigned long long*)(filts + c * 64 + c0);
            float z0 = zct[tg * 33 + c], z1 = zct[(tg + 8) * 33 + c];
            fma2(F0, pk2(z0, z0), wp);
            fma2(F1, pk2(z1, z1), wp);
        }
        float2 f0 = up2(F0), f1 = up2(F1);
        int r0 = rowbase + tg, r1 = r0 + 8;
        int q0 = r0 >> 3, b0r = r0 & 7, q1 = r1 >> 3, b1r = r1 & 7;
        float bx = biass[c0], by = biass[c0 + 1];
        *(float2*)(g_y + (b0r * QQ + q0) * 64 + c0) =
            make_float2(gelu_exact(dacc[0] + f0.x + bx), gelu_exact(dacc[1] + f0.y + by));
        *(float2*)(g_y + (b1r * QQ + q1) * 64 + c0) =
            make_float2(gelu_exact(dacc[2] + f1.x + bx), gelu_exact(dacc[3] + f1.y + by));
    }
}

// ---------------- Kernel D: 512thr k-split warp pairs, 3xTF32 ---------------
// warp w: n-group ng=w&7, k-half kh=w>>3.
// dyn smem (floats): yr[16][68]@0 | ts[16][260]@1088 | w1 16w x [32][40] @5248
//                    | w2 16w x [128][8] @25728 | part@42112 (4096)
#define KD_SMEM_FLOATS 46208
__global__ __launch_bounds__(512) void kernD(const float* __restrict__ Wm1,
                                             const float* __restrict__ bm1,
                                             const float* __restrict__ Wm2,
                                             const float* __restrict__ bm2,
                                             float* __restrict__ out) {
    extern __shared__ float dsm[];
    float* yr  = dsm;                  // stride 68
    float* ts  = dsm + 1088;           // stride 260
    float* w1s = dsm + 5248;           // per-warp [32][40]
    float* w2s = dsm + 25728;          // per-warp [128][8]
    float* part = dsm + 42112;
    int tid = threadIdx.x;
    int lane = tid & 31, w = tid >> 5, tg = lane >> 2, tc = lane & 3;
    int ng = w & 7, kh = w >> 3;
    int rb = blockIdx.x * 16;
    float* myw1 = w1s + w * 1280;
    float* myw2 = w2s + w * 1024;

    if (tid < 256) {
        int r = tid >> 4, d4 = (tid & 15) * 4;
        *(float4*)(yr + r * 68 + d4) = *(const float4*)(g_y + (rb + r) * 64 + d4);
    }
    // Wm1 slice: rows kh*32..+32, cols ng*32..+32 -> [32][40]
#pragma unroll
    for (int i = 0; i < 8; i++) {
        int ch = lane + i * 32;
        int row = ch >> 3, c4 = (ch & 7) * 4;
        cpa16(myw1 + row * 40 + c4, Wm1 + (kh * 32 + row) * 256 + ng * 32 + c4);
    }
    cpa_commit();   // group w1
    // Wm2 slice: rows kh*128..+128, cols ng*8..+8 -> [128][8]
#pragma unroll
    for (int i = 0; i < 8; i++) {
        int ch = lane + i * 32;
        int row = ch >> 1, half = ch & 1;
        cpa16(myw2 + row * 8 + half * 4, Wm2 + (kh * 128 + row) * 64 + ng * 8 + half * 4);
    }
    cpa_commit();   // group w2

    cpa_wait1();
    __syncthreads();

    // ---- phase 1: partial ts = yr(k-half) @ Wm1-slice ----
    float d1acc[4][4];
#pragma unroll
    for (int nt = 0; nt < 4; nt++)
#pragma unroll
        for (int r = 0; r < 4; r++) d1acc[nt][r] = 0.0f;
#pragma unroll
    for (int t = 0; t < 4; t++) {
        int kloc = t * 8;
        int k = kh * 32 + kloc;
        unsigned a0h, a0l, a1h, a1l, a2h, a2l, a3h, a3l;
        split_tf32(yr[tg * 68 + k + tc],           a0h, a0l);
        split_tf32(yr[(tg + 8) * 68 + k + tc],     a1h, a1l);
        split_tf32(yr[tg * 68 + k + tc + 4],       a2h, a2l);
        split_tf32(yr[(tg + 8) * 68 + k + tc + 4], a3h, a3l);
#pragma unroll
        for (int nt = 0; nt < 4; nt++) {
            int nl = nt * 8 + tg;
            unsigned b0h, b0l, b1h, b1l;
            split_tf32(myw1[(kloc + tc) * 40 + nl],     b0h, b0l);
            split_tf32(myw1[(kloc + tc + 4) * 40 + nl], b1h, b1l);
            mma_tf32(d1acc[nt], a0h, a1h, a2h, a3h, b0l, b1l);
            mma_tf32(d1acc[nt], a0l, a1l, a2l, a3l, b0h, b1h);
            mma_tf32(d1acc[nt], a0h, a1h, a2h, a3h, b0h, b1h);
        }
    }
    if (kh == 1) {
#pragma unroll
        for (int nt = 0; nt < 4; nt++)
            *(float4*)(part + ng * 512 + lane * 16 + nt * 4) = *(float4*)d1acc[nt];
    }
    __syncthreads();   // barrier1: psum1 visible
    if (kh == 0) {
#pragma unroll
        for (int nt = 0; nt < 4; nt++) {
            float4 p4 = *(float4*)(part + ng * 512 + lane * 16 + nt * 4);
            int i0 = (ng * 4 + nt) * 8 + 2 * tc;
            ts[tg * 260 + i0]           = gelu_exact(d1acc[nt][0] + p4.x + bm1[i0]);
            ts[tg * 260 + i0 + 1]       = gelu_exact(d1acc[nt][1] + p4.y + bm1[i0 + 1]);
            ts[(tg + 8) * 260 + i0]     = gelu_exact(d1acc[nt][2] + p4.z + bm1[i0]);
            ts[(tg + 8) * 260 + i0 + 1] = gelu_exact(d1acc[nt][3] + p4.w + bm1[i0 + 1]);
        }
    }
    __syncthreads();   // barrier2: ts ready, psum1 consumed
    cpa_wait0();       // w2 slice resident

    // ---- phase 2: partial out = ts(k-half) @ Wm2-slice ----
    float d2acc[4] = {0.f, 0.f, 0.f, 0.f};
#pragma unroll
    for (int t = 0; t < 4; t++) {
#pragma unroll
        for (int ks = 0; ks < 4; ks++) {
            int kloc = t * 32 + ks * 8;
            int kg = kh * 128 + kloc;
            unsigned a0h, a0l, a1h, a1l, a2h, a2l, a3h, a3l, b0h, b0l, b1h, b1l;
            split_tf32(ts[tg * 260 + kg + tc],           a0h, a0l);
            split_tf32(ts[(tg + 8) * 260 + kg + tc],     a1h, a1l);
            split_tf32(ts[tg * 260 + kg + tc + 4],       a2h, a2l);
            split_tf32(ts[(tg + 8) * 260 + kg + tc + 4], a3h, a3l);
            split_tf32(myw2[(kloc + tc) * 8 + tg],       b0h, b0l);
            split_tf32(myw2[(kloc + tc + 4) * 8 + tg],   b1h, b1l);
            mma_tf32(d2acc, a0h, a1h, a2h, a3h, b0l, b1l);
            mma_tf32(d2acc, a0l, a1l, a2l, a3l, b0h, b1h);
            mma_tf32(d2acc, a0h, a1h, a2h, a3h, b0h, b1h);
        }
    }
    if (kh == 1) *(float4*)(part + ng * 128 + lane * 4) = *(float4*)d2acc;
    __syncthreads();   // barrier3: psum2 visible
    if (kh == 0) {
        float4 p4 = *(float4*)(part + ng * 128 + lane * 4);
        int c0 = ng * 8 + 2 * tc;
        float bx = bm2[c0], by = bm2[c0 + 1];
        *(float2*)(out + (rb + tg) * 64 + c0) =
            make_float2(d2acc[0] + p4.x + bx + yr[tg * 68 + c0],
                        d2acc[1] + p4.y + by + yr[tg * 68 + c0 + 1]);
        *(float2*)(out + (rb + tg + 8) * 64 + c0) =
            make_float2(d2acc[2] + p4.z + bx + yr[(tg + 8) * 68 + c0],
                        d2acc[3] + p4.w + by + yr[(tg + 8) * 68 + c0 + 1]);
    }
}

// ---------------- launch ----------------------------------------------------
extern "C" void kernel_launch(void* const* d_in, const int* in_sizes, int n_in,
                              void* d_out, int out_size) {
    const float* x    = (const float*)d_in[0];
    const float* pos  = (const float*)d_in[1];
    const float* qp   = (const float*)d_in[2];
    const float* qmw  = (const float*)d_in[3];
    const float* qmo  = (const float*)d_in[4];
    const float* W_lin = (const float*)d_in[5];
    const float* b_lin = (const float*)d_in[6];
    const float* rff  = (const float*)d_in[7];
    const float* W1   = (const float*)d_in[8];
    const float* b1   = (const float*)d_in[9];
    const float* W2   = (const float*)d_in[10];
    const float* filt = (const float*)d_in[11];
    const float* bias = (const float*)d_in[12];
    const float* Wm1  = (const float*)d_in[13];
    const float* bm1  = (const float*)d_in[14];
    const float* Wm2  = (const float*)d_in[15];
    const float* bm2  = (const float*)d_in[16];
    float* out = (float*)d_out;

    cudaFuncSetAttribute(kernC, cudaFuncAttributeMaxDynamicSharedMemorySize,
                         KC_SMEM_FLOATS * 4);
    cudaFuncSetAttribute(kernD, cudaFuncAttributeMaxDynamicSharedMemorySize,
                         KD_SMEM_FLOATS * 4);

    kernA<<<512, 256>>>(x, W_lin, b_lin, qp, out, out_size);
    kernB<<<QQ, 256>>>(pos, qp, qmw, qmo, rff, W1, b1);
    kernC<<<128, 512, KC_SMEM_FLOATS * 4>>>(W2, filt, bias);
    kernD<<<128, 512, KD_SMEM_FLOATS * 4>>>(Wm1, bm1, Wm2, bm2, out);
}